// round 9
// baseline (speedup 1.0000x reference)
#include <cuda_runtime.h>
#include <cuda_fp16.h>
#include <math.h>
#include <stdint.h>

#define D_MODEL   768
#define D_STATE   64
#define D_CONV    4
#define HEADDIM   64
#define D_INNER   1536
#define NHEADS    24
#define CONV_DIM  1664
#define D_IN_PROJ 3224
#define BATCH     2
#define SEQLEN    4096
#define ROWS      (BATCH*SEQLEN)
#define NPAD1     3328
#define NCHUNK    64
#define CT        64

// ---------------- scratch (device globals; no allocation) ----------------
__device__ float g_zxbcdt[(size_t)ROWS * D_IN_PROJ];
__device__ float g_xBC[(size_t)ROWS * CONV_DIM];
__device__ float g_y[(size_t)ROWS * D_INNER];
__device__ float g_dtT[(size_t)BATCH * NHEADS * SEQLEN];
__device__ float g_dtAT[(size_t)BATCH * NHEADS * SEQLEN];
__device__ float g_S[(size_t)BATCH * NHEADS * NCHUNK * HEADDIM * D_STATE];
__device__ float g_H[(size_t)BATCH * NHEADS * NCHUNK * HEADDIM * D_STATE];
__device__ float g_P[(size_t)BATCH * NHEADS * NCHUNK];
__device__ __half g_xh[(size_t)ROWS * D_MODEL];
__device__ __half g_yh[(size_t)ROWS * D_INNER];
__device__ __half g_wi[(size_t)NPAD1 * D_MODEL];
__device__ __half g_wo[(size_t)D_MODEL * D_INNER];

// ---------------- common PTX helpers ----------------
__device__ __forceinline__ void cp16(uint32_t dst, const void* src) {
    asm volatile("cp.async.cg.shared.global [%0], [%1], 16;" :: "r"(dst), "l"(src) : "memory");
}
__device__ __forceinline__ void cp_commit() {
    asm volatile("cp.async.commit_group;" ::: "memory");
}
template <int N> __device__ __forceinline__ void cp_wait() {
    asm volatile("cp.async.wait_group %0;" :: "n"(N) : "memory");
}
__device__ __forceinline__ void ldsm4(uint32_t* r, uint32_t addr) {
    asm volatile("ldmatrix.sync.aligned.m8n8.x4.shared.b16 {%0,%1,%2,%3}, [%4];"
                 : "=r"(r[0]), "=r"(r[1]), "=r"(r[2]), "=r"(r[3]) : "r"(addr));
}
__device__ __forceinline__ void mma_f16(float* d, const uint32_t* a, uint32_t b0, uint32_t b1) {
    asm volatile("mma.sync.aligned.m16n8k16.row.col.f32.f16.f16.f32 "
                 "{%0,%1,%2,%3}, {%4,%5,%6,%7}, {%8,%9}, {%0,%1,%2,%3};"
                 : "+f"(d[0]), "+f"(d[1]), "+f"(d[2]), "+f"(d[3])
                 : "r"(a[0]), "r"(a[1]), "r"(a[2]), "r"(a[3]), "r"(b0), "r"(b1));
}

// ---------------- warp-MMA fp16 GEMM: block 128x256, warp tile 64x64 ----------------
#define KC      32
#define PITCH   40
#define ATILE_B (128 * PITCH * 2)       // 10240 bytes
#define BTILE_B (256 * PITCH * 2)       // 20480 bytes
#define STAGE_B (ATILE_B + BTILE_B)     // 30720 bytes
#define STAGES  3
#define GSMEM   (STAGES * STAGE_B)      // 92160 bytes

__global__ void __launch_bounds__(256, 1) mma_gemm(
    const __half* __restrict__ Ah, const __half* __restrict__ Bh,
    float* __restrict__ C, int M, int N, int K) {
    extern __shared__ __half sm[];
    const int tid = threadIdx.x;
    const int wid = tid >> 5, lane = tid & 31;
    const int warp_m = wid >> 2, warp_n = wid & 3;   // 2m x 4n
    const int g = lane >> 2, tig = lane & 3;
    const int bm = blockIdx.y * 128, bn = blockIdx.x * 256;
    const uint32_t sbase = (uint32_t)__cvta_generic_to_shared(sm);

    float acc[4][8][4];
#pragma unroll
    for (int mt = 0; mt < 4; mt++)
#pragma unroll
        for (int nt = 0; nt < 8; nt++)
#pragma unroll
            for (int i = 0; i < 4; i++) acc[mt][nt][i] = 0.f;

    const int nkt = K / KC;
    const int r_ld = tid >> 2, seg_ld = tid & 3;

    auto issue = [&](int kt) {
        const int st = kt % STAGES;
        const int kofs = kt * KC;
        const uint32_t dst0 = sbase + st * STAGE_B;
        // A: 128 rows
#pragma unroll
        for (int i = 0; i < 2; i++) {
            const int r = r_ld + i * 64;
            cp16(dst0 + (uint32_t)(r * PITCH + seg_ld * 8) * 2,
                 Ah + (size_t)(bm + r) * K + kofs + seg_ld * 8);
        }
        // B: 256 rows
#pragma unroll
        for (int i = 0; i < 4; i++) {
            const int r = r_ld + i * 64;
            cp16(dst0 + ATILE_B + (uint32_t)(r * PITCH + seg_ld * 8) * 2,
                 Bh + (size_t)(bn + r) * K + kofs + seg_ld * 8);
        }
    };

    issue(0); cp_commit();
    if (nkt > 1) { issue(1); cp_commit(); }

    const int a_row = (lane & 15);
    const int a_col = (lane >> 4) * 8;
    const int b_row = (lane & 7) + ((lane >> 4) * 8);
    const int b_col = ((lane >> 3) & 1) * 8;

    for (int kt = 0; kt < nkt; kt++) {
        if (kt + 2 < nkt) cp_wait<1>(); else cp_wait<0>();
        __syncthreads();
        if (kt + 2 < nkt) { issue(kt + 2); cp_commit(); }

        const uint32_t st0 = sbase + (kt % STAGES) * STAGE_B;
        const uint32_t aA = st0;
        const uint32_t bB = st0 + ATILE_B;

#pragma unroll
        for (int ks = 0; ks < KC; ks += 16) {
            uint32_t ah[4][4], bf[4][4];
#pragma unroll
            for (int mt = 0; mt < 4; mt++) {
                const uint32_t aoff =
                    (uint32_t)((warp_m * 64 + mt * 16 + a_row) * PITCH + ks + a_col) * 2;
                ldsm4(ah[mt], aA + aoff);
            }
#pragma unroll
            for (int ntp = 0; ntp < 4; ntp++) {
                const uint32_t boff =
                    (uint32_t)((warp_n * 64 + ntp * 16 + b_row) * PITCH + ks + b_col) * 2;
                ldsm4(bf[ntp], bB + boff);
            }
#pragma unroll
            for (int nt = 0; nt < 8; nt++) {
                const uint32_t b0 = bf[nt >> 1][(nt & 1) * 2];
                const uint32_t b1 = bf[nt >> 1][(nt & 1) * 2 + 1];
#pragma unroll
                for (int mt = 0; mt < 4; mt++)
                    mma_f16(acc[mt][nt], ah[mt], b0, b1);
            }
        }
        __syncthreads();
    }

#pragma unroll
    for (int mt = 0; mt < 4; mt++) {
        const int row0 = bm + warp_m * 64 + mt * 16 + g;
#pragma unroll
        for (int nt = 0; nt < 8; nt++) {
            const int col = bn + warp_n * 64 + nt * 8 + 2 * tig;
            if (col < N) {
                *(float2*)&C[(size_t)row0 * N + col] = make_float2(acc[mt][nt][0], acc[mt][nt][1]);
                *(float2*)&C[(size_t)(row0 + 8) * N + col] = make_float2(acc[mt][nt][2], acc[mt][nt][3]);
            }
        }
    }
}

// ---------------- fp32 -> fp16 convert ----------------
__global__ void convert_f16(const float* __restrict__ src,
                            __half* __restrict__ dst, int n4) {
    int i = blockIdx.x * blockDim.x + threadIdx.x;
    if (i >= n4) return;
    const int idx = i * 4;
    float4 v = *(const float4*)(src + idx);
    __half h[4];
    h[0] = __float2half(v.x); h[1] = __float2half(v.y);
    h[2] = __float2half(v.z); h[3] = __float2half(v.w);
    *(uint2*)(dst + idx) = *(uint2*)h;
}

// ---------------- transpose to fp16 ----------------
__global__ void transpose_f16(const float* __restrict__ src,
                              __half* __restrict__ dst,
                              int R, int C, int Cpad) {
    __shared__ float tile[32][33];
    const int c0 = blockIdx.x * 32, r0 = blockIdx.y * 32;
    const int tx = threadIdx.x, ty = threadIdx.y;
    const int c = c0 + tx;
#pragma unroll
    for (int j = ty; j < 32; j += 8) {
        const int r = r0 + j;
        tile[j][tx] = (r < R && c < C) ? src[(size_t)r * C + c] : 0.f;
    }
    __syncthreads();
#pragma unroll
    for (int j = ty; j < 32; j += 8) {
        const int orow = c0 + j;
        const int ocol = r0 + tx;
        if (orow < Cpad && ocol < R)
            dst[(size_t)orow * R + ocol] = __float2half(tile[tx][j]);
    }
}

// ---------------- dt ----------------
__global__ void dt_kernel(const float* __restrict__ dt_bias,
                          const float* __restrict__ A_log) {
    int idx = blockIdx.x * blockDim.x + threadIdx.x;
    if (idx >= BATCH * NHEADS * SEQLEN) return;
    const int l = idx % SEQLEN;
    const int bh = idx / SEQLEN;
    const int h = bh % NHEADS, b = bh / NHEADS;
    float v = g_zxbcdt[(size_t)(b * SEQLEN + l) * D_IN_PROJ + (D_INNER + CONV_DIM) + h]
              + dt_bias[h];
    float dtv = (v > 20.f) ? v : log1pf(expf(v));
    float A = -expf(A_log[h]);
    g_dtT[idx] = dtv;
    g_dtAT[idx] = dtv * A;
}

// ---------------- causal depthwise conv + silu ----------------
__global__ void conv_kernel(const float* __restrict__ conv_w,
                            const float* __restrict__ conv_b) {
    int idx = blockIdx.x * blockDim.x + threadIdx.x;
    if (idx >= ROWS * CONV_DIM) return;
    int c = idx % CONV_DIM;
    int row = idx / CONV_DIM;
    int l = row & (SEQLEN - 1);
    float acc = conv_b[c];
#pragma unroll
    for (int k = 0; k < D_CONV; k++) {
        int ls = l + k - (D_CONV - 1);
        if (ls >= 0)
            acc += g_zxbcdt[(size_t)(row + k - (D_CONV - 1)) * D_IN_PROJ + D_INNER + c] *
                   conv_w[c * D_CONV + k];
    }
    g_xBC[idx] = acc / (1.f + expf(-acc));
}

// ================= chunked SSM scan (tensor-core) =================
#define SPITCH 72

// Phase A
__global__ void __launch_bounds__(256) chunk_state(void) {
    __shared__ __half sAh[CT * SPITCH], sAl[CT * SPITCH];
    __shared__ __half sBh[CT * SPITCH], sBl[CT * SPITCH];
    __shared__ float sL[CT], sdt[CT];
    const int c = blockIdx.x, h = blockIdx.y, b = blockIdx.z;
    const int tid = threadIdx.x;
    const int bh = b * NHEADS + h;
    const int rowbase = b * SEQLEN + c * CT;

    if (tid < CT) {
        sdt[tid] = g_dtT[(size_t)bh * SEQLEN + c * CT + tid];
        sL[tid]  = g_dtAT[(size_t)bh * SEQLEN + c * CT + tid];
    }
    __syncthreads();
    if (tid == 0) {
        float run = 0.f;
        for (int t = 0; t < CT; t++) { run += sL[t]; sL[t] = run; }
    }
    __syncthreads();
    const float Lend = sL[CT - 1];

    for (int e = tid; e < CT * 16; e += 256) {
        const int t = e >> 4, q = e & 15;
        const float* rowp = g_xBC + (size_t)(rowbase + t) * CONV_DIM;
        const float w = sdt[t] * expf(Lend - sL[t]);
        float4 xv = *(const float4*)(rowp + h * HEADDIM + q * 4);
        float4 bv = *(const float4*)(rowp + D_INNER + q * 4);
        const float xa[4] = {xv.x * w, xv.y * w, xv.z * w, xv.w * w};
        const float ba[4] = {bv.x, bv.y, bv.z, bv.w};
#pragma unroll
        for (int j = 0; j < 4; j++) {
            const int p = q * 4 + j;
            __half hx = __float2half(xa[j]);
            sAh[p * SPITCH + t] = hx;
            sAl[p * SPITCH + t] = __float2half(xa[j] - __half2float(hx));
            __half hb = __float2half(ba[j]);
            sBh[p * SPITCH + t] = hb;
            sBl[p * SPITCH + t] = __float2half(ba[j] - __half2float(hb));
        }
    }
    __syncthreads();

    const int wid = tid >> 5, lane = tid & 31;
    const int warp_m = wid & 3, warp_n = wid >> 2;
    const int a_row = lane & 15, a_col = (lane >> 4) * 8;
    const int b_row = (lane & 7) + ((lane >> 4) * 8), b_col = ((lane >> 3) & 1) * 8;
    const uint32_t uAh = (uint32_t)__cvta_generic_to_shared(sAh);
    const uint32_t uAl = (uint32_t)__cvta_generic_to_shared(sAl);
    const uint32_t uBh = (uint32_t)__cvta_generic_to_shared(sBh);
    const uint32_t uBl = (uint32_t)__cvta_generic_to_shared(sBl);

    float acc[4][4];
#pragma unroll
    for (int nt = 0; nt < 4; nt++)
#pragma unroll
        for (int i = 0; i < 4; i++) acc[nt][i] = 0.f;

#pragma unroll
    for (int kt = 0; kt < 4; kt++) {
        const int k0 = kt * 16;
        uint32_t ah[4], al[4], bh[2][4], bl[2][4];
        const uint32_t aoff = (uint32_t)((warp_m * 16 + a_row) * SPITCH + k0 + a_col) * 2;
        ldsm4(ah, uAh + aoff);
        ldsm4(al, uAl + aoff);
#pragma unroll
        for (int nb = 0; nb < 2; nb++) {
            const uint32_t boff =
                (uint32_t)((warp_n * 32 + nb * 16 + b_row) * SPITCH + k0 + b_col) * 2;
            ldsm4(bh[nb], uBh + boff);
            ldsm4(bl[nb], uBl + boff);
        }
#pragma unroll
        for (int nt = 0; nt < 4; nt++) {
            const int nb = nt >> 1, pr = (nt & 1) * 2;
            mma_f16(acc[nt], ah, bh[nb][pr], bh[nb][pr + 1]);
            mma_f16(acc[nt], ah, bl[nb][pr], bl[nb][pr + 1]);
            mma_f16(acc[nt], al, bh[nb][pr], bh[nb][pr + 1]);
        }
    }

    float* Sb = g_S + ((size_t)bh * NCHUNK + c) * (HEADDIM * D_STATE);
    const int g = lane >> 2, tig = lane & 3;
#pragma unroll
    for (int nt = 0; nt < 4; nt++) {
        const int ncol = warp_n * 32 + nt * 8 + 2 * tig;
        const int prow = warp_m * 16 + g;
        *(float2*)&Sb[prow * D_STATE + ncol] = make_float2(acc[nt][0], acc[nt][1]);
        *(float2*)&Sb[(prow + 8) * D_STATE + ncol] = make_float2(acc[nt][2], acc[nt][3]);
    }
    if (tid == 0) g_P[(size_t)bh * NCHUNK + c] = Lend;
}

// Phase B
__global__ void __launch_bounds__(256) state_pass(void) {
    const int bh = blockIdx.x;
    const int tid = threadIdx.x;
    float hreg[16];
#pragma unroll
    for (int i = 0; i < 16; i++) hreg[i] = 0.f;
    for (int c = 0; c < NCHUNK; c++) {
        float* Hb = g_H + ((size_t)bh * NCHUNK + c) * (HEADDIM * D_STATE);
        const float* Sb = g_S + ((size_t)bh * NCHUNK + c) * (HEADDIM * D_STATE);
        const float P = expf(g_P[(size_t)bh * NCHUNK + c]);
#pragma unroll
        for (int i = 0; i < 16; i++) {
            Hb[tid + i * 256] = hreg[i];
            hreg[i] = P * hreg[i] + Sb[tid + i * 256];
        }
    }
}

// Phase C
#define CTILE (CT * SPITCH)
#define CSMEM (10 * CTILE * 2 + 2 * CT * 4)
__global__ void __launch_bounds__(256) chunk_output(const float* __restrict__ Dparam) {
    extern __shared__ __half cs[];
    __half* sCh = cs;
    __half* sCl = cs + CTILE;
    __half* sB2h = cs + 2 * CTILE;
    __half* sB2l = cs + 3 * CTILE;
    __half* sXh = cs + 4 * CTILE;
    __half* sXl = cs + 5 * CTILE;
    __half* sHh = cs + 6 * CTILE;
    __half* sHl = cs + 7 * CTILE;
    __half* sGh = cs + 8 * CTILE;
    __half* sGl = cs + 9 * CTILE;
    float* sL = (float*)(cs + 10 * CTILE);
    float* sdt = sL + CT;

    const int c = blockIdx.x, h = blockIdx.y, b = blockIdx.z;
    const int tid = threadIdx.x;
    const int bh = b * NHEADS + h;
    const int rowbase = b * SEQLEN + c * CT;
    const float Dh = Dparam[h];

    if (tid < CT) {
        sdt[tid] = g_dtT[(size_t)bh * SEQLEN + c * CT + tid];
        sL[tid]  = g_dtAT[(size_t)bh * SEQLEN + c * CT + tid];
    }
    __syncthreads();
    if (tid == 0) {
        float run = 0.f;
        for (int t = 0; t < CT; t++) { run += sL[t]; sL[t] = run; }
    }

    const float* Hbase = g_H + ((size_t)bh * NCHUNK + c) * (HEADDIM * D_STATE);
    for (int e = tid; e < CT * 16; e += 256) {
        const int t = e >> 4, q = e & 15;
        const float* rowp = g_xBC + (size_t)(rowbase + t) * CONV_DIM;
        float4 cv = *(const float4*)(rowp + D_INNER + D_STATE + q * 4);
        float4 bv = *(const float4*)(rowp + D_INNER + q * 4);
        float4 xv = *(const float4*)(rowp + h * HEADDIM + q * 4);
        float4 hv = *(const float4*)(Hbase + t * D_STATE + q * 4);
        const float ca[4] = {cv.x, cv.y, cv.z, cv.w};
        const float ba[4] = {bv.x, bv.y, bv.z, bv.w};
        const float xa[4] = {xv.x, xv.y, xv.z, xv.w};
        const float ha[4] = {hv.x, hv.y, hv.z, hv.w};
#pragma unroll
        for (int j = 0; j < 4; j++) {
            const int n = q * 4 + j;
            __half hc = __float2half(ca[j]);
            sCh[t * SPITCH + n] = hc;
            sCl[t * SPITCH + n] = __float2half(ca[j] - __half2float(hc));
            __half hb = __float2half(ba[j]);
            sB2h[t * SPITCH + n] = hb;
            sB2l[t * SPITCH + n] = __float2half(ba[j] - __half2float(hb));
            __half hx = __float2half(xa[j]);
            sXh[n * SPITCH + t] = hx;
            sXl[n * SPITCH + t] = __float2half(xa[j] - __half2float(hx));
            __half hh = __float2half(ha[j]);
            sHh[t * SPITCH + n] = hh;
            sHl[t * SPITCH + n] = __float2half(ha[j] - __half2float(hh));
        }
    }
    __syncthreads();

    const int wid = tid >> 5, lane = tid & 31;
    const int warp_m = wid & 3, warp_n = wid >> 2;
    const int a_row = lane & 15, a_col = (lane >> 4) * 8;
    const int b_row = (lane & 7) + ((lane >> 4) * 8), b_col = ((lane >> 3) & 1) * 8;
    const int g = lane >> 2, tig = lane & 3;
    const uint32_t uCh = (uint32_t)__cvta_generic_to_shared(sCh);
    const uint32_t uCl = (uint32_t)__cvta_generic_to_shared(sCl);
    const uint32_t uB2h = (uint32_t)__cvta_generic_to_shared(sB2h);
    const uint32_t uB2l = (uint32_t)__cvta_generic_to_shared(sB2l);
    const uint32_t uXh = (uint32_t)__cvta_generic_to_shared(sXh);
    const uint32_t uXl = (uint32_t)__cvta_generic_to_shared(sXl);
    const uint32_t uHh = (uint32_t)__cvta_generic_to_shared(sHh);
    const uint32_t uHl = (uint32_t)__cvta_generic_to_shared(sHl);
    const uint32_t uGh = (uint32_t)__cvta_generic_to_shared(sGh);
    const uint32_t uGl = (uint32_t)__cvta_generic_to_shared(sGl);

    float gacc[4][4];
#pragma unroll
    for (int nt = 0; nt < 4; nt++)
#pragma unroll
        for (int i = 0; i < 4; i++) gacc[nt][i] = 0.f;
#pragma unroll
    for (int kt = 0; kt < 4; kt++) {
        const int k0 = kt * 16;
        uint32_t ah[4], al[4], bh[2][4], bl[2][4];
        const uint32_t aoff = (uint32_t)((warp_m * 16 + a_row) * SPITCH + k0 + a_col) * 2;
        ldsm4(ah, uCh + aoff);
        ldsm4(al, uCl + aoff);
#pragma unroll
        for (int nb = 0; nb < 2; nb++) {
            const uint32_t boff =
                (uint32_t)((warp_n * 32 + nb * 16 + b_row) * SPITCH + k0 + b_col) * 2;
            ldsm4(bh[nb], uB2h + boff);
            ldsm4(bl[nb], uB2l + boff);
        }
#pragma unroll
        for (int nt = 0; nt < 4; nt++) {
            const int nb = nt >> 1, pr = (nt & 1) * 2;
            mma_f16(gacc[nt], ah, bh[nb][pr], bh[nb][pr + 1]);
            mma_f16(gacc[nt], ah, bl[nb][pr], bl[nb][pr + 1]);
            mma_f16(gacc[nt], al, bh[nb][pr], bh[nb][pr + 1]);
        }
    }
    __syncthreads();

#pragma unroll
    for (int nt = 0; nt < 4; nt++) {
        const int s0 = warp_n * 32 + nt * 8 + 2 * tig;
#pragma unroll
        for (int r = 0; r < 2; r++) {
            const int t = warp_m * 16 + g + r * 8;
            float v0 = gacc[nt][r * 2], v1 = gacc[nt][r * 2 + 1];
            const float Lt = sL[t];
            v0 = (s0 <= t)     ? v0 * sdt[s0]     * expf(Lt - sL[s0])     : 0.f;
            v1 = (s0 + 1 <= t) ? v1 * sdt[s0 + 1] * expf(Lt - sL[s0 + 1]) : 0.f;
            __half h0 = __float2half(v0), h1 = __float2half(v1);
            *(__half2*)&sGh[t * SPITCH + s0] = __halves2half2(h0, h1);
            *(__half2*)&sGl[t * SPITCH + s0] = __halves2half2(
                __float2half(v0 - __half2float(h0)), __float2half(v1 - __half2float(h1)));
        }
    }
    __syncthreads();

    float yacc[4][4], cacc[4][4];
#pragma unroll
    for (int nt = 0; nt < 4; nt++)
#pragma unroll
        for (int i = 0; i < 4; i++) { yacc[nt][i] = 0.f; cacc[nt][i] = 0.f; }
#pragma unroll
    for (int kt = 0; kt < 4; kt++) {
        const int k0 = kt * 16;
        uint32_t gh[4], gl[4], ch[4], cl[4];
        uint32_t xh[2][4], xl[2][4], hh[2][4], hl[2][4];
        const uint32_t aoff = (uint32_t)((warp_m * 16 + a_row) * SPITCH + k0 + a_col) * 2;
        ldsm4(gh, uGh + aoff);
        ldsm4(gl, uGl + aoff);
        ldsm4(ch, uCh + aoff);
        ldsm4(cl, uCl + aoff);
#pragma unroll
        for (int nb = 0; nb < 2; nb++) {
            const uint32_t boff =
                (uint32_t)((warp_n * 32 + nb * 16 + b_row) * SPITCH + k0 + b_col) * 2;
            ldsm4(xh[nb], uXh + boff);
            ldsm4(xl[nb], uXl + boff);
            ldsm4(hh[nb], uHh + boff);
            ldsm4(hl[nb], uHl + boff);
        }
#pragma unroll
        for (int nt = 0; nt < 4; nt++) {
            const int nb = nt >> 1, pr = (nt & 1) * 2;
            mma_f16(yacc[nt], gh, xh[nb][pr], xh[nb][pr + 1]);
            mma_f16(yacc[nt], gh, xl[nb][pr], xl[nb][pr + 1]);
            mma_f16(yacc[nt], gl, xh[nb][pr], xh[nb][pr + 1]);
            mma_f16(cacc[nt], ch, hh[nb][pr], hh[nb][pr + 1]);
            mma_f16(cacc[nt], ch, hl[nb][pr], hl[nb][pr + 1]);
            mma_f16(cacc[nt], cl, hh[nb][pr], hh[nb][pr + 1]);
        }
    }

#pragma unroll
    for (int nt = 0; nt < 4; nt++) {
        const int p = warp_n * 32 + nt * 8 + 2 * tig;
#pragma unroll
        for (int r = 0; r < 2; r++) {
            const int t = warp_m * 16 + g + r * 8;
            const float et = expf(sL[t]);
            const float x0 = __half2float(sXh[p * SPITCH + t]) + __half2float(sXl[p * SPITCH + t]);
            const float x1 = __half2float(sXh[(p + 1) * SPITCH + t]) + __half2float(sXl[(p + 1) * SPITCH + t]);
            const float o0 = yacc[nt][r * 2] + cacc[nt][r * 2] * et + Dh * x0;
            const float o1 = yacc[nt][r * 2 + 1] + cacc[nt][r * 2 + 1] * et + Dh * x1;
            *(float2*)&g_y[(size_t)(rowbase + t) * D_INNER + h * HEADDIM + p] =
                make_float2(o0, o1);
        }
    }
}

// ---------------- gate + RMSNorm, writing fp16 ----------------
__global__ void __launch_bounds__(256) norm_kernel(const float* __restrict__ norm_w) {
    const int row = blockIdx.x;
    const int tid = threadIdx.x;
    const float* zrow = g_zxbcdt + (size_t)row * D_IN_PROJ;
    const float* yrow = g_y + (size_t)row * D_INNER;
    __half* hrow = g_yh + (size_t)row * D_INNER;

    float vals[6];
    float ss = 0.f;
#pragma unroll
    for (int i = 0; i < 6; i++) {
        int c = tid + i * 256;
        float z = zrow[c];
        float yv = yrow[c] * (z / (1.f + expf(-z)));
        vals[i] = yv;
        ss += yv * yv;
    }
#pragma unroll
    for (int o = 16; o; o >>= 1) ss += __shfl_xor_sync(0xffffffffu, ss, o);
    __shared__ float red[8];
    if ((tid & 31) == 0) red[tid >> 5] = ss;
    __syncthreads();
    if (tid < 8) {
        float v = red[tid];
#pragma unroll
        for (int o = 4; o; o >>= 1) v += __shfl_xor_sync(0xffu, v, o);
        if (tid == 0) red[0] = v;
    }
    __syncthreads();
    const float scale = rsqrtf(red[0] * (1.f / D_INNER) + 1e-5f);
#pragma unroll
    for (int i = 0; i < 6; i++) {
        int c = tid + i * 256;
        hrow[c] = __float2half(vals[i] * scale * norm_w[c]);
    }
}

// ---------------- launch ----------------
extern "C" void kernel_launch(void* const* d_in, const int* in_sizes, int n_in,
                              void* d_out, int out_size) {
    const float* x       = (const float*)d_in[0];
    const float* W_in    = (const float*)d_in[1];
    const float* conv_w  = (const float*)d_in[2];
    const float* conv_b  = (const float*)d_in[3];
    const float* dt_bias = (const float*)d_in[4];
    const float* A_log   = (const float*)d_in[5];
    const float* Dp      = (const float*)d_in[6];
    const float* norm_w  = (const float*)d_in[7];
    const float* W_out   = (const float*)d_in[8];
    float* out = (float*)d_out;

    float *zx_ptr;
    cudaGetSymbolAddress((void**)&zx_ptr, g_zxbcdt);
    __half *xh, *yh, *wi, *wo;
    cudaGetSymbolAddress((void**)&xh, g_xh);
    cudaGetSymbolAddress((void**)&yh, g_yh);
    cudaGetSymbolAddress((void**)&wi, g_wi);
    cudaGetSymbolAddress((void**)&wo, g_wo);

    static int attr_set = 0;
    if (!attr_set) {
        cudaFuncSetAttribute(mma_gemm, cudaFuncAttributeMaxDynamicSharedMemorySize, GSMEM);
        cudaFuncSetAttribute(chunk_output, cudaFuncAttributeMaxDynamicSharedMemorySize, CSMEM);
        attr_set = 1;
    }

    // 0-2) conversions
    convert_f16<<<(ROWS * D_MODEL / 4 + 255) / 256, 256>>>(x, xh, ROWS * D_MODEL / 4);
    transpose_f16<<<dim3(NPAD1 / 32, D_MODEL / 32), dim3(32, 8)>>>(
        W_in, wi, D_MODEL, D_IN_PROJ, NPAD1);
    transpose_f16<<<dim3(D_MODEL / 32, D_INNER / 32), dim3(32, 8)>>>(
        W_out, wo, D_INNER, D_MODEL, D_MODEL);

    // 3) zxbcdt = x @ W_in   (launch index 3 -> ncu slot)
    mma_gemm<<<dim3(NPAD1 / 256, ROWS / 128), 256, GSMEM>>>(
        xh, wi, zx_ptr, ROWS, D_IN_PROJ, D_MODEL);

    // 4) dt / dtA
    dt_kernel<<<(BATCH * NHEADS * SEQLEN + 255) / 256, 256>>>(dt_bias, A_log);

    // 5) conv + silu
    conv_kernel<<<((size_t)ROWS * CONV_DIM + 255) / 256, 256>>>(conv_w, conv_b);

    // 6-8) chunked SSM scan
    chunk_state<<<dim3(NCHUNK, NHEADS, BATCH), 256>>>();
    state_pass<<<BATCH * NHEADS, 256>>>();
    chunk_output<<<dim3(NCHUNK, NHEADS, BATCH), 256, CSMEM>>>(Dp);

    // 9) gate + RMSNorm
    norm_kernel<<<ROWS, 256>>>(norm_w);

    // 10) out = y @ W_out
    mma_gemm<<<dim3(D_MODEL / 256, ROWS / 128), 256, GSMEM>>>(
        yh, wo, out, ROWS, D_MODEL, D_INNER);
}

// round 10
// speedup vs baseline: 1.0890x; 1.0890x over previous
#include <cuda_runtime.h>
#include <cuda_fp16.h>
#include <math.h>
#include <stdint.h>

#define D_MODEL   768
#define D_STATE   64
#define D_CONV    4
#define HEADDIM   64
#define D_INNER   1536
#define NHEADS    24
#define CONV_DIM  1664
#define D_IN_PROJ 3224
#define BATCH     2
#define SEQLEN    4096
#define ROWS      (BATCH*SEQLEN)
#define NPAD1     3328
#define NCHUNK    64
#define CT        64

// ---------------- scratch (device globals; no allocation) ----------------
__device__ float g_zxbcdt[(size_t)ROWS * D_IN_PROJ];
__device__ float g_xBC[(size_t)ROWS * CONV_DIM];
__device__ float g_y[(size_t)ROWS * D_INNER];
__device__ float g_dtT[(size_t)BATCH * NHEADS * SEQLEN];
__device__ float g_dtAT[(size_t)BATCH * NHEADS * SEQLEN];
__device__ float g_S[(size_t)BATCH * NHEADS * NCHUNK * HEADDIM * D_STATE];
__device__ float g_H[(size_t)BATCH * NHEADS * NCHUNK * HEADDIM * D_STATE];
__device__ float g_P[(size_t)BATCH * NHEADS * NCHUNK];
__device__ __half g_xh[(size_t)ROWS * D_MODEL];
__device__ __half g_yh[(size_t)ROWS * D_INNER];
__device__ __half g_wi[(size_t)NPAD1 * D_MODEL];
__device__ __half g_wo[(size_t)D_MODEL * D_INNER];

// ---------------- common PTX helpers ----------------
__device__ __forceinline__ void cp16(uint32_t dst, const void* src) {
    asm volatile("cp.async.ca.shared.global [%0], [%1], 16;" :: "r"(dst), "l"(src) : "memory");
}
__device__ __forceinline__ void cp_commit() {
    asm volatile("cp.async.commit_group;" ::: "memory");
}
template <int N> __device__ __forceinline__ void cp_wait() {
    asm volatile("cp.async.wait_group %0;" :: "n"(N) : "memory");
}
__device__ __forceinline__ void ldsm4(uint32_t* r, uint32_t addr) {
    asm volatile("ldmatrix.sync.aligned.m8n8.x4.shared.b16 {%0,%1,%2,%3}, [%4];"
                 : "=r"(r[0]), "=r"(r[1]), "=r"(r[2]), "=r"(r[3]) : "r"(addr));
}
__device__ __forceinline__ void mma_f16(float* d, const uint32_t* a, uint32_t b0, uint32_t b1) {
    asm volatile("mma.sync.aligned.m16n8k16.row.col.f32.f16.f16.f32 "
                 "{%0,%1,%2,%3}, {%4,%5,%6,%7}, {%8,%9}, {%0,%1,%2,%3};"
                 : "+f"(d[0]), "+f"(d[1]), "+f"(d[2]), "+f"(d[3])
                 : "r"(a[0]), "r"(a[1]), "r"(a[2]), "r"(a[3]), "r"(b0), "r"(b1));
}

// ---------------- warp-MMA fp16 GEMM: block 128x128, warp 32x64, KC=64 ----------------
#define KC      64
#define PITCH   72                       // halves per smem row (144B, 16B skew)
#define TILE_E  (128 * PITCH)
#define TILE_B  (TILE_E * 2)             // 18432 bytes
#define STAGE_B (2 * TILE_B)             // A + B: 36864 bytes
#define STAGES  3
#define GSMEM   (STAGES * STAGE_B)       // 110592 bytes

__global__ void __launch_bounds__(256, 2) mma_gemm(
    const __half* __restrict__ Ah, const __half* __restrict__ Bh,
    float* __restrict__ C, int M, int N, int K) {
    extern __shared__ __half sm[];
    const int tid = threadIdx.x;
    const int wid = tid >> 5, lane = tid & 31;
    const int warp_m = wid >> 1, warp_n = wid & 1;   // 4m x 2n, warp tile 32x64
    const int g = lane >> 2, tig = lane & 3;
    const int bm = blockIdx.y * 128, bn = blockIdx.x * 128;
    const uint32_t sbase = (uint32_t)__cvta_generic_to_shared(sm);

    float acc[2][8][4];
#pragma unroll
    for (int mt = 0; mt < 2; mt++)
#pragma unroll
        for (int nt = 0; nt < 8; nt++)
#pragma unroll
            for (int i = 0; i < 4; i++) acc[mt][nt][i] = 0.f;

    const int nkt = K / KC;
    const int r_ld = tid >> 3, seg_ld = tid & 7;     // 32 rows per pass, 8 segs of 16B

    auto issue = [&](int kt) {
        const int st = kt % STAGES;
        const int kofs = kt * KC;
        const uint32_t dst0 = sbase + st * STAGE_B;
        const __half* srcs[2] = {Ah, Bh};
#pragma unroll
        for (int arr = 0; arr < 2; arr++) {
            const int rbase = (arr == 0) ? bm : bn;
            const uint32_t db = dst0 + arr * TILE_B;
#pragma unroll
            for (int i = 0; i < 4; i++) {
                const int r = r_ld + i * 32;
                cp16(db + (uint32_t)(r * PITCH + seg_ld * 8) * 2,
                     srcs[arr] + (size_t)(rbase + r) * K + kofs + seg_ld * 8);
            }
        }
    };

    issue(0); cp_commit();
    if (nkt > 1) { issue(1); cp_commit(); }

    const int a_row = (lane & 15);
    const int a_col = (lane >> 4) * 8;
    const int b_row = (lane & 7) + ((lane >> 4) * 8);
    const int b_col = ((lane >> 3) & 1) * 8;

    for (int kt = 0; kt < nkt; kt++) {
        if (kt + 2 < nkt) cp_wait<1>(); else cp_wait<0>();
        __syncthreads();
        if (kt + 2 < nkt) { issue(kt + 2); cp_commit(); }

        const uint32_t st0 = sbase + (kt % STAGES) * STAGE_B;
        const uint32_t aA = st0;
        const uint32_t bB = st0 + TILE_B;

#pragma unroll
        for (int ks = 0; ks < KC; ks += 16) {
            uint32_t ah[2][4], bf[4][4];
#pragma unroll
            for (int mt = 0; mt < 2; mt++) {
                const uint32_t aoff =
                    (uint32_t)((warp_m * 32 + mt * 16 + a_row) * PITCH + ks + a_col) * 2;
                ldsm4(ah[mt], aA + aoff);
            }
#pragma unroll
            for (int ntp = 0; ntp < 4; ntp++) {
                const uint32_t boff =
                    (uint32_t)((warp_n * 64 + ntp * 16 + b_row) * PITCH + ks + b_col) * 2;
                ldsm4(bf[ntp], bB + boff);
            }
#pragma unroll
            for (int nt = 0; nt < 8; nt++) {
                const uint32_t b0 = bf[nt >> 1][(nt & 1) * 2];
                const uint32_t b1 = bf[nt >> 1][(nt & 1) * 2 + 1];
#pragma unroll
                for (int mt = 0; mt < 2; mt++)
                    mma_f16(acc[mt][nt], ah[mt], b0, b1);
            }
        }
        __syncthreads();
    }

#pragma unroll
    for (int mt = 0; mt < 2; mt++) {
        const int row0 = bm + warp_m * 32 + mt * 16 + g;
#pragma unroll
        for (int nt = 0; nt < 8; nt++) {
            const int col = bn + warp_n * 64 + nt * 8 + 2 * tig;
            if (col < N) {
                *(float2*)&C[(size_t)row0 * N + col] = make_float2(acc[mt][nt][0], acc[mt][nt][1]);
                *(float2*)&C[(size_t)(row0 + 8) * N + col] = make_float2(acc[mt][nt][2], acc[mt][nt][3]);
            }
        }
    }
}

// ---------------- fp32 -> fp16 convert ----------------
__global__ void convert_f16(const float* __restrict__ src,
                            __half* __restrict__ dst, int n4) {
    int i = blockIdx.x * blockDim.x + threadIdx.x;
    if (i >= n4) return;
    const int idx = i * 4;
    float4 v = *(const float4*)(src + idx);
    __half h[4];
    h[0] = __float2half(v.x); h[1] = __float2half(v.y);
    h[2] = __float2half(v.z); h[3] = __float2half(v.w);
    *(uint2*)(dst + idx) = *(uint2*)h;
}

// ---------------- transpose to fp16 ----------------
__global__ void transpose_f16(const float* __restrict__ src,
                              __half* __restrict__ dst,
                              int R, int C, int Cpad) {
    __shared__ float tile[32][33];
    const int c0 = blockIdx.x * 32, r0 = blockIdx.y * 32;
    const int tx = threadIdx.x, ty = threadIdx.y;
    const int c = c0 + tx;
#pragma unroll
    for (int j = ty; j < 32; j += 8) {
        const int r = r0 + j;
        tile[j][tx] = (r < R && c < C) ? src[(size_t)r * C + c] : 0.f;
    }
    __syncthreads();
#pragma unroll
    for (int j = ty; j < 32; j += 8) {
        const int orow = c0 + j;
        const int ocol = r0 + tx;
        if (orow < Cpad && ocol < R)
            dst[(size_t)orow * R + ocol] = __float2half(tile[tx][j]);
    }
}

// ---------------- dt ----------------
__global__ void dt_kernel(const float* __restrict__ dt_bias,
                          const float* __restrict__ A_log) {
    int idx = blockIdx.x * blockDim.x + threadIdx.x;
    if (idx >= BATCH * NHEADS * SEQLEN) return;
    const int l = idx % SEQLEN;
    const int bh = idx / SEQLEN;
    const int h = bh % NHEADS, b = bh / NHEADS;
    float v = g_zxbcdt[(size_t)(b * SEQLEN + l) * D_IN_PROJ + (D_INNER + CONV_DIM) + h]
              + dt_bias[h];
    float dtv = (v > 20.f) ? v : log1pf(expf(v));
    float A = -expf(A_log[h]);
    g_dtT[idx] = dtv;
    g_dtAT[idx] = dtv * A;
}

// ---------------- causal depthwise conv + silu ----------------
__global__ void conv_kernel(const float* __restrict__ conv_w,
                            const float* __restrict__ conv_b) {
    int idx = blockIdx.x * blockDim.x + threadIdx.x;
    if (idx >= ROWS * CONV_DIM) return;
    int c = idx % CONV_DIM;
    int row = idx / CONV_DIM;
    int l = row & (SEQLEN - 1);
    float acc = conv_b[c];
#pragma unroll
    for (int k = 0; k < D_CONV; k++) {
        int ls = l + k - (D_CONV - 1);
        if (ls >= 0)
            acc += g_zxbcdt[(size_t)(row + k - (D_CONV - 1)) * D_IN_PROJ + D_INNER + c] *
                   conv_w[c * D_CONV + k];
    }
    g_xBC[idx] = acc / (1.f + expf(-acc));
}

// ================= chunked SSM scan (tensor-core) =================
#define SPITCH 72

// Phase A
__global__ void __launch_bounds__(256) chunk_state(void) {
    __shared__ __half sAh[CT * SPITCH], sAl[CT * SPITCH];
    __shared__ __half sBh[CT * SPITCH], sBl[CT * SPITCH];
    __shared__ float sL[CT], sdt[CT];
    const int c = blockIdx.x, h = blockIdx.y, b = blockIdx.z;
    const int tid = threadIdx.x;
    const int bh = b * NHEADS + h;
    const int rowbase = b * SEQLEN + c * CT;

    if (tid < CT) {
        sdt[tid] = g_dtT[(size_t)bh * SEQLEN + c * CT + tid];
        sL[tid]  = g_dtAT[(size_t)bh * SEQLEN + c * CT + tid];
    }
    __syncthreads();
    if (tid == 0) {
        float run = 0.f;
        for (int t = 0; t < CT; t++) { run += sL[t]; sL[t] = run; }
    }
    __syncthreads();
    const float Lend = sL[CT - 1];

    for (int e = tid; e < CT * 16; e += 256) {
        const int t = e >> 4, q = e & 15;
        const float* rowp = g_xBC + (size_t)(rowbase + t) * CONV_DIM;
        const float w = sdt[t] * expf(Lend - sL[t]);
        float4 xv = *(const float4*)(rowp + h * HEADDIM + q * 4);
        float4 bv = *(const float4*)(rowp + D_INNER + q * 4);
        const float xa[4] = {xv.x * w, xv.y * w, xv.z * w, xv.w * w};
        const float ba[4] = {bv.x, bv.y, bv.z, bv.w};
#pragma unroll
        for (int j = 0; j < 4; j++) {
            const int p = q * 4 + j;
            __half hx = __float2half(xa[j]);
            sAh[p * SPITCH + t] = hx;
            sAl[p * SPITCH + t] = __float2half(xa[j] - __half2float(hx));
            __half hb = __float2half(ba[j]);
            sBh[p * SPITCH + t] = hb;
            sBl[p * SPITCH + t] = __float2half(ba[j] - __half2float(hb));
        }
    }
    __syncthreads();

    const int wid = tid >> 5, lane = tid & 31;
    const int warp_m = wid & 3, warp_n = wid >> 2;
    const int a_row = lane & 15, a_col = (lane >> 4) * 8;
    const int b_row = (lane & 7) + ((lane >> 4) * 8), b_col = ((lane >> 3) & 1) * 8;
    const uint32_t uAh = (uint32_t)__cvta_generic_to_shared(sAh);
    const uint32_t uAl = (uint32_t)__cvta_generic_to_shared(sAl);
    const uint32_t uBh = (uint32_t)__cvta_generic_to_shared(sBh);
    const uint32_t uBl = (uint32_t)__cvta_generic_to_shared(sBl);

    float acc[4][4];
#pragma unroll
    for (int nt = 0; nt < 4; nt++)
#pragma unroll
        for (int i = 0; i < 4; i++) acc[nt][i] = 0.f;

#pragma unroll
    for (int kt = 0; kt < 4; kt++) {
        const int k0 = kt * 16;
        uint32_t ah[4], al[4], bh[2][4], bl[2][4];
        const uint32_t aoff = (uint32_t)((warp_m * 16 + a_row) * SPITCH + k0 + a_col) * 2;
        ldsm4(ah, uAh + aoff);
        ldsm4(al, uAl + aoff);
#pragma unroll
        for (int nb = 0; nb < 2; nb++) {
            const uint32_t boff =
                (uint32_t)((warp_n * 32 + nb * 16 + b_row) * SPITCH + k0 + b_col) * 2;
            ldsm4(bh[nb], uBh + boff);
            ldsm4(bl[nb], uBl + boff);
        }
#pragma unroll
        for (int nt = 0; nt < 4; nt++) {
            const int nb = nt >> 1, pr = (nt & 1) * 2;
            mma_f16(acc[nt], ah, bh[nb][pr], bh[nb][pr + 1]);
            mma_f16(acc[nt], ah, bl[nb][pr], bl[nb][pr + 1]);
            mma_f16(acc[nt], al, bh[nb][pr], bh[nb][pr + 1]);
        }
    }

    float* Sb = g_S + ((size_t)bh * NCHUNK + c) * (HEADDIM * D_STATE);
    const int g = lane >> 2, tig = lane & 3;
#pragma unroll
    for (int nt = 0; nt < 4; nt++) {
        const int ncol = warp_n * 32 + nt * 8 + 2 * tig;
        const int prow = warp_m * 16 + g;
        *(float2*)&Sb[prow * D_STATE + ncol] = make_float2(acc[nt][0], acc[nt][1]);
        *(float2*)&Sb[(prow + 8) * D_STATE + ncol] = make_float2(acc[nt][2], acc[nt][3]);
    }
    if (tid == 0) g_P[(size_t)bh * NCHUNK + c] = Lend;
}

// Phase B
__global__ void __launch_bounds__(256) state_pass(void) {
    const int bh = blockIdx.x;
    const int tid = threadIdx.x;
    float hreg[16];
#pragma unroll
    for (int i = 0; i < 16; i++) hreg[i] = 0.f;
    for (int c = 0; c < NCHUNK; c++) {
        float* Hb = g_H + ((size_t)bh * NCHUNK + c) * (HEADDIM * D_STATE);
        const float* Sb = g_S + ((size_t)bh * NCHUNK + c) * (HEADDIM * D_STATE);
        const float P = expf(g_P[(size_t)bh * NCHUNK + c]);
#pragma unroll
        for (int i = 0; i < 16; i++) {
            Hb[tid + i * 256] = hreg[i];
            hreg[i] = P * hreg[i] + Sb[tid + i * 256];
        }
    }
}

// Phase C
#define CTILE (CT * SPITCH)
#define CSMEM (10 * CTILE * 2 + 2 * CT * 4)
__global__ void __launch_bounds__(256) chunk_output(const float* __restrict__ Dparam) {
    extern __shared__ __half cs[];
    __half* sCh = cs;
    __half* sCl = cs + CTILE;
    __half* sB2h = cs + 2 * CTILE;
    __half* sB2l = cs + 3 * CTILE;
    __half* sXh = cs + 4 * CTILE;
    __half* sXl = cs + 5 * CTILE;
    __half* sHh = cs + 6 * CTILE;
    __half* sHl = cs + 7 * CTILE;
    __half* sGh = cs + 8 * CTILE;
    __half* sGl = cs + 9 * CTILE;
    float* sL = (float*)(cs + 10 * CTILE);
    float* sdt = sL + CT;

    const int c = blockIdx.x, h = blockIdx.y, b = blockIdx.z;
    const int tid = threadIdx.x;
    const int bh = b * NHEADS + h;
    const int rowbase = b * SEQLEN + c * CT;
    const float Dh = Dparam[h];

    if (tid < CT) {
        sdt[tid] = g_dtT[(size_t)bh * SEQLEN + c * CT + tid];
        sL[tid]  = g_dtAT[(size_t)bh * SEQLEN + c * CT + tid];
    }
    __syncthreads();
    if (tid == 0) {
        float run = 0.f;
        for (int t = 0; t < CT; t++) { run += sL[t]; sL[t] = run; }
    }

    const float* Hbase = g_H + ((size_t)bh * NCHUNK + c) * (HEADDIM * D_STATE);
    for (int e = tid; e < CT * 16; e += 256) {
        const int t = e >> 4, q = e & 15;
        const float* rowp = g_xBC + (size_t)(rowbase + t) * CONV_DIM;
        float4 cv = *(const float4*)(rowp + D_INNER + D_STATE + q * 4);
        float4 bv = *(const float4*)(rowp + D_INNER + q * 4);
        float4 xv = *(const float4*)(rowp + h * HEADDIM + q * 4);
        float4 hv = *(const float4*)(Hbase + t * D_STATE + q * 4);
        const float ca[4] = {cv.x, cv.y, cv.z, cv.w};
        const float ba[4] = {bv.x, bv.y, bv.z, bv.w};
        const float xa[4] = {xv.x, xv.y, xv.z, xv.w};
        const float ha[4] = {hv.x, hv.y, hv.z, hv.w};
#pragma unroll
        for (int j = 0; j < 4; j++) {
            const int n = q * 4 + j;
            __half hc = __float2half(ca[j]);
            sCh[t * SPITCH + n] = hc;
            sCl[t * SPITCH + n] = __float2half(ca[j] - __half2float(hc));
            __half hb = __float2half(ba[j]);
            sB2h[t * SPITCH + n] = hb;
            sB2l[t * SPITCH + n] = __float2half(ba[j] - __half2float(hb));
            __half hx = __float2half(xa[j]);
            sXh[n * SPITCH + t] = hx;
            sXl[n * SPITCH + t] = __float2half(xa[j] - __half2float(hx));
            __half hh = __float2half(ha[j]);
            sHh[t * SPITCH + n] = hh;
            sHl[t * SPITCH + n] = __float2half(ha[j] - __half2float(hh));
        }
    }
    __syncthreads();

    const int wid = tid >> 5, lane = tid & 31;
    const int warp_m = wid & 3, warp_n = wid >> 2;
    const int a_row = lane & 15, a_col = (lane >> 4) * 8;
    const int b_row = (lane & 7) + ((lane >> 4) * 8), b_col = ((lane >> 3) & 1) * 8;
    const int g = lane >> 2, tig = lane & 3;
    const uint32_t uCh = (uint32_t)__cvta_generic_to_shared(sCh);
    const uint32_t uCl = (uint32_t)__cvta_generic_to_shared(sCl);
    const uint32_t uB2h = (uint32_t)__cvta_generic_to_shared(sB2h);
    const uint32_t uB2l = (uint32_t)__cvta_generic_to_shared(sB2l);
    const uint32_t uXh = (uint32_t)__cvta_generic_to_shared(sXh);
    const uint32_t uXl = (uint32_t)__cvta_generic_to_shared(sXl);
    const uint32_t uHh = (uint32_t)__cvta_generic_to_shared(sHh);
    const uint32_t uHl = (uint32_t)__cvta_generic_to_shared(sHl);
    const uint32_t uGh = (uint32_t)__cvta_generic_to_shared(sGh);
    const uint32_t uGl = (uint32_t)__cvta_generic_to_shared(sGl);

    float gacc[4][4];
#pragma unroll
    for (int nt = 0; nt < 4; nt++)
#pragma unroll
        for (int i = 0; i < 4; i++) gacc[nt][i] = 0.f;
#pragma unroll
    for (int kt = 0; kt < 4; kt++) {
        const int k0 = kt * 16;
        uint32_t ah[4], al[4], bh[2][4], bl[2][4];
        const uint32_t aoff = (uint32_t)((warp_m * 16 + a_row) * SPITCH + k0 + a_col) * 2;
        ldsm4(ah, uCh + aoff);
        ldsm4(al, uCl + aoff);
#pragma unroll
        for (int nb = 0; nb < 2; nb++) {
            const uint32_t boff =
                (uint32_t)((warp_n * 32 + nb * 16 + b_row) * SPITCH + k0 + b_col) * 2;
            ldsm4(bh[nb], uB2h + boff);
            ldsm4(bl[nb], uB2l + boff);
        }
#pragma unroll
        for (int nt = 0; nt < 4; nt++) {
            const int nb = nt >> 1, pr = (nt & 1) * 2;
            mma_f16(gacc[nt], ah, bh[nb][pr], bh[nb][pr + 1]);
            mma_f16(gacc[nt], ah, bl[nb][pr], bl[nb][pr + 1]);
            mma_f16(gacc[nt], al, bh[nb][pr], bh[nb][pr + 1]);
        }
    }
    __syncthreads();

#pragma unroll
    for (int nt = 0; nt < 4; nt++) {
        const int s0 = warp_n * 32 + nt * 8 + 2 * tig;
#pragma unroll
        for (int r = 0; r < 2; r++) {
            const int t = warp_m * 16 + g + r * 8;
            float v0 = gacc[nt][r * 2], v1 = gacc[nt][r * 2 + 1];
            const float Lt = sL[t];
            v0 = (s0 <= t)     ? v0 * sdt[s0]     * expf(Lt - sL[s0])     : 0.f;
            v1 = (s0 + 1 <= t) ? v1 * sdt[s0 + 1] * expf(Lt - sL[s0 + 1]) : 0.f;
            __half h0 = __float2half(v0), h1 = __float2half(v1);
            *(__half2*)&sGh[t * SPITCH + s0] = __halves2half2(h0, h1);
            *(__half2*)&sGl[t * SPITCH + s0] = __halves2half2(
                __float2half(v0 - __half2float(h0)), __float2half(v1 - __half2float(h1)));
        }
    }
    __syncthreads();

    float yacc[4][4], cacc[4][4];
#pragma unroll
    for (int nt = 0; nt < 4; nt++)
#pragma unroll
        for (int i = 0; i < 4; i++) { yacc[nt][i] = 0.f; cacc[nt][i] = 0.f; }
#pragma unroll
    for (int kt = 0; kt < 4; kt++) {
        const int k0 = kt * 16;
        uint32_t gh[4], gl[4], ch[4], cl[4];
        uint32_t xh[2][4], xl[2][4], hh[2][4], hl[2][4];
        const uint32_t aoff = (uint32_t)((warp_m * 16 + a_row) * SPITCH + k0 + a_col) * 2;
        ldsm4(gh, uGh + aoff);
        ldsm4(gl, uGl + aoff);
        ldsm4(ch, uCh + aoff);
        ldsm4(cl, uCl + aoff);
#pragma unroll
        for (int nb = 0; nb < 2; nb++) {
            const uint32_t boff =
                (uint32_t)((warp_n * 32 + nb * 16 + b_row) * SPITCH + k0 + b_col) * 2;
            ldsm4(xh[nb], uXh + boff);
            ldsm4(xl[nb], uXl + boff);
            ldsm4(hh[nb], uHh + boff);
            ldsm4(hl[nb], uHl + boff);
        }
#pragma unroll
        for (int nt = 0; nt < 4; nt++) {
            const int nb = nt >> 1, pr = (nt & 1) * 2;
            mma_f16(yacc[nt], gh, xh[nb][pr], xh[nb][pr + 1]);
            mma_f16(yacc[nt], gh, xl[nb][pr], xl[nb][pr + 1]);
            mma_f16(yacc[nt], gl, xh[nb][pr], xh[nb][pr + 1]);
            mma_f16(cacc[nt], ch, hh[nb][pr], hh[nb][pr + 1]);
            mma_f16(cacc[nt], ch, hl[nb][pr], hl[nb][pr + 1]);
            mma_f16(cacc[nt], cl, hh[nb][pr], hh[nb][pr + 1]);
        }
    }

#pragma unroll
    for (int nt = 0; nt < 4; nt++) {
        const int p = warp_n * 32 + nt * 8 + 2 * tig;
#pragma unroll
        for (int r = 0; r < 2; r++) {
            const int t = warp_m * 16 + g + r * 8;
            const float et = expf(sL[t]);
            const float x0 = __half2float(sXh[p * SPITCH + t]) + __half2float(sXl[p * SPITCH + t]);
            const float x1 = __half2float(sXh[(p + 1) * SPITCH + t]) + __half2float(sXl[(p + 1) * SPITCH + t]);
            const float o0 = yacc[nt][r * 2] + cacc[nt][r * 2] * et + Dh * x0;
            const float o1 = yacc[nt][r * 2 + 1] + cacc[nt][r * 2 + 1] * et + Dh * x1;
            *(float2*)&g_y[(size_t)(rowbase + t) * D_INNER + h * HEADDIM + p] =
                make_float2(o0, o1);
        }
    }
}

// ---------------- gate + RMSNorm, writing fp16 ----------------
__global__ void __launch_bounds__(256) norm_kernel(const float* __restrict__ norm_w) {
    const int row = blockIdx.x;
    const int tid = threadIdx.x;
    const float* zrow = g_zxbcdt + (size_t)row * D_IN_PROJ;
    const float* yrow = g_y + (size_t)row * D_INNER;
    __half* hrow = g_yh + (size_t)row * D_INNER;

    float vals[6];
    float ss = 0.f;
#pragma unroll
    for (int i = 0; i < 6; i++) {
        int c = tid + i * 256;
        float z = zrow[c];
        float yv = yrow[c] * (z / (1.f + expf(-z)));
        vals[i] = yv;
        ss += yv * yv;
    }
#pragma unroll
    for (int o = 16; o; o >>= 1) ss += __shfl_xor_sync(0xffffffffu, ss, o);
    __shared__ float red[8];
    if ((tid & 31) == 0) red[tid >> 5] = ss;
    __syncthreads();
    if (tid < 8) {
        float v = red[tid];
#pragma unroll
        for (int o = 4; o; o >>= 1) v += __shfl_xor_sync(0xffu, v, o);
        if (tid == 0) red[0] = v;
    }
    __syncthreads();
    const float scale = rsqrtf(red[0] * (1.f / D_INNER) + 1e-5f);
#pragma unroll
    for (int i = 0; i < 6; i++) {
        int c = tid + i * 256;
        hrow[c] = __float2half(vals[i] * scale * norm_w[c]);
    }
}

// ---------------- launch ----------------
extern "C" void kernel_launch(void* const* d_in, const int* in_sizes, int n_in,
                              void* d_out, int out_size) {
    const float* x       = (const float*)d_in[0];
    const float* W_in    = (const float*)d_in[1];
    const float* conv_w  = (const float*)d_in[2];
    const float* conv_b  = (const float*)d_in[3];
    const float* dt_bias = (const float*)d_in[4];
    const float* A_log   = (const float*)d_in[5];
    const float* Dp      = (const float*)d_in[6];
    const float* norm_w  = (const float*)d_in[7];
    const float* W_out   = (const float*)d_in[8];
    float* out = (float*)d_out;

    float *zx_ptr;
    cudaGetSymbolAddress((void**)&zx_ptr, g_zxbcdt);
    __half *xh, *yh, *wi, *wo;
    cudaGetSymbolAddress((void**)&xh, g_xh);
    cudaGetSymbolAddress((void**)&yh, g_yh);
    cudaGetSymbolAddress((void**)&wi, g_wi);
    cudaGetSymbolAddress((void**)&wo, g_wo);

    static int attr_set = 0;
    if (!attr_set) {
        cudaFuncSetAttribute(mma_gemm, cudaFuncAttributeMaxDynamicSharedMemorySize, GSMEM);
        cudaFuncSetAttribute(chunk_output, cudaFuncAttributeMaxDynamicSharedMemorySize, CSMEM);
        attr_set = 1;
    }

    // 0-2) conversions
    convert_f16<<<(ROWS * D_MODEL / 4 + 255) / 256, 256>>>(x, xh, ROWS * D_MODEL / 4);
    transpose_f16<<<dim3(NPAD1 / 32, D_MODEL / 32), dim3(32, 8)>>>(
        W_in, wi, D_MODEL, D_IN_PROJ, NPAD1);
    transpose_f16<<<dim3(D_MODEL / 32, D_INNER / 32), dim3(32, 8)>>>(
        W_out, wo, D_INNER, D_MODEL, D_MODEL);

    // 3) zxbcdt = x @ W_in   (launch index 3 -> ncu slot)
    mma_gemm<<<dim3(NPAD1 / 128, ROWS / 128), 256, GSMEM>>>(
        xh, wi, zx_ptr, ROWS, D_IN_PROJ, D_MODEL);

    // 4) dt / dtA
    dt_kernel<<<(BATCH * NHEADS * SEQLEN + 255) / 256, 256>>>(dt_bias, A_log);

    // 5) conv + silu
    conv_kernel<<<((size_t)ROWS * CONV_DIM + 255) / 256, 256>>>(conv_w, conv_b);

    // 6-8) chunked SSM scan
    chunk_state<<<dim3(NCHUNK, NHEADS, BATCH), 256>>>();
    state_pass<<<BATCH * NHEADS, 256>>>();
    chunk_output<<<dim3(NCHUNK, NHEADS, BATCH), 256, CSMEM>>>(Dp);

    // 9) gate + RMSNorm
    norm_kernel<<<ROWS, 256>>>(norm_w);

    // 10) out = y @ W_out
    mma_gemm<<<dim3(D_MODEL / 128, ROWS / 128), 256, GSMEM>>>(
        yh, wo, out, ROWS, D_MODEL, D_INNER);
}

// round 11
// speedup vs baseline: 1.3441x; 1.2342x over previous
#include <cuda_runtime.h>
#include <cuda_fp16.h>
#include <math.h>
#include <stdint.h>

#define D_MODEL   768
#define D_STATE   64
#define D_CONV    4
#define HEADDIM   64
#define D_INNER   1536
#define NHEADS    24
#define CONV_DIM  1664
#define D_IN_PROJ 3224
#define BATCH     2
#define SEQLEN    4096
#define ROWS      (BATCH*SEQLEN)
#define NPAD1     3328
#define NCHUNK    64
#define CT        64

// ---------------- scratch (device globals; no allocation) ----------------
__device__ float g_zxbcdt[(size_t)ROWS * D_IN_PROJ];
__device__ float g_xBC[(size_t)ROWS * CONV_DIM];
__device__ float g_y[(size_t)ROWS * D_INNER];
__device__ float g_dtT[(size_t)BATCH * NHEADS * SEQLEN];
__device__ float g_dtAT[(size_t)BATCH * NHEADS * SEQLEN];
__device__ float g_S[(size_t)BATCH * NHEADS * NCHUNK * HEADDIM * D_STATE];
__device__ float g_H[(size_t)BATCH * NHEADS * NCHUNK * HEADDIM * D_STATE];
__device__ float g_P[(size_t)BATCH * NHEADS * NCHUNK];
__device__ __half g_xh[(size_t)ROWS * D_MODEL];
__device__ __half g_yh[(size_t)ROWS * D_INNER];
__device__ __half g_wi[(size_t)NPAD1 * D_MODEL];
__device__ __half g_wo[(size_t)D_MODEL * D_INNER];

// ---------------- common PTX helpers ----------------
__device__ __forceinline__ void cp16(uint32_t dst, const void* src) {
    asm volatile("cp.async.ca.shared.global [%0], [%1], 16;" :: "r"(dst), "l"(src) : "memory");
}
__device__ __forceinline__ void cp_commit() {
    asm volatile("cp.async.commit_group;" ::: "memory");
}
template <int N> __device__ __forceinline__ void cp_wait() {
    asm volatile("cp.async.wait_group %0;" :: "n"(N) : "memory");
}
__device__ __forceinline__ void ldsm4(uint32_t* r, uint32_t addr) {
    asm volatile("ldmatrix.sync.aligned.m8n8.x4.shared.b16 {%0,%1,%2,%3}, [%4];"
                 : "=r"(r[0]), "=r"(r[1]), "=r"(r[2]), "=r"(r[3]) : "r"(addr));
}
__device__ __forceinline__ void mma_f16(float* d, const uint32_t* a, uint32_t b0, uint32_t b1) {
    asm volatile("mma.sync.aligned.m16n8k16.row.col.f32.f16.f16.f32 "
                 "{%0,%1,%2,%3}, {%4,%5,%6,%7}, {%8,%9}, {%0,%1,%2,%3};"
                 : "+f"(d[0]), "+f"(d[1]), "+f"(d[2]), "+f"(d[3])
                 : "r"(a[0]), "r"(a[1]), "r"(a[2]), "r"(a[3]), "r"(b0), "r"(b1));
}

// ---------------- warp-MMA fp16 GEMM (R8 best config: KC=32, 2 CTA/SM) ----------------
#define KC      32
#define PITCH   40
#define TILE_E  (128 * PITCH)
#define TILE_B  (TILE_E * 2)
#define STAGE_B (2 * TILE_B)
#define STAGES  3
#define GSMEM   (STAGES * STAGE_B)      // 61440 bytes

__global__ void __launch_bounds__(256, 2) mma_gemm(
    const __half* __restrict__ Ah, const __half* __restrict__ Bh,
    float* __restrict__ C, int M, int N, int K) {
    extern __shared__ __half sm[];
    const int tid = threadIdx.x;
    const int wid = tid >> 5, lane = tid & 31;
    const int warp_m = wid >> 1, warp_n = wid & 1;
    const int g = lane >> 2, tig = lane & 3;
    const int bm = blockIdx.y * 128, bn = blockIdx.x * 128;
    const uint32_t sbase = (uint32_t)__cvta_generic_to_shared(sm);

    float acc[2][8][4];
#pragma unroll
    for (int mt = 0; mt < 2; mt++)
#pragma unroll
        for (int nt = 0; nt < 8; nt++)
#pragma unroll
            for (int i = 0; i < 4; i++) acc[mt][nt][i] = 0.f;

    const int nkt = K / KC;
    const int r_ld = tid >> 2, seg_ld = tid & 3;

    auto issue = [&](int kt) {
        const int st = kt % STAGES;
        const int kofs = kt * KC;
        const uint32_t dst0 = sbase + st * STAGE_B;
        const __half* srcs[2] = {Ah, Bh};
#pragma unroll
        for (int arr = 0; arr < 2; arr++) {
            const int rbase = (arr == 0) ? bm : bn;
            const uint32_t db = dst0 + arr * TILE_B;
#pragma unroll
            for (int i = 0; i < 2; i++) {
                const int r = r_ld + i * 64;
                cp16(db + (uint32_t)(r * PITCH + seg_ld * 8) * 2,
                     srcs[arr] + (size_t)(rbase + r) * K + kofs + seg_ld * 8);
            }
        }
    };

    issue(0); cp_commit();
    if (nkt > 1) { issue(1); cp_commit(); }

    const int a_row = (lane & 15);
    const int a_col = (lane >> 4) * 8;
    const int b_row = (lane & 7) + ((lane >> 4) * 8);
    const int b_col = ((lane >> 3) & 1) * 8;

    for (int kt = 0; kt < nkt; kt++) {
        if (kt + 2 < nkt) cp_wait<1>(); else cp_wait<0>();
        __syncthreads();
        if (kt + 2 < nkt) { issue(kt + 2); cp_commit(); }

        const uint32_t st0 = sbase + (kt % STAGES) * STAGE_B;
        const uint32_t aA = st0;
        const uint32_t bB = st0 + TILE_B;

#pragma unroll
        for (int ks = 0; ks < KC; ks += 16) {
            uint32_t ah[2][4], bf[4][4];
#pragma unroll
            for (int mt = 0; mt < 2; mt++) {
                const uint32_t aoff =
                    (uint32_t)((warp_m * 32 + mt * 16 + a_row) * PITCH + ks + a_col) * 2;
                ldsm4(ah[mt], aA + aoff);
            }
#pragma unroll
            for (int ntp = 0; ntp < 4; ntp++) {
                const uint32_t boff =
                    (uint32_t)((warp_n * 64 + ntp * 16 + b_row) * PITCH + ks + b_col) * 2;
                ldsm4(bf[ntp], bB + boff);
            }
#pragma unroll
            for (int nt = 0; nt < 8; nt++) {
                const uint32_t b0 = bf[nt >> 1][(nt & 1) * 2];
                const uint32_t b1 = bf[nt >> 1][(nt & 1) * 2 + 1];
#pragma unroll
                for (int mt = 0; mt < 2; mt++)
                    mma_f16(acc[mt][nt], ah[mt], b0, b1);
            }
        }
        __syncthreads();
    }

#pragma unroll
    for (int mt = 0; mt < 2; mt++) {
        const int row0 = bm + warp_m * 32 + mt * 16 + g;
#pragma unroll
        for (int nt = 0; nt < 8; nt++) {
            const int col = bn + warp_n * 64 + nt * 8 + 2 * tig;
            if (col < N) {
                *(float2*)&C[(size_t)row0 * N + col] = make_float2(acc[mt][nt][0], acc[mt][nt][1]);
                *(float2*)&C[(size_t)(row0 + 8) * N + col] = make_float2(acc[mt][nt][2], acc[mt][nt][3]);
            }
        }
    }
}

// ---------------- fp32 -> fp16 convert ----------------
__global__ void convert_f16(const float* __restrict__ src,
                            __half* __restrict__ dst, int n4) {
    int i = blockIdx.x * blockDim.x + threadIdx.x;
    if (i >= n4) return;
    const int idx = i * 4;
    float4 v = *(const float4*)(src + idx);
    __half h[4];
    h[0] = __float2half(v.x); h[1] = __float2half(v.y);
    h[2] = __float2half(v.z); h[3] = __float2half(v.w);
    *(uint2*)(dst + idx) = *(uint2*)h;
}

// ---------------- transpose to fp16 ----------------
__global__ void transpose_f16(const float* __restrict__ src,
                              __half* __restrict__ dst,
                              int R, int C, int Cpad) {
    __shared__ float tile[32][33];
    const int c0 = blockIdx.x * 32, r0 = blockIdx.y * 32;
    const int tx = threadIdx.x, ty = threadIdx.y;
    const int c = c0 + tx;
#pragma unroll
    for (int j = ty; j < 32; j += 8) {
        const int r = r0 + j;
        tile[j][tx] = (r < R && c < C) ? src[(size_t)r * C + c] : 0.f;
    }
    __syncthreads();
#pragma unroll
    for (int j = ty; j < 32; j += 8) {
        const int orow = c0 + j;
        const int ocol = r0 + tx;
        if (orow < Cpad && ocol < R)
            dst[(size_t)orow * R + ocol] = __float2half(tile[tx][j]);
    }
}

// ---------------- dt ----------------
__global__ void dt_kernel(const float* __restrict__ dt_bias,
                          const float* __restrict__ A_log) {
    int idx = blockIdx.x * blockDim.x + threadIdx.x;
    if (idx >= BATCH * NHEADS * SEQLEN) return;
    const int l = idx % SEQLEN;
    const int bh = idx / SEQLEN;
    const int h = bh % NHEADS, b = bh / NHEADS;
    float v = g_zxbcdt[(size_t)(b * SEQLEN + l) * D_IN_PROJ + (D_INNER + CONV_DIM) + h]
              + dt_bias[h];
    float dtv = (v > 20.f) ? v : log1pf(expf(v));
    float A = -expf(A_log[h]);
    g_dtT[idx] = dtv;
    g_dtAT[idx] = dtv * A;
}

// ---------------- causal depthwise conv + silu (float4 over channels) ----------------
__global__ void conv_kernel(const float* __restrict__ conv_w,
                            const float* __restrict__ conv_b) {
    int i = blockIdx.x * blockDim.x + threadIdx.x;
    if (i >= ROWS * (CONV_DIM / 4)) return;
    const int c4 = (i % (CONV_DIM / 4)) * 4;
    const int row = i / (CONV_DIM / 4);
    const int l = row & (SEQLEN - 1);

    float4 acc = *(const float4*)(conv_b + c4);
    const float4 w0 = *(const float4*)(conv_w + (c4 + 0) * 4);
    const float4 w1 = *(const float4*)(conv_w + (c4 + 1) * 4);
    const float4 w2 = *(const float4*)(conv_w + (c4 + 2) * 4);
    const float4 w3 = *(const float4*)(conv_w + (c4 + 3) * 4);
    const float wt0[4] = {w0.x, w0.y, w0.z, w0.w};
    const float wt1[4] = {w1.x, w1.y, w1.z, w1.w};
    const float wt2[4] = {w2.x, w2.y, w2.z, w2.w};
    const float wt3[4] = {w3.x, w3.y, w3.z, w3.w};

#pragma unroll
    for (int k = 0; k < D_CONV; k++) {
        const int ls = l + k - (D_CONV - 1);
        if (ls >= 0) {
            float4 v = *(const float4*)(g_zxbcdt +
                (size_t)(row + k - (D_CONV - 1)) * D_IN_PROJ + D_INNER + c4);
            acc.x += v.x * wt0[k];
            acc.y += v.y * wt1[k];
            acc.z += v.z * wt2[k];
            acc.w += v.w * wt3[k];
        }
    }
    acc.x = acc.x / (1.f + expf(-acc.x));
    acc.y = acc.y / (1.f + expf(-acc.y));
    acc.z = acc.z / (1.f + expf(-acc.z));
    acc.w = acc.w / (1.f + expf(-acc.w));
    *(float4*)(g_xBC + (size_t)row * CONV_DIM + c4) = acc;
}

// ================= chunked SSM scan (tensor-core) =================
#define SPITCH 72

// Phase A
__global__ void __launch_bounds__(256) chunk_state(void) {
    __shared__ __half sAh[CT * SPITCH], sAl[CT * SPITCH];
    __shared__ __half sBh[CT * SPITCH], sBl[CT * SPITCH];
    __shared__ float sL[CT], sdt[CT];
    const int c = blockIdx.x, h = blockIdx.y, b = blockIdx.z;
    const int tid = threadIdx.x;
    const int bh = b * NHEADS + h;
    const int rowbase = b * SEQLEN + c * CT;

    if (tid < CT) {
        sdt[tid] = g_dtT[(size_t)bh * SEQLEN + c * CT + tid];
        sL[tid]  = g_dtAT[(size_t)bh * SEQLEN + c * CT + tid];
    }
    __syncthreads();
    if (tid == 0) {
        float run = 0.f;
        for (int t = 0; t < CT; t++) { run += sL[t]; sL[t] = run; }
    }
    __syncthreads();
    const float Lend = sL[CT - 1];

    for (int e = tid; e < CT * 16; e += 256) {
        const int t = e >> 4, q = e & 15;
        const float* rowp = g_xBC + (size_t)(rowbase + t) * CONV_DIM;
        const float w = sdt[t] * expf(Lend - sL[t]);
        float4 xv = *(const float4*)(rowp + h * HEADDIM + q * 4);
        float4 bv = *(const float4*)(rowp + D_INNER + q * 4);
        const float xa[4] = {xv.x * w, xv.y * w, xv.z * w, xv.w * w};
        const float ba[4] = {bv.x, bv.y, bv.z, bv.w};
#pragma unroll
        for (int j = 0; j < 4; j++) {
            const int p = q * 4 + j;
            __half hx = __float2half(xa[j]);
            sAh[p * SPITCH + t] = hx;
            sAl[p * SPITCH + t] = __float2half(xa[j] - __half2float(hx));
            __half hb = __float2half(ba[j]);
            sBh[p * SPITCH + t] = hb;
            sBl[p * SPITCH + t] = __float2half(ba[j] - __half2float(hb));
        }
    }
    __syncthreads();

    const int wid = tid >> 5, lane = tid & 31;
    const int warp_m = wid & 3, warp_n = wid >> 2;
    const int a_row = lane & 15, a_col = (lane >> 4) * 8;
    const int b_row = (lane & 7) + ((lane >> 4) * 8), b_col = ((lane >> 3) & 1) * 8;
    const uint32_t uAh = (uint32_t)__cvta_generic_to_shared(sAh);
    const uint32_t uAl = (uint32_t)__cvta_generic_to_shared(sAl);
    const uint32_t uBh = (uint32_t)__cvta_generic_to_shared(sBh);
    const uint32_t uBl = (uint32_t)__cvta_generic_to_shared(sBl);

    float acc[4][4];
#pragma unroll
    for (int nt = 0; nt < 4; nt++)
#pragma unroll
        for (int i = 0; i < 4; i++) acc[nt][i] = 0.f;

#pragma unroll
    for (int kt = 0; kt < 4; kt++) {
        const int k0 = kt * 16;
        uint32_t ah[4], al[4], bh[2][4], bl[2][4];
        const uint32_t aoff = (uint32_t)((warp_m * 16 + a_row) * SPITCH + k0 + a_col) * 2;
        ldsm4(ah, uAh + aoff);
        ldsm4(al, uAl + aoff);
#pragma unroll
        for (int nb = 0; nb < 2; nb++) {
            const uint32_t boff =
                (uint32_t)((warp_n * 32 + nb * 16 + b_row) * SPITCH + k0 + b_col) * 2;
            ldsm4(bh[nb], uBh + boff);
            ldsm4(bl[nb], uBl + boff);
        }
#pragma unroll
        for (int nt = 0; nt < 4; nt++) {
            const int nb = nt >> 1, pr = (nt & 1) * 2;
            mma_f16(acc[nt], ah, bh[nb][pr], bh[nb][pr + 1]);
            mma_f16(acc[nt], ah, bl[nb][pr], bl[nb][pr + 1]);
            mma_f16(acc[nt], al, bh[nb][pr], bh[nb][pr + 1]);
        }
    }

    float* Sb = g_S + ((size_t)bh * NCHUNK + c) * (HEADDIM * D_STATE);
    const int g = lane >> 2, tig = lane & 3;
#pragma unroll
    for (int nt = 0; nt < 4; nt++) {
        const int ncol = warp_n * 32 + nt * 8 + 2 * tig;
        const int prow = warp_m * 16 + g;
        *(float2*)&Sb[prow * D_STATE + ncol] = make_float2(acc[nt][0], acc[nt][1]);
        *(float2*)&Sb[(prow + 8) * D_STATE + ncol] = make_float2(acc[nt][2], acc[nt][3]);
    }
    if (tid == 0) g_P[(size_t)bh * NCHUNK + c] = Lend;
}

// Phase B: fully parallel over state elements; one thread per element
#define SPB 16
__global__ void __launch_bounds__(256) state_pass(void) {
    const int blk = blockIdx.x;
    const int bh = blk / SPB, seg = blk % SPB;
    const int e = seg * 256 + threadIdx.x;
    __shared__ float sP[NCHUNK];
    if (threadIdx.x < NCHUNK)
        sP[threadIdx.x] = expf(g_P[(size_t)bh * NCHUNK + threadIdx.x]);
    __syncthreads();
    float hv = 0.f;
    const size_t base = (size_t)bh * NCHUNK * (HEADDIM * D_STATE) + e;
#pragma unroll 4
    for (int c = 0; c < NCHUNK; c++) {
        const size_t off = base + (size_t)c * (HEADDIM * D_STATE);
        g_H[off] = hv;
        hv = sP[c] * hv + g_S[off];
    }
}

// Phase C
#define CTILE (CT * SPITCH)
#define CSMEM (10 * CTILE * 2 + 2 * CT * 4)
__global__ void __launch_bounds__(256) chunk_output(const float* __restrict__ Dparam) {
    extern __shared__ __half cs[];
    __half* sCh = cs;
    __half* sCl = cs + CTILE;
    __half* sB2h = cs + 2 * CTILE;
    __half* sB2l = cs + 3 * CTILE;
    __half* sXh = cs + 4 * CTILE;
    __half* sXl = cs + 5 * CTILE;
    __half* sHh = cs + 6 * CTILE;
    __half* sHl = cs + 7 * CTILE;
    __half* sGh = cs + 8 * CTILE;
    __half* sGl = cs + 9 * CTILE;
    float* sL = (float*)(cs + 10 * CTILE);
    float* sdt = sL + CT;

    const int c = blockIdx.x, h = blockIdx.y, b = blockIdx.z;
    const int tid = threadIdx.x;
    const int bh = b * NHEADS + h;
    const int rowbase = b * SEQLEN + c * CT;
    const float Dh = Dparam[h];

    if (tid < CT) {
        sdt[tid] = g_dtT[(size_t)bh * SEQLEN + c * CT + tid];
        sL[tid]  = g_dtAT[(size_t)bh * SEQLEN + c * CT + tid];
    }
    __syncthreads();
    if (tid == 0) {
        float run = 0.f;
        for (int t = 0; t < CT; t++) { run += sL[t]; sL[t] = run; }
    }

    const float* Hbase = g_H + ((size_t)bh * NCHUNK + c) * (HEADDIM * D_STATE);
    for (int e = tid; e < CT * 16; e += 256) {
        const int t = e >> 4, q = e & 15;
        const float* rowp = g_xBC + (size_t)(rowbase + t) * CONV_DIM;
        float4 cv = *(const float4*)(rowp + D_INNER + D_STATE + q * 4);
        float4 bv = *(const float4*)(rowp + D_INNER + q * 4);
        float4 xv = *(const float4*)(rowp + h * HEADDIM + q * 4);
        float4 hv = *(const float4*)(Hbase + t * D_STATE + q * 4);
        const float ca[4] = {cv.x, cv.y, cv.z, cv.w};
        const float ba[4] = {bv.x, bv.y, bv.z, bv.w};
        const float xa[4] = {xv.x, xv.y, xv.z, xv.w};
        const float ha[4] = {hv.x, hv.y, hv.z, hv.w};
#pragma unroll
        for (int j = 0; j < 4; j++) {
            const int n = q * 4 + j;
            __half hc = __float2half(ca[j]);
            sCh[t * SPITCH + n] = hc;
            sCl[t * SPITCH + n] = __float2half(ca[j] - __half2float(hc));
            __half hb = __float2half(ba[j]);
            sB2h[t * SPITCH + n] = hb;
            sB2l[t * SPITCH + n] = __float2half(ba[j] - __half2float(hb));
            __half hx = __float2half(xa[j]);
            sXh[n * SPITCH + t] = hx;
            sXl[n * SPITCH + t] = __float2half(xa[j] - __half2float(hx));
            __half hh = __float2half(ha[j]);
            sHh[t * SPITCH + n] = hh;
            sHl[t * SPITCH + n] = __float2half(ha[j] - __half2float(hh));
        }
    }
    __syncthreads();

    const int wid = tid >> 5, lane = tid & 31;
    const int warp_m = wid & 3, warp_n = wid >> 2;
    const int a_row = lane & 15, a_col = (lane >> 4) * 8;
    const int b_row = (lane & 7) + ((lane >> 4) * 8), b_col = ((lane >> 3) & 1) * 8;
    const int g = lane >> 2, tig = lane & 3;
    const uint32_t uCh = (uint32_t)__cvta_generic_to_shared(sCh);
    const uint32_t uCl = (uint32_t)__cvta_generic_to_shared(sCl);
    const uint32_t uB2h = (uint32_t)__cvta_generic_to_shared(sB2h);
    const uint32_t uB2l = (uint32_t)__cvta_generic_to_shared(sB2l);
    const uint32_t uXh = (uint32_t)__cvta_generic_to_shared(sXh);
    const uint32_t uXl = (uint32_t)__cvta_generic_to_shared(sXl);
    const uint32_t uHh = (uint32_t)__cvta_generic_to_shared(sHh);
    const uint32_t uHl = (uint32_t)__cvta_generic_to_shared(sHl);
    const uint32_t uGh = (uint32_t)__cvta_generic_to_shared(sGh);
    const uint32_t uGl = (uint32_t)__cvta_generic_to_shared(sGl);

    float gacc[4][4];
#pragma unroll
    for (int nt = 0; nt < 4; nt++)
#pragma unroll
        for (int i = 0; i < 4; i++) gacc[nt][i] = 0.f;
#pragma unroll
    for (int kt = 0; kt < 4; kt++) {
        const int k0 = kt * 16;
        uint32_t ah[4], al[4], bh[2][4], bl[2][4];
        const uint32_t aoff = (uint32_t)((warp_m * 16 + a_row) * SPITCH + k0 + a_col) * 2;
        ldsm4(ah, uCh + aoff);
        ldsm4(al, uCl + aoff);
#pragma unroll
        for (int nb = 0; nb < 2; nb++) {
            const uint32_t boff =
                (uint32_t)((warp_n * 32 + nb * 16 + b_row) * SPITCH + k0 + b_col) * 2;
            ldsm4(bh[nb], uB2h + boff);
            ldsm4(bl[nb], uB2l + boff);
        }
#pragma unroll
        for (int nt = 0; nt < 4; nt++) {
            const int nb = nt >> 1, pr = (nt & 1) * 2;
            mma_f16(gacc[nt], ah, bh[nb][pr], bh[nb][pr + 1]);
            mma_f16(gacc[nt], ah, bl[nb][pr], bl[nb][pr + 1]);
            mma_f16(gacc[nt], al, bh[nb][pr], bh[nb][pr + 1]);
        }
    }
    __syncthreads();

#pragma unroll
    for (int nt = 0; nt < 4; nt++) {
        const int s0 = warp_n * 32 + nt * 8 + 2 * tig;
#pragma unroll
        for (int r = 0; r < 2; r++) {
            const int t = warp_m * 16 + g + r * 8;
            float v0 = gacc[nt][r * 2], v1 = gacc[nt][r * 2 + 1];
            const float Lt = sL[t];
            v0 = (s0 <= t)     ? v0 * sdt[s0]     * expf(Lt - sL[s0])     : 0.f;
            v1 = (s0 + 1 <= t) ? v1 * sdt[s0 + 1] * expf(Lt - sL[s0 + 1]) : 0.f;
            __half h0 = __float2half(v0), h1 = __float2half(v1);
            *(__half2*)&sGh[t * SPITCH + s0] = __halves2half2(h0, h1);
            *(__half2*)&sGl[t * SPITCH + s0] = __halves2half2(
                __float2half(v0 - __half2float(h0)), __float2half(v1 - __half2float(h1)));
        }
    }
    __syncthreads();

    float yacc[4][4], cacc[4][4];
#pragma unroll
    for (int nt = 0; nt < 4; nt++)
#pragma unroll
        for (int i = 0; i < 4; i++) { yacc[nt][i] = 0.f; cacc[nt][i] = 0.f; }
#pragma unroll
    for (int kt = 0; kt < 4; kt++) {
        const int k0 = kt * 16;
        uint32_t gh[4], gl[4], ch[4], cl[4];
        uint32_t xh[2][4], xl[2][4], hh[2][4], hl[2][4];
        const uint32_t aoff = (uint32_t)((warp_m * 16 + a_row) * SPITCH + k0 + a_col) * 2;
        ldsm4(gh, uGh + aoff);
        ldsm4(gl, uGl + aoff);
        ldsm4(ch, uCh + aoff);
        ldsm4(cl, uCl + aoff);
#pragma unroll
        for (int nb = 0; nb < 2; nb++) {
            const uint32_t boff =
                (uint32_t)((warp_n * 32 + nb * 16 + b_row) * SPITCH + k0 + b_col) * 2;
            ldsm4(xh[nb], uXh + boff);
            ldsm4(xl[nb], uXl + boff);
            ldsm4(hh[nb], uHh + boff);
            ldsm4(hl[nb], uHl + boff);
        }
#pragma unroll
        for (int nt = 0; nt < 4; nt++) {
            const int nb = nt >> 1, pr = (nt & 1) * 2;
            mma_f16(yacc[nt], gh, xh[nb][pr], xh[nb][pr + 1]);
            mma_f16(yacc[nt], gh, xl[nb][pr], xl[nb][pr + 1]);
            mma_f16(yacc[nt], gl, xh[nb][pr], xh[nb][pr + 1]);
            mma_f16(cacc[nt], ch, hh[nb][pr], hh[nb][pr + 1]);
            mma_f16(cacc[nt], ch, hl[nb][pr], hl[nb][pr + 1]);
            mma_f16(cacc[nt], cl, hh[nb][pr], hh[nb][pr + 1]);
        }
    }

#pragma unroll
    for (int nt = 0; nt < 4; nt++) {
        const int p = warp_n * 32 + nt * 8 + 2 * tig;
#pragma unroll
        for (int r = 0; r < 2; r++) {
            const int t = warp_m * 16 + g + r * 8;
            const float et = expf(sL[t]);
            const float x0 = __half2float(sXh[p * SPITCH + t]) + __half2float(sXl[p * SPITCH + t]);
            const float x1 = __half2float(sXh[(p + 1) * SPITCH + t]) + __half2float(sXl[(p + 1) * SPITCH + t]);
            const float o0 = yacc[nt][r * 2] + cacc[nt][r * 2] * et + Dh * x0;
            const float o1 = yacc[nt][r * 2 + 1] + cacc[nt][r * 2 + 1] * et + Dh * x1;
            *(float2*)&g_y[(size_t)(rowbase + t) * D_INNER + h * HEADDIM + p] =
                make_float2(o0, o1);
        }
    }
}

// ---------------- gate + RMSNorm, writing fp16 ----------------
__global__ void __launch_bounds__(256) norm_kernel(const float* __restrict__ norm_w) {
    const int row = blockIdx.x;
    const int tid = threadIdx.x;
    const float* zrow = g_zxbcdt + (size_t)row * D_IN_PROJ;
    const float* yrow = g_y + (size_t)row * D_INNER;
    __half* hrow = g_yh + (size_t)row * D_INNER;

    float vals[6];
    float ss = 0.f;
#pragma unroll
    for (int i = 0; i < 6; i++) {
        int c = tid + i * 256;
        float z = zrow[c];
        float yv = yrow[c] * (z / (1.f + expf(-z)));
        vals[i] = yv;
        ss += yv * yv;
    }
#pragma unroll
    for (int o = 16; o; o >>= 1) ss += __shfl_xor_sync(0xffffffffu, ss, o);
    __shared__ float red[8];
    if ((tid & 31) == 0) red[tid >> 5] = ss;
    __syncthreads();
    if (tid < 8) {
        float v = red[tid];
#pragma unroll
        for (int o = 4; o; o >>= 1) v += __shfl_xor_sync(0xffu, v, o);
        if (tid == 0) red[0] = v;
    }
    __syncthreads();
    const float scale = rsqrtf(red[0] * (1.f / D_INNER) + 1e-5f);
#pragma unroll
    for (int i = 0; i < 6; i++) {
        int c = tid + i * 256;
        hrow[c] = __float2half(vals[i] * scale * norm_w[c]);
    }
}

// ---------------- launch ----------------
extern "C" void kernel_launch(void* const* d_in, const int* in_sizes, int n_in,
                              void* d_out, int out_size) {
    const float* x       = (const float*)d_in[0];
    const float* W_in    = (const float*)d_in[1];
    const float* conv_w  = (const float*)d_in[2];
    const float* conv_b  = (const float*)d_in[3];
    const float* dt_bias = (const float*)d_in[4];
    const float* A_log   = (const float*)d_in[5];
    const float* Dp      = (const float*)d_in[6];
    const float* norm_w  = (const float*)d_in[7];
    const float* W_out   = (const float*)d_in[8];
    float* out = (float*)d_out;

    float *zx_ptr;
    cudaGetSymbolAddress((void**)&zx_ptr, g_zxbcdt);
    __half *xh, *yh, *wi, *wo;
    cudaGetSymbolAddress((void**)&xh, g_xh);
    cudaGetSymbolAddress((void**)&yh, g_yh);
    cudaGetSymbolAddress((void**)&wi, g_wi);
    cudaGetSymbolAddress((void**)&wo, g_wo);

    static int attr_set = 0;
    if (!attr_set) {
        cudaFuncSetAttribute(mma_gemm, cudaFuncAttributeMaxDynamicSharedMemorySize, GSMEM);
        cudaFuncSetAttribute(chunk_output, cudaFuncAttributeMaxDynamicSharedMemorySize, CSMEM);
        attr_set = 1;
    }

    // 0-1) preps for GEMM1
    convert_f16<<<(ROWS * D_MODEL / 4 + 255) / 256, 256>>>(x, xh, ROWS * D_MODEL / 4);
    transpose_f16<<<dim3(NPAD1 / 32, D_MODEL / 32), dim3(32, 8)>>>(
        W_in, wi, D_MODEL, D_IN_PROJ, NPAD1);

    // 2) zxbcdt = x @ W_in
    mma_gemm<<<dim3(NPAD1 / 128, ROWS / 128), 256, GSMEM>>>(
        xh, wi, zx_ptr, ROWS, D_IN_PROJ, D_MODEL);

    // 3) conv + silu   (launch index 3 -> ncu profile slot)
    conv_kernel<<<((size_t)ROWS * (CONV_DIM / 4) + 255) / 256, 256>>>(conv_w, conv_b);

    // 4) dt / dtA
    dt_kernel<<<(BATCH * NHEADS * SEQLEN + 255) / 256, 256>>>(dt_bias, A_log);

    // 5-7) chunked SSM scan
    chunk_state<<<dim3(NCHUNK, NHEADS, BATCH), 256>>>();
    state_pass<<<BATCH * NHEADS * SPB, 256>>>();
    chunk_output<<<dim3(NCHUNK, NHEADS, BATCH), 256, CSMEM>>>(Dp);

    // 8) gate + RMSNorm
    norm_kernel<<<ROWS, 256>>>(norm_w);

    // 9) transpose W_out
    transpose_f16<<<dim3(D_MODEL / 32, D_INNER / 32), dim3(32, 8)>>>(
        W_out, wo, D_INNER, D_MODEL, D_MODEL);

    // 10) out = y @ W_out
    mma_gemm<<<dim3(D_MODEL / 128, ROWS / 128), 256, GSMEM>>>(
        yh, wo, out, ROWS, D_MODEL, D_INNER);
}

// round 12
// speedup vs baseline: 1.4334x; 1.0664x over previous
#include <cuda_runtime.h>
#include <cuda_fp16.h>
#include <math.h>
#include <stdint.h>

#define D_MODEL   768
#define D_STATE   64
#define D_CONV    4
#define HEADDIM   64
#define D_INNER   1536
#define NHEADS    24
#define CONV_DIM  1664
#define D_IN_PROJ 3224
#define BATCH     2
#define SEQLEN    4096
#define ROWS      (BATCH*SEQLEN)
#define NPAD1     3328
#define NCHUNK    64
#define CT        64

// ---------------- scratch (device globals; no allocation) ----------------
__device__ float g_zxbcdt[(size_t)ROWS * D_IN_PROJ];
__device__ float g_xBC[(size_t)ROWS * CONV_DIM];
__device__ float g_y[(size_t)ROWS * D_INNER];
__device__ float g_dtT[(size_t)BATCH * NHEADS * SEQLEN];
__device__ float g_dtAT[(size_t)BATCH * NHEADS * SEQLEN];
__device__ float g_S[(size_t)BATCH * NHEADS * NCHUNK * HEADDIM * D_STATE];
__device__ float g_H[(size_t)BATCH * NHEADS * NCHUNK * HEADDIM * D_STATE];
__device__ float g_P[(size_t)BATCH * NHEADS * NCHUNK];
__device__ __half g_xh[(size_t)ROWS * D_MODEL];
__device__ __half g_yh[(size_t)ROWS * D_INNER];
__device__ __half g_wi[(size_t)NPAD1 * D_MODEL];
__device__ __half g_wo[(size_t)D_MODEL * D_INNER];

// ---------------- common PTX helpers ----------------
__device__ __forceinline__ void cp16(uint32_t dst, const void* src) {
    asm volatile("cp.async.ca.shared.global [%0], [%1], 16;" :: "r"(dst), "l"(src) : "memory");
}
__device__ __forceinline__ void cp_commit() {
    asm volatile("cp.async.commit_group;" ::: "memory");
}
template <int N> __device__ __forceinline__ void cp_wait() {
    asm volatile("cp.async.wait_group %0;" :: "n"(N) : "memory");
}
__device__ __forceinline__ void ldsm4(uint32_t* r, uint32_t addr) {
    asm volatile("ldmatrix.sync.aligned.m8n8.x4.shared.b16 {%0,%1,%2,%3}, [%4];"
                 : "=r"(r[0]), "=r"(r[1]), "=r"(r[2]), "=r"(r[3]) : "r"(addr));
}
__device__ __forceinline__ void mma_f16(float* d, const uint32_t* a, uint32_t b0, uint32_t b1) {
    asm volatile("mma.sync.aligned.m16n8k16.row.col.f32.f16.f16.f32 "
                 "{%0,%1,%2,%3}, {%4,%5,%6,%7}, {%8,%9}, {%0,%1,%2,%3};"
                 : "+f"(d[0]), "+f"(d[1]), "+f"(d[2]), "+f"(d[3])
                 : "r"(a[0]), "r"(a[1]), "r"(a[2]), "r"(a[3]), "r"(b0), "r"(b1));
}

// ---------------- warp-MMA fp16 GEMM (R8 best config: KC=32, 2 CTA/SM) ----------------
#define KC      32
#define PITCH   40
#define TILE_E  (128 * PITCH)
#define TILE_B  (TILE_E * 2)
#define STAGE_B (2 * TILE_B)
#define STAGES  3
#define GSMEM   (STAGES * STAGE_B)      // 61440 bytes

__global__ void __launch_bounds__(256, 2) mma_gemm(
    const __half* __restrict__ Ah, const __half* __restrict__ Bh,
    float* __restrict__ C, int M, int N, int K) {
    extern __shared__ __half sm[];
    const int tid = threadIdx.x;
    const int wid = tid >> 5, lane = tid & 31;
    const int warp_m = wid >> 1, warp_n = wid & 1;
    const int g = lane >> 2, tig = lane & 3;
    const int bm = blockIdx.y * 128, bn = blockIdx.x * 128;
    const uint32_t sbase = (uint32_t)__cvta_generic_to_shared(sm);

    float acc[2][8][4];
#pragma unroll
    for (int mt = 0; mt < 2; mt++)
#pragma unroll
        for (int nt = 0; nt < 8; nt++)
#pragma unroll
            for (int i = 0; i < 4; i++) acc[mt][nt][i] = 0.f;

    const int nkt = K / KC;
    const int r_ld = tid >> 2, seg_ld = tid & 3;

    auto issue = [&](int kt) {
        const int st = kt % STAGES;
        const int kofs = kt * KC;
        const uint32_t dst0 = sbase + st * STAGE_B;
        const __half* srcs[2] = {Ah, Bh};
#pragma unroll
        for (int arr = 0; arr < 2; arr++) {
            const int rbase = (arr == 0) ? bm : bn;
            const uint32_t db = dst0 + arr * TILE_B;
#pragma unroll
            for (int i = 0; i < 2; i++) {
                const int r = r_ld + i * 64;
                cp16(db + (uint32_t)(r * PITCH + seg_ld * 8) * 2,
                     srcs[arr] + (size_t)(rbase + r) * K + kofs + seg_ld * 8);
            }
        }
    };

    issue(0); cp_commit();
    if (nkt > 1) { issue(1); cp_commit(); }

    const int a_row = (lane & 15);
    const int a_col = (lane >> 4) * 8;
    const int b_row = (lane & 7) + ((lane >> 4) * 8);
    const int b_col = ((lane >> 3) & 1) * 8;

    for (int kt = 0; kt < nkt; kt++) {
        if (kt + 2 < nkt) cp_wait<1>(); else cp_wait<0>();
        __syncthreads();
        if (kt + 2 < nkt) { issue(kt + 2); cp_commit(); }

        const uint32_t st0 = sbase + (kt % STAGES) * STAGE_B;
        const uint32_t aA = st0;
        const uint32_t bB = st0 + TILE_B;

#pragma unroll
        for (int ks = 0; ks < KC; ks += 16) {
            uint32_t ah[2][4], bf[4][4];
#pragma unroll
            for (int mt = 0; mt < 2; mt++) {
                const uint32_t aoff =
                    (uint32_t)((warp_m * 32 + mt * 16 + a_row) * PITCH + ks + a_col) * 2;
                ldsm4(ah[mt], aA + aoff);
            }
#pragma unroll
            for (int ntp = 0; ntp < 4; ntp++) {
                const uint32_t boff =
                    (uint32_t)((warp_n * 64 + ntp * 16 + b_row) * PITCH + ks + b_col) * 2;
                ldsm4(bf[ntp], bB + boff);
            }
#pragma unroll
            for (int nt = 0; nt < 8; nt++) {
                const uint32_t b0 = bf[nt >> 1][(nt & 1) * 2];
                const uint32_t b1 = bf[nt >> 1][(nt & 1) * 2 + 1];
#pragma unroll
                for (int mt = 0; mt < 2; mt++)
                    mma_f16(acc[mt][nt], ah[mt], b0, b1);
            }
        }
        __syncthreads();
    }

#pragma unroll
    for (int mt = 0; mt < 2; mt++) {
        const int row0 = bm + warp_m * 32 + mt * 16 + g;
#pragma unroll
        for (int nt = 0; nt < 8; nt++) {
            const int col = bn + warp_n * 64 + nt * 8 + 2 * tig;
            if (col < N) {
                *(float2*)&C[(size_t)row0 * N + col] = make_float2(acc[mt][nt][0], acc[mt][nt][1]);
                *(float2*)&C[(size_t)(row0 + 8) * N + col] = make_float2(acc[mt][nt][2], acc[mt][nt][3]);
            }
        }
    }
}

// ---------------- fp32 -> fp16 convert ----------------
__global__ void convert_f16(const float* __restrict__ src,
                            __half* __restrict__ dst, int n4) {
    int i = blockIdx.x * blockDim.x + threadIdx.x;
    if (i >= n4) return;
    const int idx = i * 4;
    float4 v = *(const float4*)(src + idx);
    __half h[4];
    h[0] = __float2half(v.x); h[1] = __float2half(v.y);
    h[2] = __float2half(v.z); h[3] = __float2half(v.w);
    *(uint2*)(dst + idx) = *(uint2*)h;
}

// ---------------- transpose to fp16 ----------------
__global__ void transpose_f16(const float* __restrict__ src,
                              __half* __restrict__ dst,
                              int R, int C, int Cpad) {
    __shared__ float tile[32][33];
    const int c0 = blockIdx.x * 32, r0 = blockIdx.y * 32;
    const int tx = threadIdx.x, ty = threadIdx.y;
    const int c = c0 + tx;
#pragma unroll
    for (int j = ty; j < 32; j += 8) {
        const int r = r0 + j;
        tile[j][tx] = (r < R && c < C) ? src[(size_t)r * C + c] : 0.f;
    }
    __syncthreads();
#pragma unroll
    for (int j = ty; j < 32; j += 8) {
        const int orow = c0 + j;
        const int ocol = r0 + tx;
        if (orow < Cpad && ocol < R)
            dst[(size_t)orow * R + ocol] = __float2half(tile[tx][j]);
    }
}

// ---------------- dt ----------------
__global__ void dt_kernel(const float* __restrict__ dt_bias,
                          const float* __restrict__ A_log) {
    int idx = blockIdx.x * blockDim.x + threadIdx.x;
    if (idx >= BATCH * NHEADS * SEQLEN) return;
    const int l = idx % SEQLEN;
    const int bh = idx / SEQLEN;
    const int h = bh % NHEADS, b = bh / NHEADS;
    float v = g_zxbcdt[(size_t)(b * SEQLEN + l) * D_IN_PROJ + (D_INNER + CONV_DIM) + h]
              + dt_bias[h];
    float dtv = (v > 20.f) ? v : log1pf(expf(v));
    float A = -expf(A_log[h]);
    g_dtT[idx] = dtv;
    g_dtAT[idx] = dtv * A;
}

// ---------------- causal depthwise conv + silu: 4-row temporal blocking ----------------
#define NC4 (CONV_DIM / 4)
__global__ void conv_kernel(const float* __restrict__ conv_w,
                            const float* __restrict__ conv_b) {
    int i = blockIdx.x * blockDim.x + threadIdx.x;
    if (i >= (ROWS / 4) * NC4) return;
    const int c4 = (i % NC4) * 4;
    const int rb = (i / NC4) * 4;           // row-block start (SEQLEN%4==0: same sequence)
    const int l0 = rb & (SEQLEN - 1);

    const float4 bias = *(const float4*)(conv_b + c4);
    const float4 w0 = *(const float4*)(conv_w + (c4 + 0) * 4);
    const float4 w1 = *(const float4*)(conv_w + (c4 + 1) * 4);
    const float4 w2 = *(const float4*)(conv_w + (c4 + 2) * 4);
    const float4 w3 = *(const float4*)(conv_w + (c4 + 3) * 4);
    const float wt0[4] = {w0.x, w0.y, w0.z, w0.w};
    const float wt1[4] = {w1.x, w1.y, w1.z, w1.w};
    const float wt2[4] = {w2.x, w2.y, w2.z, w2.w};
    const float wt3[4] = {w3.x, w3.y, w3.z, w3.w};

    float4 v[7];
#pragma unroll
    for (int j = 0; j < 7; j++) {
        const int ls = l0 + j - 3;
        if (ls >= 0)
            v[j] = *(const float4*)(g_zxbcdt + (size_t)(rb + j - 3) * D_IN_PROJ + D_INNER + c4);
        else
            v[j] = make_float4(0.f, 0.f, 0.f, 0.f);
    }

#pragma unroll
    for (int j = 0; j < 4; j++) {
        float4 acc = bias;
#pragma unroll
        for (int k = 0; k < D_CONV; k++) {
            acc.x += v[j + k].x * wt0[k];
            acc.y += v[j + k].y * wt1[k];
            acc.z += v[j + k].z * wt2[k];
            acc.w += v[j + k].w * wt3[k];
        }
        acc.x = acc.x / (1.f + expf(-acc.x));
        acc.y = acc.y / (1.f + expf(-acc.y));
        acc.z = acc.z / (1.f + expf(-acc.z));
        acc.w = acc.w / (1.f + expf(-acc.w));
        *(float4*)(g_xBC + (size_t)(rb + j) * CONV_DIM + c4) = acc;
    }
}

// ================= chunked SSM scan (tensor-core) =================
#define SPITCH 72

// Phase A
__global__ void __launch_bounds__(256) chunk_state(void) {
    __shared__ __half sAh[CT * SPITCH], sAl[CT * SPITCH];
    __shared__ __half sBh[CT * SPITCH], sBl[CT * SPITCH];
    __shared__ float sL[CT], sdt[CT];
    const int c = blockIdx.x, h = blockIdx.y, b = blockIdx.z;
    const int tid = threadIdx.x;
    const int bh = b * NHEADS + h;
    const int rowbase = b * SEQLEN + c * CT;

    if (tid < CT) {
        sdt[tid] = g_dtT[(size_t)bh * SEQLEN + c * CT + tid];
        sL[tid]  = g_dtAT[(size_t)bh * SEQLEN + c * CT + tid];
    }
    __syncthreads();
    if (tid == 0) {
        float run = 0.f;
        for (int t = 0; t < CT; t++) { run += sL[t]; sL[t] = run; }
    }
    __syncthreads();
    const float Lend = sL[CT - 1];

    for (int e = tid; e < CT * 16; e += 256) {
        const int t = e >> 4, q = e & 15;
        const float* rowp = g_xBC + (size_t)(rowbase + t) * CONV_DIM;
        const float w = sdt[t] * expf(Lend - sL[t]);
        float4 xv = *(const float4*)(rowp + h * HEADDIM + q * 4);
        float4 bv = *(const float4*)(rowp + D_INNER + q * 4);
        const float xa[4] = {xv.x * w, xv.y * w, xv.z * w, xv.w * w};
        const float ba[4] = {bv.x, bv.y, bv.z, bv.w};
#pragma unroll
        for (int j = 0; j < 4; j++) {
            const int p = q * 4 + j;
            __half hx = __float2half(xa[j]);
            sAh[p * SPITCH + t] = hx;
            sAl[p * SPITCH + t] = __float2half(xa[j] - __half2float(hx));
            __half hb = __float2half(ba[j]);
            sBh[p * SPITCH + t] = hb;
            sBl[p * SPITCH + t] = __float2half(ba[j] - __half2float(hb));
        }
    }
    __syncthreads();

    const int wid = tid >> 5, lane = tid & 31;
    const int warp_m = wid & 3, warp_n = wid >> 2;
    const int a_row = lane & 15, a_col = (lane >> 4) * 8;
    const int b_row = (lane & 7) + ((lane >> 4) * 8), b_col = ((lane >> 3) & 1) * 8;
    const uint32_t uAh = (uint32_t)__cvta_generic_to_shared(sAh);
    const uint32_t uAl = (uint32_t)__cvta_generic_to_shared(sAl);
    const uint32_t uBh = (uint32_t)__cvta_generic_to_shared(sBh);
    const uint32_t uBl = (uint32_t)__cvta_generic_to_shared(sBl);

    float acc[4][4];
#pragma unroll
    for (int nt = 0; nt < 4; nt++)
#pragma unroll
        for (int i = 0; i < 4; i++) acc[nt][i] = 0.f;

#pragma unroll
    for (int kt = 0; kt < 4; kt++) {
        const int k0 = kt * 16;
        uint32_t ah[4], al[4], bh[2][4], bl[2][4];
        const uint32_t aoff = (uint32_t)((warp_m * 16 + a_row) * SPITCH + k0 + a_col) * 2;
        ldsm4(ah, uAh + aoff);
        ldsm4(al, uAl + aoff);
#pragma unroll
        for (int nb = 0; nb < 2; nb++) {
            const uint32_t boff =
                (uint32_t)((warp_n * 32 + nb * 16 + b_row) * SPITCH + k0 + b_col) * 2;
            ldsm4(bh[nb], uBh + boff);
            ldsm4(bl[nb], uBl + boff);
        }
#pragma unroll
        for (int nt = 0; nt < 4; nt++) {
            const int nb = nt >> 1, pr = (nt & 1) * 2;
            mma_f16(acc[nt], ah, bh[nb][pr], bh[nb][pr + 1]);
            mma_f16(acc[nt], ah, bl[nb][pr], bl[nb][pr + 1]);
            mma_f16(acc[nt], al, bh[nb][pr], bh[nb][pr + 1]);
        }
    }

    float* Sb = g_S + ((size_t)bh * NCHUNK + c) * (HEADDIM * D_STATE);
    const int g = lane >> 2, tig = lane & 3;
#pragma unroll
    for (int nt = 0; nt < 4; nt++) {
        const int ncol = warp_n * 32 + nt * 8 + 2 * tig;
        const int prow = warp_m * 16 + g;
        *(float2*)&Sb[prow * D_STATE + ncol] = make_float2(acc[nt][0], acc[nt][1]);
        *(float2*)&Sb[(prow + 8) * D_STATE + ncol] = make_float2(acc[nt][2], acc[nt][3]);
    }
    if (tid == 0) g_P[(size_t)bh * NCHUNK + c] = Lend;
}

// Phase B: fully parallel over state elements
#define SPB 16
__global__ void __launch_bounds__(256) state_pass(void) {
    const int blk = blockIdx.x;
    const int bh = blk / SPB, seg = blk % SPB;
    const int e = seg * 256 + threadIdx.x;
    __shared__ float sP[NCHUNK];
    if (threadIdx.x < NCHUNK)
        sP[threadIdx.x] = expf(g_P[(size_t)bh * NCHUNK + threadIdx.x]);
    __syncthreads();
    float hv = 0.f;
    const size_t base = (size_t)bh * NCHUNK * (HEADDIM * D_STATE) + e;
#pragma unroll 4
    for (int c = 0; c < NCHUNK; c++) {
        const size_t off = base + (size_t)c * (HEADDIM * D_STATE);
        g_H[off] = hv;
        hv = sP[c] * hv + g_S[off];
    }
}

// Phase C
#define CTILE (CT * SPITCH)
#define CSMEM (10 * CTILE * 2 + 2 * CT * 4)
__global__ void __launch_bounds__(256) chunk_output(const float* __restrict__ Dparam) {
    extern __shared__ __half cs[];
    __half* sCh = cs;
    __half* sCl = cs + CTILE;
    __half* sB2h = cs + 2 * CTILE;
    __half* sB2l = cs + 3 * CTILE;
    __half* sXh = cs + 4 * CTILE;
    __half* sXl = cs + 5 * CTILE;
    __half* sHh = cs + 6 * CTILE;
    __half* sHl = cs + 7 * CTILE;
    __half* sGh = cs + 8 * CTILE;
    __half* sGl = cs + 9 * CTILE;
    float* sL = (float*)(cs + 10 * CTILE);
    float* sdt = sL + CT;

    const int c = blockIdx.x, h = blockIdx.y, b = blockIdx.z;
    const int tid = threadIdx.x;
    const int bh = b * NHEADS + h;
    const int rowbase = b * SEQLEN + c * CT;
    const float Dh = Dparam[h];

    if (tid < CT) {
        sdt[tid] = g_dtT[(size_t)bh * SEQLEN + c * CT + tid];
        sL[tid]  = g_dtAT[(size_t)bh * SEQLEN + c * CT + tid];
    }
    __syncthreads();
    if (tid == 0) {
        float run = 0.f;
        for (int t = 0; t < CT; t++) { run += sL[t]; sL[t] = run; }
    }

    const float* Hbase = g_H + ((size_t)bh * NCHUNK + c) * (HEADDIM * D_STATE);
    for (int e = tid; e < CT * 16; e += 256) {
        const int t = e >> 4, q = e & 15;
        const float* rowp = g_xBC + (size_t)(rowbase + t) * CONV_DIM;
        float4 cv = *(const float4*)(rowp + D_INNER + D_STATE + q * 4);
        float4 bv = *(const float4*)(rowp + D_INNER + q * 4);
        float4 xv = *(const float4*)(rowp + h * HEADDIM + q * 4);
        float4 hv = *(const float4*)(Hbase + t * D_STATE + q * 4);
        const float ca[4] = {cv.x, cv.y, cv.z, cv.w};
        const float ba[4] = {bv.x, bv.y, bv.z, bv.w};
        const float xa[4] = {xv.x, xv.y, xv.z, xv.w};
        const float ha[4] = {hv.x, hv.y, hv.z, hv.w};
#pragma unroll
        for (int j = 0; j < 4; j++) {
            const int n = q * 4 + j;
            __half hc = __float2half(ca[j]);
            sCh[t * SPITCH + n] = hc;
            sCl[t * SPITCH + n] = __float2half(ca[j] - __half2float(hc));
            __half hb = __float2half(ba[j]);
            sB2h[t * SPITCH + n] = hb;
            sB2l[t * SPITCH + n] = __float2half(ba[j] - __half2float(hb));
            __half hx = __float2half(xa[j]);
            sXh[n * SPITCH + t] = hx;
            sXl[n * SPITCH + t] = __float2half(xa[j] - __half2float(hx));
            __half hh = __float2half(ha[j]);
            sHh[t * SPITCH + n] = hh;
            sHl[t * SPITCH + n] = __float2half(ha[j] - __half2float(hh));
        }
    }
    __syncthreads();

    const int wid = tid >> 5, lane = tid & 31;
    const int warp_m = wid & 3, warp_n = wid >> 2;
    const int a_row = lane & 15, a_col = (lane >> 4) * 8;
    const int b_row = (lane & 7) + ((lane >> 4) * 8), b_col = ((lane >> 3) & 1) * 8;
    const int g = lane >> 2, tig = lane & 3;
    const uint32_t uCh = (uint32_t)__cvta_generic_to_shared(sCh);
    const uint32_t uCl = (uint32_t)__cvta_generic_to_shared(sCl);
    const uint32_t uB2h = (uint32_t)__cvta_generic_to_shared(sB2h);
    const uint32_t uB2l = (uint32_t)__cvta_generic_to_shared(sB2l);
    const uint32_t uXh = (uint32_t)__cvta_generic_to_shared(sXh);
    const uint32_t uXl = (uint32_t)__cvta_generic_to_shared(sXl);
    const uint32_t uHh = (uint32_t)__cvta_generic_to_shared(sHh);
    const uint32_t uHl = (uint32_t)__cvta_generic_to_shared(sHl);
    const uint32_t uGh = (uint32_t)__cvta_generic_to_shared(sGh);
    const uint32_t uGl = (uint32_t)__cvta_generic_to_shared(sGl);

    float gacc[4][4];
#pragma unroll
    for (int nt = 0; nt < 4; nt++)
#pragma unroll
        for (int i = 0; i < 4; i++) gacc[nt][i] = 0.f;
#pragma unroll
    for (int kt = 0; kt < 4; kt++) {
        const int k0 = kt * 16;
        uint32_t ah[4], al[4], bh[2][4], bl[2][4];
        const uint32_t aoff = (uint32_t)((warp_m * 16 + a_row) * SPITCH + k0 + a_col) * 2;
        ldsm4(ah, uCh + aoff);
        ldsm4(al, uCl + aoff);
#pragma unroll
        for (int nb = 0; nb < 2; nb++) {
            const uint32_t boff =
                (uint32_t)((warp_n * 32 + nb * 16 + b_row) * SPITCH + k0 + b_col) * 2;
            ldsm4(bh[nb], uB2h + boff);
            ldsm4(bl[nb], uB2l + boff);
        }
#pragma unroll
        for (int nt = 0; nt < 4; nt++) {
            const int nb = nt >> 1, pr = (nt & 1) * 2;
            mma_f16(gacc[nt], ah, bh[nb][pr], bh[nb][pr + 1]);
            mma_f16(gacc[nt], ah, bl[nb][pr], bl[nb][pr + 1]);
            mma_f16(gacc[nt], al, bh[nb][pr], bh[nb][pr + 1]);
        }
    }
    __syncthreads();

#pragma unroll
    for (int nt = 0; nt < 4; nt++) {
        const int s0 = warp_n * 32 + nt * 8 + 2 * tig;
#pragma unroll
        for (int r = 0; r < 2; r++) {
            const int t = warp_m * 16 + g + r * 8;
            float v0 = gacc[nt][r * 2], v1 = gacc[nt][r * 2 + 1];
            const float Lt = sL[t];
            v0 = (s0 <= t)     ? v0 * sdt[s0]     * expf(Lt - sL[s0])     : 0.f;
            v1 = (s0 + 1 <= t) ? v1 * sdt[s0 + 1] * expf(Lt - sL[s0 + 1]) : 0.f;
            __half h0 = __float2half(v0), h1 = __float2half(v1);
            *(__half2*)&sGh[t * SPITCH + s0] = __halves2half2(h0, h1);
            *(__half2*)&sGl[t * SPITCH + s0] = __halves2half2(
                __float2half(v0 - __half2float(h0)), __float2half(v1 - __half2float(h1)));
        }
    }
    __syncthreads();

    float yacc[4][4], cacc[4][4];
#pragma unroll
    for (int nt = 0; nt < 4; nt++)
#pragma unroll
        for (int i = 0; i < 4; i++) { yacc[nt][i] = 0.f; cacc[nt][i] = 0.f; }
#pragma unroll
    for (int kt = 0; kt < 4; kt++) {
        const int k0 = kt * 16;
        uint32_t gh[4], gl[4], ch[4], cl[4];
        uint32_t xh[2][4], xl[2][4], hh[2][4], hl[2][4];
        const uint32_t aoff = (uint32_t)((warp_m * 16 + a_row) * SPITCH + k0 + a_col) * 2;
        ldsm4(gh, uGh + aoff);
        ldsm4(gl, uGl + aoff);
        ldsm4(ch, uCh + aoff);
        ldsm4(cl, uCl + aoff);
#pragma unroll
        for (int nb = 0; nb < 2; nb++) {
            const uint32_t boff =
                (uint32_t)((warp_n * 32 + nb * 16 + b_row) * SPITCH + k0 + b_col) * 2;
            ldsm4(xh[nb], uXh + boff);
            ldsm4(xl[nb], uXl + boff);
            ldsm4(hh[nb], uHh + boff);
            ldsm4(hl[nb], uHl + boff);
        }
#pragma unroll
        for (int nt = 0; nt < 4; nt++) {
            const int nb = nt >> 1, pr = (nt & 1) * 2;
            mma_f16(yacc[nt], gh, xh[nb][pr], xh[nb][pr + 1]);
            mma_f16(yacc[nt], gh, xl[nb][pr], xl[nb][pr + 1]);
            mma_f16(yacc[nt], gl, xh[nb][pr], xh[nb][pr + 1]);
            mma_f16(cacc[nt], ch, hh[nb][pr], hh[nb][pr + 1]);
            mma_f16(cacc[nt], ch, hl[nb][pr], hl[nb][pr + 1]);
            mma_f16(cacc[nt], cl, hh[nb][pr], hh[nb][pr + 1]);
        }
    }

#pragma unroll
    for (int nt = 0; nt < 4; nt++) {
        const int p = warp_n * 32 + nt * 8 + 2 * tig;
#pragma unroll
        for (int r = 0; r < 2; r++) {
            const int t = warp_m * 16 + g + r * 8;
            const float et = expf(sL[t]);
            const float x0 = __half2float(sXh[p * SPITCH + t]) + __half2float(sXl[p * SPITCH + t]);
            const float x1 = __half2float(sXh[(p + 1) * SPITCH + t]) + __half2float(sXl[(p + 1) * SPITCH + t]);
            const float o0 = yacc[nt][r * 2] + cacc[nt][r * 2] * et + Dh * x0;
            const float o1 = yacc[nt][r * 2 + 1] + cacc[nt][r * 2 + 1] * et + Dh * x1;
            *(float2*)&g_y[(size_t)(rowbase + t) * D_INNER + h * HEADDIM + p] =
                make_float2(o0, o1);
        }
    }
}

// ---------------- gate + RMSNorm, writing fp16 ----------------
__global__ void __launch_bounds__(256) norm_kernel(const float* __restrict__ norm_w) {
    const int row = blockIdx.x;
    const int tid = threadIdx.x;
    const float* zrow = g_zxbcdt + (size_t)row * D_IN_PROJ;
    const float* yrow = g_y + (size_t)row * D_INNER;
    __half* hrow = g_yh + (size_t)row * D_INNER;

    float vals[6];
    float ss = 0.f;
#pragma unroll
    for (int i = 0; i < 6; i++) {
        int c = tid + i * 256;
        float z = zrow[c];
        float yv = yrow[c] * (z / (1.f + expf(-z)));
        vals[i] = yv;
        ss += yv * yv;
    }
#pragma unroll
    for (int o = 16; o; o >>= 1) ss += __shfl_xor_sync(0xffffffffu, ss, o);
    __shared__ float red[8];
    if ((tid & 31) == 0) red[tid >> 5] = ss;
    __syncthreads();
    if (tid < 8) {
        float v = red[tid];
#pragma unroll
        for (int o = 4; o; o >>= 1) v += __shfl_xor_sync(0xffu, v, o);
        if (tid == 0) red[0] = v;
    }
    __syncthreads();
    const float scale = rsqrtf(red[0] * (1.f / D_INNER) + 1e-5f);
#pragma unroll
    for (int i = 0; i < 6; i++) {
        int c = tid + i * 256;
        hrow[c] = __float2half(vals[i] * scale * norm_w[c]);
    }
}

// ---------------- launch ----------------
extern "C" void kernel_launch(void* const* d_in, const int* in_sizes, int n_in,
                              void* d_out, int out_size) {
    const float* x       = (const float*)d_in[0];
    const float* W_in    = (const float*)d_in[1];
    const float* conv_w  = (const float*)d_in[2];
    const float* conv_b  = (const float*)d_in[3];
    const float* dt_bias = (const float*)d_in[4];
    const float* A_log   = (const float*)d_in[5];
    const float* Dp      = (const float*)d_in[6];
    const float* norm_w  = (const float*)d_in[7];
    const float* W_out   = (const float*)d_in[8];
    float* out = (float*)d_out;

    float *zx_ptr;
    cudaGetSymbolAddress((void**)&zx_ptr, g_zxbcdt);
    __half *xh, *yh, *wi, *wo;
    cudaGetSymbolAddress((void**)&xh, g_xh);
    cudaGetSymbolAddress((void**)&yh, g_yh);
    cudaGetSymbolAddress((void**)&wi, g_wi);
    cudaGetSymbolAddress((void**)&wo, g_wo);

    static int attr_set = 0;
    if (!attr_set) {
        cudaFuncSetAttribute(mma_gemm, cudaFuncAttributeMaxDynamicSharedMemorySize, GSMEM);
        cudaFuncSetAttribute(chunk_output, cudaFuncAttributeMaxDynamicSharedMemorySize, CSMEM);
        attr_set = 1;
    }

    // 0-1) preps for GEMM1
    convert_f16<<<(ROWS * D_MODEL / 4 + 255) / 256, 256>>>(x, xh, ROWS * D_MODEL / 4);
    transpose_f16<<<dim3(NPAD1 / 32, D_MODEL / 32), dim3(32, 8)>>>(
        W_in, wi, D_MODEL, D_IN_PROJ, NPAD1);

    // 2) zxbcdt = x @ W_in
    mma_gemm<<<dim3(NPAD1 / 128, ROWS / 128), 256, GSMEM>>>(
        xh, wi, zx_ptr, ROWS, D_IN_PROJ, D_MODEL);

    // 3) conv + silu   (launch index 3 -> ncu profile slot)
    conv_kernel<<<((ROWS / 4) * NC4 + 255) / 256, 256>>>(conv_w, conv_b);

    // 4) dt / dtA
    dt_kernel<<<(BATCH * NHEADS * SEQLEN + 255) / 256, 256>>>(dt_bias, A_log);

    // 5-7) chunked SSM scan
    chunk_state<<<dim3(NCHUNK, NHEADS, BATCH), 256>>>();
    state_pass<<<BATCH * NHEADS * SPB, 256>>>();
    chunk_output<<<dim3(NCHUNK, NHEADS, BATCH), 256, CSMEM>>>(Dp);

    // 8) gate + RMSNorm
    norm_kernel<<<ROWS, 256>>>(norm_w);

    // 9) transpose W_out
    transpose_f16<<<dim3(D_MODEL / 32, D_INNER / 32), dim3(32, 8)>>>(
        W_out, wo, D_INNER, D_MODEL, D_MODEL);

    // 10) out = y @ W_out
    mma_gemm<<<dim3(D_MODEL / 128, ROWS / 128), 256, GSMEM>>>(
        yh, wo, out, ROWS, D_MODEL, D_INNER);
}

// round 13
// speedup vs baseline: 1.4975x; 1.0447x over previous
#include <cuda_runtime.h>
#include <cuda_fp16.h>
#include <math.h>
#include <stdint.h>

#define D_MODEL   768
#define D_STATE   64
#define D_CONV    4
#define HEADDIM   64
#define D_INNER   1536
#define NHEADS    24
#define CONV_DIM  1664
#define D_IN_PROJ 3224
#define BATCH     2
#define SEQLEN    4096
#define ROWS      (BATCH*SEQLEN)
#define NPAD1     3328
#define NCHUNK    64
#define CT        64

// ---------------- scratch (device globals; no allocation) ----------------
__device__ float g_zxbcdt[(size_t)ROWS * D_IN_PROJ];
__device__ float g_xBC[(size_t)ROWS * CONV_DIM];
__device__ float g_y[(size_t)ROWS * D_INNER];
__device__ float g_dtT[(size_t)BATCH * NHEADS * SEQLEN];
__device__ float g_dtAT[(size_t)BATCH * NHEADS * SEQLEN];
__device__ float g_S[(size_t)BATCH * NHEADS * NCHUNK * HEADDIM * D_STATE];
__device__ __half g_H[(size_t)BATCH * NHEADS * NCHUNK * HEADDIM * D_STATE];
__device__ float g_P[(size_t)BATCH * NHEADS * NCHUNK];
__device__ __half g_xh[(size_t)ROWS * D_MODEL];
__device__ __half g_yh[(size_t)ROWS * D_INNER];
__device__ __half g_wi[(size_t)NPAD1 * D_MODEL];
__device__ __half g_wo[(size_t)D_MODEL * D_INNER];

// ---------------- common PTX helpers ----------------
__device__ __forceinline__ void cp16(uint32_t dst, const void* src) {
    asm volatile("cp.async.ca.shared.global [%0], [%1], 16;" :: "r"(dst), "l"(src) : "memory");
}
__device__ __forceinline__ void cp_commit() {
    asm volatile("cp.async.commit_group;" ::: "memory");
}
template <int N> __device__ __forceinline__ void cp_wait() {
    asm volatile("cp.async.wait_group %0;" :: "n"(N) : "memory");
}
__device__ __forceinline__ void ldsm4(uint32_t* r, uint32_t addr) {
    asm volatile("ldmatrix.sync.aligned.m8n8.x4.shared.b16 {%0,%1,%2,%3}, [%4];"
                 : "=r"(r[0]), "=r"(r[1]), "=r"(r[2]), "=r"(r[3]) : "r"(addr));
}
__device__ __forceinline__ void mma_f16(float* d, const uint32_t* a, uint32_t b0, uint32_t b1) {
    asm volatile("mma.sync.aligned.m16n8k16.row.col.f32.f16.f16.f32 "
                 "{%0,%1,%2,%3}, {%4,%5,%6,%7}, {%8,%9}, {%0,%1,%2,%3};"
                 : "+f"(d[0]), "+f"(d[1]), "+f"(d[2]), "+f"(d[3])
                 : "r"(a[0]), "r"(a[1]), "r"(a[2]), "r"(a[3]), "r"(b0), "r"(b1));
}

// ---------------- warp-MMA fp16 GEMM (R8 best config: KC=32, 2 CTA/SM) ----------------
#define KC      32
#define PITCH   40
#define TILE_E  (128 * PITCH)
#define TILE_B  (TILE_E * 2)
#define STAGE_B (2 * TILE_B)
#define STAGES  3
#define GSMEM   (STAGES * STAGE_B)      // 61440 bytes

__global__ void __launch_bounds__(256, 2) mma_gemm(
    const __half* __restrict__ Ah, const __half* __restrict__ Bh,
    float* __restrict__ C, int M, int N, int K) {
    extern __shared__ __half sm[];
    const int tid = threadIdx.x;
    const int wid = tid >> 5, lane = tid & 31;
    const int warp_m = wid >> 1, warp_n = wid & 1;
    const int g = lane >> 2, tig = lane & 3;
    const int bm = blockIdx.y * 128, bn = blockIdx.x * 128;
    const uint32_t sbase = (uint32_t)__cvta_generic_to_shared(sm);

    float acc[2][8][4];
#pragma unroll
    for (int mt = 0; mt < 2; mt++)
#pragma unroll
        for (int nt = 0; nt < 8; nt++)
#pragma unroll
            for (int i = 0; i < 4; i++) acc[mt][nt][i] = 0.f;

    const int nkt = K / KC;
    const int r_ld = tid >> 2, seg_ld = tid & 3;

    auto issue = [&](int kt) {
        const int st = kt % STAGES;
        const int kofs = kt * KC;
        const uint32_t dst0 = sbase + st * STAGE_B;
        const __half* srcs[2] = {Ah, Bh};
#pragma unroll
        for (int arr = 0; arr < 2; arr++) {
            const int rbase = (arr == 0) ? bm : bn;
            const uint32_t db = dst0 + arr * TILE_B;
#pragma unroll
            for (int i = 0; i < 2; i++) {
                const int r = r_ld + i * 64;
                cp16(db + (uint32_t)(r * PITCH + seg_ld * 8) * 2,
                     srcs[arr] + (size_t)(rbase + r) * K + kofs + seg_ld * 8);
            }
        }
    };

    issue(0); cp_commit();
    if (nkt > 1) { issue(1); cp_commit(); }

    const int a_row = (lane & 15);
    const int a_col = (lane >> 4) * 8;
    const int b_row = (lane & 7) + ((lane >> 4) * 8);
    const int b_col = ((lane >> 3) & 1) * 8;

    for (int kt = 0; kt < nkt; kt++) {
        if (kt + 2 < nkt) cp_wait<1>(); else cp_wait<0>();
        __syncthreads();
        if (kt + 2 < nkt) { issue(kt + 2); cp_commit(); }

        const uint32_t st0 = sbase + (kt % STAGES) * STAGE_B;
        const uint32_t aA = st0;
        const uint32_t bB = st0 + TILE_B;

#pragma unroll
        for (int ks = 0; ks < KC; ks += 16) {
            uint32_t ah[2][4], bf[4][4];
#pragma unroll
            for (int mt = 0; mt < 2; mt++) {
                const uint32_t aoff =
                    (uint32_t)((warp_m * 32 + mt * 16 + a_row) * PITCH + ks + a_col) * 2;
                ldsm4(ah[mt], aA + aoff);
            }
#pragma unroll
            for (int ntp = 0; ntp < 4; ntp++) {
                const uint32_t boff =
                    (uint32_t)((warp_n * 64 + ntp * 16 + b_row) * PITCH + ks + b_col) * 2;
                ldsm4(bf[ntp], bB + boff);
            }
#pragma unroll
            for (int nt = 0; nt < 8; nt++) {
                const uint32_t b0 = bf[nt >> 1][(nt & 1) * 2];
                const uint32_t b1 = bf[nt >> 1][(nt & 1) * 2 + 1];
#pragma unroll
                for (int mt = 0; mt < 2; mt++)
                    mma_f16(acc[mt][nt], ah[mt], b0, b1);
            }
        }
        __syncthreads();
    }

#pragma unroll
    for (int mt = 0; mt < 2; mt++) {
        const int row0 = bm + warp_m * 32 + mt * 16 + g;
#pragma unroll
        for (int nt = 0; nt < 8; nt++) {
            const int col = bn + warp_n * 64 + nt * 8 + 2 * tig;
            if (col < N) {
                *(float2*)&C[(size_t)row0 * N + col] = make_float2(acc[mt][nt][0], acc[mt][nt][1]);
                *(float2*)&C[(size_t)(row0 + 8) * N + col] = make_float2(acc[mt][nt][2], acc[mt][nt][3]);
            }
        }
    }
}

// ---------------- fp32 -> fp16 convert ----------------
__global__ void convert_f16(const float* __restrict__ src,
                            __half* __restrict__ dst, int n4) {
    int i = blockIdx.x * blockDim.x + threadIdx.x;
    if (i >= n4) return;
    const int idx = i * 4;
    float4 v = *(const float4*)(src + idx);
    __half h[4];
    h[0] = __float2half(v.x); h[1] = __float2half(v.y);
    h[2] = __float2half(v.z); h[3] = __float2half(v.w);
    *(uint2*)(dst + idx) = *(uint2*)h;
}

// ---------------- transpose to fp16 ----------------
__global__ void transpose_f16(const float* __restrict__ src,
                              __half* __restrict__ dst,
                              int R, int C, int Cpad) {
    __shared__ float tile[32][33];
    const int c0 = blockIdx.x * 32, r0 = blockIdx.y * 32;
    const int tx = threadIdx.x, ty = threadIdx.y;
    const int c = c0 + tx;
#pragma unroll
    for (int j = ty; j < 32; j += 8) {
        const int r = r0 + j;
        tile[j][tx] = (r < R && c < C) ? src[(size_t)r * C + c] : 0.f;
    }
    __syncthreads();
#pragma unroll
    for (int j = ty; j < 32; j += 8) {
        const int orow = c0 + j;
        const int ocol = r0 + tx;
        if (orow < Cpad && ocol < R)
            dst[(size_t)orow * R + ocol] = __float2half(tile[tx][j]);
    }
}

// ---------------- dt ----------------
__global__ void dt_kernel(const float* __restrict__ dt_bias,
                          const float* __restrict__ A_log) {
    int idx = blockIdx.x * blockDim.x + threadIdx.x;
    if (idx >= BATCH * NHEADS * SEQLEN) return;
    const int l = idx % SEQLEN;
    const int bh = idx / SEQLEN;
    const int h = bh % NHEADS, b = bh / NHEADS;
    float v = g_zxbcdt[(size_t)(b * SEQLEN + l) * D_IN_PROJ + (D_INNER + CONV_DIM) + h]
              + dt_bias[h];
    float dtv = (v > 20.f) ? v : log1pf(expf(v));
    float A = -expf(A_log[h]);
    g_dtT[idx] = dtv;
    g_dtAT[idx] = dtv * A;
}

// ---------------- causal depthwise conv + silu: 4-row temporal blocking ----------------
#define NC4 (CONV_DIM / 4)
__global__ void conv_kernel(const float* __restrict__ conv_w,
                            const float* __restrict__ conv_b) {
    int i = blockIdx.x * blockDim.x + threadIdx.x;
    if (i >= (ROWS / 4) * NC4) return;
    const int c4 = (i % NC4) * 4;
    const int rb = (i / NC4) * 4;
    const int l0 = rb & (SEQLEN - 1);

    const float4 bias = *(const float4*)(conv_b + c4);
    const float4 w0 = *(const float4*)(conv_w + (c4 + 0) * 4);
    const float4 w1 = *(const float4*)(conv_w + (c4 + 1) * 4);
    const float4 w2 = *(const float4*)(conv_w + (c4 + 2) * 4);
    const float4 w3 = *(const float4*)(conv_w + (c4 + 3) * 4);
    const float wt0[4] = {w0.x, w0.y, w0.z, w0.w};
    const float wt1[4] = {w1.x, w1.y, w1.z, w1.w};
    const float wt2[4] = {w2.x, w2.y, w2.z, w2.w};
    const float wt3[4] = {w3.x, w3.y, w3.z, w3.w};

    float4 v[7];
#pragma unroll
    for (int j = 0; j < 7; j++) {
        const int ls = l0 + j - 3;
        if (ls >= 0)
            v[j] = *(const float4*)(g_zxbcdt + (size_t)(rb + j - 3) * D_IN_PROJ + D_INNER + c4);
        else
            v[j] = make_float4(0.f, 0.f, 0.f, 0.f);
    }

#pragma unroll
    for (int j = 0; j < 4; j++) {
        float4 acc = bias;
#pragma unroll
        for (int k = 0; k < D_CONV; k++) {
            acc.x += v[j + k].x * wt0[k];
            acc.y += v[j + k].y * wt1[k];
            acc.z += v[j + k].z * wt2[k];
            acc.w += v[j + k].w * wt3[k];
        }
        acc.x = acc.x / (1.f + expf(-acc.x));
        acc.y = acc.y / (1.f + expf(-acc.y));
        acc.z = acc.z / (1.f + expf(-acc.z));
        acc.w = acc.w / (1.f + expf(-acc.w));
        *(float4*)(g_xBC + (size_t)(rb + j) * CONV_DIM + c4) = acc;
    }
}

// ================= chunked SSM scan (tensor-core) =================
#define SPITCH 72

// Phase A
__global__ void __launch_bounds__(256) chunk_state(void) {
    __shared__ __half sAh[CT * SPITCH], sAl[CT * SPITCH];
    __shared__ __half sBh[CT * SPITCH], sBl[CT * SPITCH];
    __shared__ float sL[CT], sdt[CT];
    const int c = blockIdx.x, h = blockIdx.y, b = blockIdx.z;
    const int tid = threadIdx.x;
    const int bh = b * NHEADS + h;
    const int rowbase = b * SEQLEN + c * CT;

    if (tid < CT) {
        sdt[tid] = g_dtT[(size_t)bh * SEQLEN + c * CT + tid];
        sL[tid]  = g_dtAT[(size_t)bh * SEQLEN + c * CT + tid];
    }
    __syncthreads();
    if (tid == 0) {
        float run = 0.f;
        for (int t = 0; t < CT; t++) { run += sL[t]; sL[t] = run; }
    }
    __syncthreads();
    const float Lend = sL[CT - 1];

    for (int e = tid; e < CT * 16; e += 256) {
        const int t = e >> 4, q = e & 15;
        const float* rowp = g_xBC + (size_t)(rowbase + t) * CONV_DIM;
        const float w = sdt[t] * expf(Lend - sL[t]);
        float4 xv = *(const float4*)(rowp + h * HEADDIM + q * 4);
        float4 bv = *(const float4*)(rowp + D_INNER + q * 4);
        const float xa[4] = {xv.x * w, xv.y * w, xv.z * w, xv.w * w};
        const float ba[4] = {bv.x, bv.y, bv.z, bv.w};
#pragma unroll
        for (int j = 0; j < 4; j++) {
            const int p = q * 4 + j;
            __half hx = __float2half(xa[j]);
            sAh[p * SPITCH + t] = hx;
            sAl[p * SPITCH + t] = __float2half(xa[j] - __half2float(hx));
            __half hb = __float2half(ba[j]);
            sBh[p * SPITCH + t] = hb;
            sBl[p * SPITCH + t] = __float2half(ba[j] - __half2float(hb));
        }
    }
    __syncthreads();

    const int wid = tid >> 5, lane = tid & 31;
    const int warp_m = wid & 3, warp_n = wid >> 2;
    const int a_row = lane & 15, a_col = (lane >> 4) * 8;
    const int b_row = (lane & 7) + ((lane >> 4) * 8), b_col = ((lane >> 3) & 1) * 8;
    const uint32_t uAh = (uint32_t)__cvta_generic_to_shared(sAh);
    const uint32_t uAl = (uint32_t)__cvta_generic_to_shared(sAl);
    const uint32_t uBh = (uint32_t)__cvta_generic_to_shared(sBh);
    const uint32_t uBl = (uint32_t)__cvta_generic_to_shared(sBl);

    float acc[4][4];
#pragma unroll
    for (int nt = 0; nt < 4; nt++)
#pragma unroll
        for (int i = 0; i < 4; i++) acc[nt][i] = 0.f;

#pragma unroll
    for (int kt = 0; kt < 4; kt++) {
        const int k0 = kt * 16;
        uint32_t ah[4], al[4], bh[2][4], bl[2][4];
        const uint32_t aoff = (uint32_t)((warp_m * 16 + a_row) * SPITCH + k0 + a_col) * 2;
        ldsm4(ah, uAh + aoff);
        ldsm4(al, uAl + aoff);
#pragma unroll
        for (int nb = 0; nb < 2; nb++) {
            const uint32_t boff =
                (uint32_t)((warp_n * 32 + nb * 16 + b_row) * SPITCH + k0 + b_col) * 2;
            ldsm4(bh[nb], uBh + boff);
            ldsm4(bl[nb], uBl + boff);
        }
#pragma unroll
        for (int nt = 0; nt < 4; nt++) {
            const int nb = nt >> 1, pr = (nt & 1) * 2;
            mma_f16(acc[nt], ah, bh[nb][pr], bh[nb][pr + 1]);
            mma_f16(acc[nt], ah, bl[nb][pr], bl[nb][pr + 1]);
            mma_f16(acc[nt], al, bh[nb][pr], bh[nb][pr + 1]);
        }
    }

    float* Sb = g_S + ((size_t)bh * NCHUNK + c) * (HEADDIM * D_STATE);
    const int g = lane >> 2, tig = lane & 3;
#pragma unroll
    for (int nt = 0; nt < 4; nt++) {
        const int ncol = warp_n * 32 + nt * 8 + 2 * tig;
        const int prow = warp_m * 16 + g;
        *(float2*)&Sb[prow * D_STATE + ncol] = make_float2(acc[nt][0], acc[nt][1]);
        *(float2*)&Sb[(prow + 8) * D_STATE + ncol] = make_float2(acc[nt][2], acc[nt][3]);
    }
    if (tid == 0) g_P[(size_t)bh * NCHUNK + c] = Lend;
}

// Phase B: fully parallel over state elements; H stored fp16
#define SPB 16
__global__ void __launch_bounds__(256) state_pass(void) {
    const int blk = blockIdx.x;
    const int bh = blk / SPB, seg = blk % SPB;
    const int e = seg * 256 + threadIdx.x;
    __shared__ float sP[NCHUNK];
    if (threadIdx.x < NCHUNK)
        sP[threadIdx.x] = expf(g_P[(size_t)bh * NCHUNK + threadIdx.x]);
    __syncthreads();
    float hv = 0.f;
    const size_t base = (size_t)bh * NCHUNK * (HEADDIM * D_STATE) + e;
#pragma unroll 4
    for (int c = 0; c < NCHUNK; c++) {
        const size_t off = base + (size_t)c * (HEADDIM * D_STATE);
        g_H[off] = __float2half(hv);
        hv = sP[c] * hv + g_S[off];
    }
}

// Phase C: H is fp16 (no lo residual) -> 9 smem tiles, 2 CH MMAs
#define CTILE (CT * SPITCH)
#define CSMEM (9 * CTILE * 2 + 2 * CT * 4)
__global__ void __launch_bounds__(256) chunk_output(const float* __restrict__ Dparam) {
    extern __shared__ __half cs[];
    __half* sCh = cs;
    __half* sCl = cs + CTILE;
    __half* sB2h = cs + 2 * CTILE;
    __half* sB2l = cs + 3 * CTILE;
    __half* sXh = cs + 4 * CTILE;
    __half* sXl = cs + 5 * CTILE;
    __half* sHh = cs + 6 * CTILE;
    __half* sGh = cs + 7 * CTILE;
    __half* sGl = cs + 8 * CTILE;
    float* sL = (float*)(cs + 9 * CTILE);
    float* sdt = sL + CT;

    const int c = blockIdx.x, h = blockIdx.y, b = blockIdx.z;
    const int tid = threadIdx.x;
    const int bh = b * NHEADS + h;
    const int rowbase = b * SEQLEN + c * CT;
    const float Dh = Dparam[h];

    if (tid < CT) {
        sdt[tid] = g_dtT[(size_t)bh * SEQLEN + c * CT + tid];
        sL[tid]  = g_dtAT[(size_t)bh * SEQLEN + c * CT + tid];
    }
    __syncthreads();
    if (tid == 0) {
        float run = 0.f;
        for (int t = 0; t < CT; t++) { run += sL[t]; sL[t] = run; }
    }

    const __half* Hbase = g_H + ((size_t)bh * NCHUNK + c) * (HEADDIM * D_STATE);
    for (int e = tid; e < CT * 16; e += 256) {
        const int t = e >> 4, q = e & 15;
        const float* rowp = g_xBC + (size_t)(rowbase + t) * CONV_DIM;
        float4 cv = *(const float4*)(rowp + D_INNER + D_STATE + q * 4);
        float4 bv = *(const float4*)(rowp + D_INNER + q * 4);
        float4 xv = *(const float4*)(rowp + h * HEADDIM + q * 4);
        uint2 hraw = *(const uint2*)(Hbase + t * D_STATE + q * 4);   // 4 halves; t plays p
        const __half* hh4 = (const __half*)&hraw;
        const float ca[4] = {cv.x, cv.y, cv.z, cv.w};
        const float ba[4] = {bv.x, bv.y, bv.z, bv.w};
        const float xa[4] = {xv.x, xv.y, xv.z, xv.w};
#pragma unroll
        for (int j = 0; j < 4; j++) {
            const int n = q * 4 + j;
            __half hc = __float2half(ca[j]);
            sCh[t * SPITCH + n] = hc;
            sCl[t * SPITCH + n] = __float2half(ca[j] - __half2float(hc));
            __half hb = __float2half(ba[j]);
            sB2h[t * SPITCH + n] = hb;
            sB2l[t * SPITCH + n] = __float2half(ba[j] - __half2float(hb));
            __half hx = __float2half(xa[j]);
            sXh[n * SPITCH + t] = hx;
            sXl[n * SPITCH + t] = __float2half(xa[j] - __half2float(hx));
            sHh[t * SPITCH + n] = hh4[j];
        }
    }
    __syncthreads();

    const int wid = tid >> 5, lane = tid & 31;
    const int warp_m = wid & 3, warp_n = wid >> 2;
    const int a_row = lane & 15, a_col = (lane >> 4) * 8;
    const int b_row = (lane & 7) + ((lane >> 4) * 8), b_col = ((lane >> 3) & 1) * 8;
    const int g = lane >> 2, tig = lane & 3;
    const uint32_t uCh = (uint32_t)__cvta_generic_to_shared(sCh);
    const uint32_t uCl = (uint32_t)__cvta_generic_to_shared(sCl);
    const uint32_t uB2h = (uint32_t)__cvta_generic_to_shared(sB2h);
    const uint32_t uB2l = (uint32_t)__cvta_generic_to_shared(sB2l);
    const uint32_t uXh = (uint32_t)__cvta_generic_to_shared(sXh);
    const uint32_t uXl = (uint32_t)__cvta_generic_to_shared(sXl);
    const uint32_t uHh = (uint32_t)__cvta_generic_to_shared(sHh);
    const uint32_t uGh = (uint32_t)__cvta_generic_to_shared(sGh);
    const uint32_t uGl = (uint32_t)__cvta_generic_to_shared(sGl);

    float gacc[4][4];
#pragma unroll
    for (int nt = 0; nt < 4; nt++)
#pragma unroll
        for (int i = 0; i < 4; i++) gacc[nt][i] = 0.f;
#pragma unroll
    for (int kt = 0; kt < 4; kt++) {
        const int k0 = kt * 16;
        uint32_t ah[4], al[4], bh[2][4], bl[2][4];
        const uint32_t aoff = (uint32_t)((warp_m * 16 + a_row) * SPITCH + k0 + a_col) * 2;
        ldsm4(ah, uCh + aoff);
        ldsm4(al, uCl + aoff);
#pragma unroll
        for (int nb = 0; nb < 2; nb++) {
            const uint32_t boff =
                (uint32_t)((warp_n * 32 + nb * 16 + b_row) * SPITCH + k0 + b_col) * 2;
            ldsm4(bh[nb], uB2h + boff);
            ldsm4(bl[nb], uB2l + boff);
        }
#pragma unroll
        for (int nt = 0; nt < 4; nt++) {
            const int nb = nt >> 1, pr = (nt & 1) * 2;
            mma_f16(gacc[nt], ah, bh[nb][pr], bh[nb][pr + 1]);
            mma_f16(gacc[nt], ah, bl[nb][pr], bl[nb][pr + 1]);
            mma_f16(gacc[nt], al, bh[nb][pr], bh[nb][pr + 1]);
        }
    }
    __syncthreads();

#pragma unroll
    for (int nt = 0; nt < 4; nt++) {
        const int s0 = warp_n * 32 + nt * 8 + 2 * tig;
#pragma unroll
        for (int r = 0; r < 2; r++) {
            const int t = warp_m * 16 + g + r * 8;
            float v0 = gacc[nt][r * 2], v1 = gacc[nt][r * 2 + 1];
            const float Lt = sL[t];
            v0 = (s0 <= t)     ? v0 * sdt[s0]     * expf(Lt - sL[s0])     : 0.f;
            v1 = (s0 + 1 <= t) ? v1 * sdt[s0 + 1] * expf(Lt - sL[s0 + 1]) : 0.f;
            __half h0 = __float2half(v0), h1 = __float2half(v1);
            *(__half2*)&sGh[t * SPITCH + s0] = __halves2half2(h0, h1);
            *(__half2*)&sGl[t * SPITCH + s0] = __halves2half2(
                __float2half(v0 - __half2float(h0)), __float2half(v1 - __half2float(h1)));
        }
    }
    __syncthreads();

    float yacc[4][4], cacc[4][4];
#pragma unroll
    for (int nt = 0; nt < 4; nt++)
#pragma unroll
        for (int i = 0; i < 4; i++) { yacc[nt][i] = 0.f; cacc[nt][i] = 0.f; }
#pragma unroll
    for (int kt = 0; kt < 4; kt++) {
        const int k0 = kt * 16;
        uint32_t gh[4], gl[4], ch[4], cl[4];
        uint32_t xh[2][4], xl[2][4], hh[2][4];
        const uint32_t aoff = (uint32_t)((warp_m * 16 + a_row) * SPITCH + k0 + a_col) * 2;
        ldsm4(gh, uGh + aoff);
        ldsm4(gl, uGl + aoff);
        ldsm4(ch, uCh + aoff);
        ldsm4(cl, uCl + aoff);
#pragma unroll
        for (int nb = 0; nb < 2; nb++) {
            const uint32_t boff =
                (uint32_t)((warp_n * 32 + nb * 16 + b_row) * SPITCH + k0 + b_col) * 2;
            ldsm4(xh[nb], uXh + boff);
            ldsm4(xl[nb], uXl + boff);
            ldsm4(hh[nb], uHh + boff);
        }
#pragma unroll
        for (int nt = 0; nt < 4; nt++) {
            const int nb = nt >> 1, pr = (nt & 1) * 2;
            mma_f16(yacc[nt], gh, xh[nb][pr], xh[nb][pr + 1]);
            mma_f16(yacc[nt], gh, xl[nb][pr], xl[nb][pr + 1]);
            mma_f16(yacc[nt], gl, xh[nb][pr], xh[nb][pr + 1]);
            mma_f16(cacc[nt], ch, hh[nb][pr], hh[nb][pr + 1]);
            mma_f16(cacc[nt], cl, hh[nb][pr], hh[nb][pr + 1]);
        }
    }

#pragma unroll
    for (int nt = 0; nt < 4; nt++) {
        const int p = warp_n * 32 + nt * 8 + 2 * tig;
#pragma unroll
        for (int r = 0; r < 2; r++) {
            const int t = warp_m * 16 + g + r * 8;
            const float et = expf(sL[t]);
            const float x0 = __half2float(sXh[p * SPITCH + t]) + __half2float(sXl[p * SPITCH + t]);
            const float x1 = __half2float(sXh[(p + 1) * SPITCH + t]) + __half2float(sXl[(p + 1) * SPITCH + t]);
            const float o0 = yacc[nt][r * 2] + cacc[nt][r * 2] * et + Dh * x0;
            const float o1 = yacc[nt][r * 2 + 1] + cacc[nt][r * 2 + 1] * et + Dh * x1;
            *(float2*)&g_y[(size_t)(rowbase + t) * D_INNER + h * HEADDIM + p] =
                make_float2(o0, o1);
        }
    }
}

// ---------------- gate + RMSNorm (vectorized), writing fp16 ----------------
__global__ void __launch_bounds__(192) norm_kernel(const float* __restrict__ norm_w) {
    const int row = blockIdx.x;
    const int tid = threadIdx.x;
    const float4* z4 = (const float4*)(g_zxbcdt + (size_t)row * D_IN_PROJ);
    const float4* y4 = (const float4*)(g_y + (size_t)row * D_INNER);
    __half* hrow = g_yh + (size_t)row * D_INNER;

    float4 gv[2];
    float ss = 0.f;
#pragma unroll
    for (int i = 0; i < 2; i++) {
        const int idx = tid + i * 192;
        float4 z = z4[idx];
        float4 y = y4[idx];
        y.x *= z.x / (1.f + expf(-z.x));
        y.y *= z.y / (1.f + expf(-z.y));
        y.z *= z.z / (1.f + expf(-z.z));
        y.w *= z.w / (1.f + expf(-z.w));
        gv[i] = y;
        ss += y.x * y.x + y.y * y.y + y.z * y.z + y.w * y.w;
    }
#pragma unroll
    for (int o = 16; o; o >>= 1) ss += __shfl_xor_sync(0xffffffffu, ss, o);
    __shared__ float red[6];
    if ((tid & 31) == 0) red[tid >> 5] = ss;
    __syncthreads();
    __shared__ float stotal;
    if (tid == 0) {
        float v = red[0] + red[1] + red[2] + red[3] + red[4] + red[5];
        stotal = rsqrtf(v * (1.f / D_INNER) + 1e-5f);
    }
    __syncthreads();
    const float scale = stotal;
#pragma unroll
    for (int i = 0; i < 2; i++) {
        const int idx = tid + i * 192;
        float4 w = *(const float4*)(norm_w + idx * 4);
        __half h[4];
        h[0] = __float2half(gv[i].x * scale * w.x);
        h[1] = __float2half(gv[i].y * scale * w.y);
        h[2] = __float2half(gv[i].z * scale * w.z);
        h[3] = __float2half(gv[i].w * scale * w.w);
        *(uint2*)(hrow + idx * 4) = *(uint2*)h;
    }
}

// ---------------- launch ----------------
extern "C" void kernel_launch(void* const* d_in, const int* in_sizes, int n_in,
                              void* d_out, int out_size) {
    const float* x       = (const float*)d_in[0];
    const float* W_in    = (const float*)d_in[1];
    const float* conv_w  = (const float*)d_in[2];
    const float* conv_b  = (const float*)d_in[3];
    const float* dt_bias = (const float*)d_in[4];
    const float* A_log   = (const float*)d_in[5];
    const float* Dp      = (const float*)d_in[6];
    const float* norm_w  = (const float*)d_in[7];
    const float* W_out   = (const float*)d_in[8];
    float* out = (float*)d_out;

    float *zx_ptr;
    cudaGetSymbolAddress((void**)&zx_ptr, g_zxbcdt);
    __half *xh, *yh, *wi, *wo;
    cudaGetSymbolAddress((void**)&xh, g_xh);
    cudaGetSymbolAddress((void**)&yh, g_yh);
    cudaGetSymbolAddress((void**)&wi, g_wi);
    cudaGetSymbolAddress((void**)&wo, g_wo);

    static int attr_set = 0;
    if (!attr_set) {
        cudaFuncSetAttribute(mma_gemm, cudaFuncAttributeMaxDynamicSharedMemorySize, GSMEM);
        cudaFuncSetAttribute(chunk_output, cudaFuncAttributeMaxDynamicSharedMemorySize, CSMEM);
        attr_set = 1;
    }

    // 0-1) preps for GEMM1
    convert_f16<<<(ROWS * D_MODEL / 4 + 255) / 256, 256>>>(x, xh, ROWS * D_MODEL / 4);
    transpose_f16<<<dim3(NPAD1 / 32, D_MODEL / 32), dim3(32, 8)>>>(
        W_in, wi, D_MODEL, D_IN_PROJ, NPAD1);

    // 2) zxbcdt = x @ W_in
    mma_gemm<<<dim3(NPAD1 / 128, ROWS / 128), 256, GSMEM>>>(
        xh, wi, zx_ptr, ROWS, D_IN_PROJ, D_MODEL);

    // 3) conv + silu   (launch index 3 -> ncu profile slot)
    conv_kernel<<<((ROWS / 4) * NC4 + 255) / 256, 256>>>(conv_w, conv_b);

    // 4) dt / dtA
    dt_kernel<<<(BATCH * NHEADS * SEQLEN + 255) / 256, 256>>>(dt_bias, A_log);

    // 5-7) chunked SSM scan
    chunk_state<<<dim3(NCHUNK, NHEADS, BATCH), 256>>>();
    state_pass<<<BATCH * NHEADS * SPB, 256>>>();
    chunk_output<<<dim3(NCHUNK, NHEADS, BATCH), 256, CSMEM>>>(Dp);

    // 8) gate + RMSNorm
    norm_kernel<<<ROWS, 192>>>(norm_w);

    // 9) transpose W_out
    transpose_f16<<<dim3(D_MODEL / 32, D_INNER / 32), dim3(32, 8)>>>(
        W_out, wo, D_INNER, D_MODEL, D_MODEL);

    // 10) out = y @ W_out
    mma_gemm<<<dim3(D_MODEL / 128, ROWS / 128), 256, GSMEM>>>(
        yh, wo, out, ROWS, D_MODEL, D_INNER);
}

// round 14
// speedup vs baseline: 1.5583x; 1.0406x over previous
#include <cuda_runtime.h>
#include <cuda_fp16.h>
#include <math.h>
#include <stdint.h>

#define D_MODEL   768
#define D_STATE   64
#define D_CONV    4
#define HEADDIM   64
#define D_INNER   1536
#define NHEADS    24
#define CONV_DIM  1664
#define D_IN_PROJ 3224
#define BATCH     2
#define SEQLEN    4096
#define ROWS      (BATCH*SEQLEN)
#define NPAD1     3328
#define NCHUNK    64
#define CT        64

// ---------------- scratch (device globals; no allocation) ----------------
__device__ float g_zxbcdt[(size_t)ROWS * D_IN_PROJ];
__device__ float g_xBC[(size_t)ROWS * CONV_DIM];
__device__ __half g_yraw[(size_t)ROWS * D_INNER];
__device__ float g_dtT[(size_t)BATCH * NHEADS * SEQLEN];
__device__ float g_dtAT[(size_t)BATCH * NHEADS * SEQLEN];
__device__ __half g_S[(size_t)BATCH * NHEADS * NCHUNK * HEADDIM * D_STATE];
__device__ __half g_H[(size_t)BATCH * NHEADS * NCHUNK * HEADDIM * D_STATE];
__device__ float g_P[(size_t)BATCH * NHEADS * NCHUNK];
__device__ __half g_xh[(size_t)ROWS * D_MODEL];
__device__ __half g_yh[(size_t)ROWS * D_INNER];
__device__ __half g_wi[(size_t)NPAD1 * D_MODEL];
__device__ __half g_wo[(size_t)D_MODEL * D_INNER];

// ---------------- common PTX helpers ----------------
__device__ __forceinline__ void cp16(uint32_t dst, const void* src) {
    asm volatile("cp.async.ca.shared.global [%0], [%1], 16;" :: "r"(dst), "l"(src) : "memory");
}
__device__ __forceinline__ void cp_commit() {
    asm volatile("cp.async.commit_group;" ::: "memory");
}
template <int N> __device__ __forceinline__ void cp_wait() {
    asm volatile("cp.async.wait_group %0;" :: "n"(N) : "memory");
}
__device__ __forceinline__ void ldsm4(uint32_t* r, uint32_t addr) {
    asm volatile("ldmatrix.sync.aligned.m8n8.x4.shared.b16 {%0,%1,%2,%3}, [%4];"
                 : "=r"(r[0]), "=r"(r[1]), "=r"(r[2]), "=r"(r[3]) : "r"(addr));
}
__device__ __forceinline__ void mma_f16(float* d, const uint32_t* a, uint32_t b0, uint32_t b1) {
    asm volatile("mma.sync.aligned.m16n8k16.row.col.f32.f16.f16.f32 "
                 "{%0,%1,%2,%3}, {%4,%5,%6,%7}, {%8,%9}, {%0,%1,%2,%3};"
                 : "+f"(d[0]), "+f"(d[1]), "+f"(d[2]), "+f"(d[3])
                 : "r"(a[0]), "r"(a[1]), "r"(a[2]), "r"(a[3]), "r"(b0), "r"(b1));
}

// ---------------- warp-MMA fp16 GEMM (R8 best config: KC=32, 2 CTA/SM) ----------------
#define KC      32
#define PITCH   40
#define TILE_E  (128 * PITCH)
#define TILE_B  (TILE_E * 2)
#define STAGE_B (2 * TILE_B)
#define STAGES  3
#define GSMEM   (STAGES * STAGE_B)      // 61440 bytes

__global__ void __launch_bounds__(256, 2) mma_gemm(
    const __half* __restrict__ Ah, const __half* __restrict__ Bh,
    float* __restrict__ C, int M, int N, int K) {
    extern __shared__ __half sm[];
    const int tid = threadIdx.x;
    const int wid = tid >> 5, lane = tid & 31;
    const int warp_m = wid >> 1, warp_n = wid & 1;
    const int g = lane >> 2, tig = lane & 3;
    const int bm = blockIdx.y * 128, bn = blockIdx.x * 128;
    const uint32_t sbase = (uint32_t)__cvta_generic_to_shared(sm);

    float acc[2][8][4];
#pragma unroll
    for (int mt = 0; mt < 2; mt++)
#pragma unroll
        for (int nt = 0; nt < 8; nt++)
#pragma unroll
            for (int i = 0; i < 4; i++) acc[mt][nt][i] = 0.f;

    const int nkt = K / KC;
    const int r_ld = tid >> 2, seg_ld = tid & 3;

    auto issue = [&](int kt) {
        const int st = kt % STAGES;
        const int kofs = kt * KC;
        const uint32_t dst0 = sbase + st * STAGE_B;
        const __half* srcs[2] = {Ah, Bh};
#pragma unroll
        for (int arr = 0; arr < 2; arr++) {
            const int rbase = (arr == 0) ? bm : bn;
            const uint32_t db = dst0 + arr * TILE_B;
#pragma unroll
            for (int i = 0; i < 2; i++) {
                const int r = r_ld + i * 64;
                cp16(db + (uint32_t)(r * PITCH + seg_ld * 8) * 2,
                     srcs[arr] + (size_t)(rbase + r) * K + kofs + seg_ld * 8);
            }
        }
    };

    issue(0); cp_commit();
    if (nkt > 1) { issue(1); cp_commit(); }

    const int a_row = (lane & 15);
    const int a_col = (lane >> 4) * 8;
    const int b_row = (lane & 7) + ((lane >> 4) * 8);
    const int b_col = ((lane >> 3) & 1) * 8;

    for (int kt = 0; kt < nkt; kt++) {
        if (kt + 2 < nkt) cp_wait<1>(); else cp_wait<0>();
        __syncthreads();
        if (kt + 2 < nkt) { issue(kt + 2); cp_commit(); }

        const uint32_t st0 = sbase + (kt % STAGES) * STAGE_B;
        const uint32_t aA = st0;
        const uint32_t bB = st0 + TILE_B;

#pragma unroll
        for (int ks = 0; ks < KC; ks += 16) {
            uint32_t ah[2][4], bf[4][4];
#pragma unroll
            for (int mt = 0; mt < 2; mt++) {
                const uint32_t aoff =
                    (uint32_t)((warp_m * 32 + mt * 16 + a_row) * PITCH + ks + a_col) * 2;
                ldsm4(ah[mt], aA + aoff);
            }
#pragma unroll
            for (int ntp = 0; ntp < 4; ntp++) {
                const uint32_t boff =
                    (uint32_t)((warp_n * 64 + ntp * 16 + b_row) * PITCH + ks + b_col) * 2;
                ldsm4(bf[ntp], bB + boff);
            }
#pragma unroll
            for (int nt = 0; nt < 8; nt++) {
                const uint32_t b0 = bf[nt >> 1][(nt & 1) * 2];
                const uint32_t b1 = bf[nt >> 1][(nt & 1) * 2 + 1];
#pragma unroll
                for (int mt = 0; mt < 2; mt++)
                    mma_f16(acc[mt][nt], ah[mt], b0, b1);
            }
        }
        __syncthreads();
    }

#pragma unroll
    for (int mt = 0; mt < 2; mt++) {
        const int row0 = bm + warp_m * 32 + mt * 16 + g;
#pragma unroll
        for (int nt = 0; nt < 8; nt++) {
            const int col = bn + warp_n * 64 + nt * 8 + 2 * tig;
            if (col < N) {
                *(float2*)&C[(size_t)row0 * N + col] = make_float2(acc[mt][nt][0], acc[mt][nt][1]);
                *(float2*)&C[(size_t)(row0 + 8) * N + col] = make_float2(acc[mt][nt][2], acc[mt][nt][3]);
            }
        }
    }
}

// ---------------- fp32 -> fp16 convert ----------------
__global__ void convert_f16(const float* __restrict__ src,
                            __half* __restrict__ dst, int n4) {
    int i = blockIdx.x * blockDim.x + threadIdx.x;
    if (i >= n4) return;
    const int idx = i * 4;
    float4 v = *(const float4*)(src + idx);
    __half h[4];
    h[0] = __float2half(v.x); h[1] = __float2half(v.y);
    h[2] = __float2half(v.z); h[3] = __float2half(v.w);
    *(uint2*)(dst + idx) = *(uint2*)h;
}

// ---------------- transpose to fp16 ----------------
__global__ void transpose_f16(const float* __restrict__ src,
                              __half* __restrict__ dst,
                              int R, int C, int Cpad) {
    __shared__ float tile[32][33];
    const int c0 = blockIdx.x * 32, r0 = blockIdx.y * 32;
    const int tx = threadIdx.x, ty = threadIdx.y;
    const int c = c0 + tx;
#pragma unroll
    for (int j = ty; j < 32; j += 8) {
        const int r = r0 + j;
        tile[j][tx] = (r < R && c < C) ? src[(size_t)r * C + c] : 0.f;
    }
    __syncthreads();
#pragma unroll
    for (int j = ty; j < 32; j += 8) {
        const int orow = c0 + j;
        const int ocol = r0 + tx;
        if (orow < Cpad && ocol < R)
            dst[(size_t)orow * R + ocol] = __float2half(tile[tx][j]);
    }
}

// ---------------- dt ----------------
__global__ void dt_kernel(const float* __restrict__ dt_bias,
                          const float* __restrict__ A_log) {
    int idx = blockIdx.x * blockDim.x + threadIdx.x;
    if (idx >= BATCH * NHEADS * SEQLEN) return;
    const int l = idx % SEQLEN;
    const int bh = idx / SEQLEN;
    const int h = bh % NHEADS, b = bh / NHEADS;
    float v = g_zxbcdt[(size_t)(b * SEQLEN + l) * D_IN_PROJ + (D_INNER + CONV_DIM) + h]
              + dt_bias[h];
    float dtv = (v > 20.f) ? v : log1pf(expf(v));
    float A = -expf(A_log[h]);
    g_dtT[idx] = dtv;
    g_dtAT[idx] = dtv * A;
}

// ---------------- causal depthwise conv + silu: 4-row temporal blocking ----------------
#define NC4 (CONV_DIM / 4)
__global__ void conv_kernel(const float* __restrict__ conv_w,
                            const float* __restrict__ conv_b) {
    int i = blockIdx.x * blockDim.x + threadIdx.x;
    if (i >= (ROWS / 4) * NC4) return;
    const int c4 = (i % NC4) * 4;
    const int rb = (i / NC4) * 4;
    const int l0 = rb & (SEQLEN - 1);

    const float4 bias = *(const float4*)(conv_b + c4);
    const float4 w0 = *(const float4*)(conv_w + (c4 + 0) * 4);
    const float4 w1 = *(const float4*)(conv_w + (c4 + 1) * 4);
    const float4 w2 = *(const float4*)(conv_w + (c4 + 2) * 4);
    const float4 w3 = *(const float4*)(conv_w + (c4 + 3) * 4);
    const float wt0[4] = {w0.x, w0.y, w0.z, w0.w};
    const float wt1[4] = {w1.x, w1.y, w1.z, w1.w};
    const float wt2[4] = {w2.x, w2.y, w2.z, w2.w};
    const float wt3[4] = {w3.x, w3.y, w3.z, w3.w};

    float4 v[7];
#pragma unroll
    for (int j = 0; j < 7; j++) {
        const int ls = l0 + j - 3;
        if (ls >= 0)
            v[j] = *(const float4*)(g_zxbcdt + (size_t)(rb + j - 3) * D_IN_PROJ + D_INNER + c4);
        else
            v[j] = make_float4(0.f, 0.f, 0.f, 0.f);
    }

#pragma unroll
    for (int j = 0; j < 4; j++) {
        float4 acc = bias;
#pragma unroll
        for (int k = 0; k < D_CONV; k++) {
            acc.x += v[j + k].x * wt0[k];
            acc.y += v[j + k].y * wt1[k];
            acc.z += v[j + k].z * wt2[k];
            acc.w += v[j + k].w * wt3[k];
        }
        acc.x = acc.x / (1.f + expf(-acc.x));
        acc.y = acc.y / (1.f + expf(-acc.y));
        acc.z = acc.z / (1.f + expf(-acc.z));
        acc.w = acc.w / (1.f + expf(-acc.w));
        *(float4*)(g_xBC + (size_t)(rb + j) * CONV_DIM + c4) = acc;
    }
}

// ================= chunked SSM scan (tensor-core) =================
#define SPITCH 72

// Phase A (S stored fp16)
__global__ void __launch_bounds__(256) chunk_state(void) {
    __shared__ __half sAh[CT * SPITCH], sAl[CT * SPITCH];
    __shared__ __half sBh[CT * SPITCH], sBl[CT * SPITCH];
    __shared__ float sL[CT], sdt[CT];
    const int c = blockIdx.x, h = blockIdx.y, b = blockIdx.z;
    const int tid = threadIdx.x;
    const int bh = b * NHEADS + h;
    const int rowbase = b * SEQLEN + c * CT;

    if (tid < CT) {
        sdt[tid] = g_dtT[(size_t)bh * SEQLEN + c * CT + tid];
        sL[tid]  = g_dtAT[(size_t)bh * SEQLEN + c * CT + tid];
    }
    __syncthreads();
    if (tid == 0) {
        float run = 0.f;
        for (int t = 0; t < CT; t++) { run += sL[t]; sL[t] = run; }
    }
    __syncthreads();
    const float Lend = sL[CT - 1];

    for (int e = tid; e < CT * 16; e += 256) {
        const int t = e >> 4, q = e & 15;
        const float* rowp = g_xBC + (size_t)(rowbase + t) * CONV_DIM;
        const float w = sdt[t] * expf(Lend - sL[t]);
        float4 xv = *(const float4*)(rowp + h * HEADDIM + q * 4);
        float4 bv = *(const float4*)(rowp + D_INNER + q * 4);
        const float xa[4] = {xv.x * w, xv.y * w, xv.z * w, xv.w * w};
        const float ba[4] = {bv.x, bv.y, bv.z, bv.w};
#pragma unroll
        for (int j = 0; j < 4; j++) {
            const int p = q * 4 + j;
            __half hx = __float2half(xa[j]);
            sAh[p * SPITCH + t] = hx;
            sAl[p * SPITCH + t] = __float2half(xa[j] - __half2float(hx));
            __half hb = __float2half(ba[j]);
            sBh[p * SPITCH + t] = hb;
            sBl[p * SPITCH + t] = __float2half(ba[j] - __half2float(hb));
        }
    }
    __syncthreads();

    const int wid = tid >> 5, lane = tid & 31;
    const int warp_m = wid & 3, warp_n = wid >> 2;
    const int a_row = lane & 15, a_col = (lane >> 4) * 8;
    const int b_row = (lane & 7) + ((lane >> 4) * 8), b_col = ((lane >> 3) & 1) * 8;
    const uint32_t uAh = (uint32_t)__cvta_generic_to_shared(sAh);
    const uint32_t uAl = (uint32_t)__cvta_generic_to_shared(sAl);
    const uint32_t uBh = (uint32_t)__cvta_generic_to_shared(sBh);
    const uint32_t uBl = (uint32_t)__cvta_generic_to_shared(sBl);

    float acc[4][4];
#pragma unroll
    for (int nt = 0; nt < 4; nt++)
#pragma unroll
        for (int i = 0; i < 4; i++) acc[nt][i] = 0.f;

#pragma unroll
    for (int kt = 0; kt < 4; kt++) {
        const int k0 = kt * 16;
        uint32_t ah[4], al[4], bh[2][4], bl[2][4];
        const uint32_t aoff = (uint32_t)((warp_m * 16 + a_row) * SPITCH + k0 + a_col) * 2;
        ldsm4(ah, uAh + aoff);
        ldsm4(al, uAl + aoff);
#pragma unroll
        for (int nb = 0; nb < 2; nb++) {
            const uint32_t boff =
                (uint32_t)((warp_n * 32 + nb * 16 + b_row) * SPITCH + k0 + b_col) * 2;
            ldsm4(bh[nb], uBh + boff);
            ldsm4(bl[nb], uBl + boff);
        }
#pragma unroll
        for (int nt = 0; nt < 4; nt++) {
            const int nb = nt >> 1, pr = (nt & 1) * 2;
            mma_f16(acc[nt], ah, bh[nb][pr], bh[nb][pr + 1]);
            mma_f16(acc[nt], ah, bl[nb][pr], bl[nb][pr + 1]);
            mma_f16(acc[nt], al, bh[nb][pr], bh[nb][pr + 1]);
        }
    }

    __half* Sb = g_S + ((size_t)bh * NCHUNK + c) * (HEADDIM * D_STATE);
    const int g = lane >> 2, tig = lane & 3;
#pragma unroll
    for (int nt = 0; nt < 4; nt++) {
        const int ncol = warp_n * 32 + nt * 8 + 2 * tig;
        const int prow = warp_m * 16 + g;
        *(__half2*)&Sb[prow * D_STATE + ncol] =
            __halves2half2(__float2half(acc[nt][0]), __float2half(acc[nt][1]));
        *(__half2*)&Sb[(prow + 8) * D_STATE + ncol] =
            __halves2half2(__float2half(acc[nt][2]), __float2half(acc[nt][3]));
    }
    if (tid == 0) g_P[(size_t)bh * NCHUNK + c] = Lend;
}

// Phase B: fully parallel over state elements; S,H fp16
#define SPB 16
__global__ void __launch_bounds__(256) state_pass(void) {
    const int blk = blockIdx.x;
    const int bh = blk / SPB, seg = blk % SPB;
    const int e = seg * 256 + threadIdx.x;
    __shared__ float sP[NCHUNK];
    if (threadIdx.x < NCHUNK)
        sP[threadIdx.x] = expf(g_P[(size_t)bh * NCHUNK + threadIdx.x]);
    __syncthreads();
    float hv = 0.f;
    const size_t base = (size_t)bh * NCHUNK * (HEADDIM * D_STATE) + e;
#pragma unroll 4
    for (int c = 0; c < NCHUNK; c++) {
        const size_t off = base + (size_t)c * (HEADDIM * D_STATE);
        g_H[off] = __float2half(hv);
        hv = sP[c] * hv + __half2float(g_S[off]);
    }
}

// Phase C: H fp16 -> 9 smem tiles, 2 CH MMAs; y written fp16
#define CTILE (CT * SPITCH)
#define CSMEM (9 * CTILE * 2 + 2 * CT * 4)
__global__ void __launch_bounds__(256) chunk_output(const float* __restrict__ Dparam) {
    extern __shared__ __half cs[];
    __half* sCh = cs;
    __half* sCl = cs + CTILE;
    __half* sB2h = cs + 2 * CTILE;
    __half* sB2l = cs + 3 * CTILE;
    __half* sXh = cs + 4 * CTILE;
    __half* sXl = cs + 5 * CTILE;
    __half* sHh = cs + 6 * CTILE;
    __half* sGh = cs + 7 * CTILE;
    __half* sGl = cs + 8 * CTILE;
    float* sL = (float*)(cs + 9 * CTILE);
    float* sdt = sL + CT;

    const int c = blockIdx.x, h = blockIdx.y, b = blockIdx.z;
    const int tid = threadIdx.x;
    const int bh = b * NHEADS + h;
    const int rowbase = b * SEQLEN + c * CT;
    const float Dh = Dparam[h];

    if (tid < CT) {
        sdt[tid] = g_dtT[(size_t)bh * SEQLEN + c * CT + tid];
        sL[tid]  = g_dtAT[(size_t)bh * SEQLEN + c * CT + tid];
    }
    __syncthreads();
    if (tid == 0) {
        float run = 0.f;
        for (int t = 0; t < CT; t++) { run += sL[t]; sL[t] = run; }
    }

    const __half* Hbase = g_H + ((size_t)bh * NCHUNK + c) * (HEADDIM * D_STATE);
    for (int e = tid; e < CT * 16; e += 256) {
        const int t = e >> 4, q = e & 15;
        const float* rowp = g_xBC + (size_t)(rowbase + t) * CONV_DIM;
        float4 cv = *(const float4*)(rowp + D_INNER + D_STATE + q * 4);
        float4 bv = *(const float4*)(rowp + D_INNER + q * 4);
        float4 xv = *(const float4*)(rowp + h * HEADDIM + q * 4);
        uint2 hraw = *(const uint2*)(Hbase + t * D_STATE + q * 4);
        const __half* hh4 = (const __half*)&hraw;
        const float ca[4] = {cv.x, cv.y, cv.z, cv.w};
        const float ba[4] = {bv.x, bv.y, bv.z, bv.w};
        const float xa[4] = {xv.x, xv.y, xv.z, xv.w};
#pragma unroll
        for (int j = 0; j < 4; j++) {
            const int n = q * 4 + j;
            __half hc = __float2half(ca[j]);
            sCh[t * SPITCH + n] = hc;
            sCl[t * SPITCH + n] = __float2half(ca[j] - __half2float(hc));
            __half hb = __float2half(ba[j]);
            sB2h[t * SPITCH + n] = hb;
            sB2l[t * SPITCH + n] = __float2half(ba[j] - __half2float(hb));
            __half hx = __float2half(xa[j]);
            sXh[n * SPITCH + t] = hx;
            sXl[n * SPITCH + t] = __float2half(xa[j] - __half2float(hx));
            sHh[t * SPITCH + n] = hh4[j];
        }
    }
    __syncthreads();

    const int wid = tid >> 5, lane = tid & 31;
    const int warp_m = wid & 3, warp_n = wid >> 2;
    const int a_row = lane & 15, a_col = (lane >> 4) * 8;
    const int b_row = (lane & 7) + ((lane >> 4) * 8), b_col = ((lane >> 3) & 1) * 8;
    const int g = lane >> 2, tig = lane & 3;
    const uint32_t uCh = (uint32_t)__cvta_generic_to_shared(sCh);
    const uint32_t uCl = (uint32_t)__cvta_generic_to_shared(sCl);
    const uint32_t uB2h = (uint32_t)__cvta_generic_to_shared(sB2h);
    const uint32_t uB2l = (uint32_t)__cvta_generic_to_shared(sB2l);
    const uint32_t uXh = (uint32_t)__cvta_generic_to_shared(sXh);
    const uint32_t uXl = (uint32_t)__cvta_generic_to_shared(sXl);
    const uint32_t uHh = (uint32_t)__cvta_generic_to_shared(sHh);
    const uint32_t uGh = (uint32_t)__cvta_generic_to_shared(sGh);
    const uint32_t uGl = (uint32_t)__cvta_generic_to_shared(sGl);

    float gacc[4][4];
#pragma unroll
    for (int nt = 0; nt < 4; nt++)
#pragma unroll
        for (int i = 0; i < 4; i++) gacc[nt][i] = 0.f;
#pragma unroll
    for (int kt = 0; kt < 4; kt++) {
        const int k0 = kt * 16;
        uint32_t ah[4], al[4], bh[2][4], bl[2][4];
        const uint32_t aoff = (uint32_t)((warp_m * 16 + a_row) * SPITCH + k0 + a_col) * 2;
        ldsm4(ah, uCh + aoff);
        ldsm4(al, uCl + aoff);
#pragma unroll
        for (int nb = 0; nb < 2; nb++) {
            const uint32_t boff =
                (uint32_t)((warp_n * 32 + nb * 16 + b_row) * SPITCH + k0 + b_col) * 2;
            ldsm4(bh[nb], uB2h + boff);
            ldsm4(bl[nb], uB2l + boff);
        }
#pragma unroll
        for (int nt = 0; nt < 4; nt++) {
            const int nb = nt >> 1, pr = (nt & 1) * 2;
            mma_f16(gacc[nt], ah, bh[nb][pr], bh[nb][pr + 1]);
            mma_f16(gacc[nt], ah, bl[nb][pr], bl[nb][pr + 1]);
            mma_f16(gacc[nt], al, bh[nb][pr], bh[nb][pr + 1]);
        }
    }
    __syncthreads();

#pragma unroll
    for (int nt = 0; nt < 4; nt++) {
        const int s0 = warp_n * 32 + nt * 8 + 2 * tig;
#pragma unroll
        for (int r = 0; r < 2; r++) {
            const int t = warp_m * 16 + g + r * 8;
            float v0 = gacc[nt][r * 2], v1 = gacc[nt][r * 2 + 1];
            const float Lt = sL[t];
            v0 = (s0 <= t)     ? v0 * sdt[s0]     * expf(Lt - sL[s0])     : 0.f;
            v1 = (s0 + 1 <= t) ? v1 * sdt[s0 + 1] * expf(Lt - sL[s0 + 1]) : 0.f;
            __half h0 = __float2half(v0), h1 = __float2half(v1);
            *(__half2*)&sGh[t * SPITCH + s0] = __halves2half2(h0, h1);
            *(__half2*)&sGl[t * SPITCH + s0] = __halves2half2(
                __float2half(v0 - __half2float(h0)), __float2half(v1 - __half2float(h1)));
        }
    }
    __syncthreads();

    float yacc[4][4], cacc[4][4];
#pragma unroll
    for (int nt = 0; nt < 4; nt++)
#pragma unroll
        for (int i = 0; i < 4; i++) { yacc[nt][i] = 0.f; cacc[nt][i] = 0.f; }
#pragma unroll
    for (int kt = 0; kt < 4; kt++) {
        const int k0 = kt * 16;
        uint32_t gh[4], gl[4], ch[4], cl[4];
        uint32_t xh[2][4], xl[2][4], hh[2][4];
        const uint32_t aoff = (uint32_t)((warp_m * 16 + a_row) * SPITCH + k0 + a_col) * 2;
        ldsm4(gh, uGh + aoff);
        ldsm4(gl, uGl + aoff);
        ldsm4(ch, uCh + aoff);
        ldsm4(cl, uCl + aoff);
#pragma unroll
        for (int nb = 0; nb < 2; nb++) {
            const uint32_t boff =
                (uint32_t)((warp_n * 32 + nb * 16 + b_row) * SPITCH + k0 + b_col) * 2;
            ldsm4(xh[nb], uXh + boff);
            ldsm4(xl[nb], uXl + boff);
            ldsm4(hh[nb], uHh + boff);
        }
#pragma unroll
        for (int nt = 0; nt < 4; nt++) {
            const int nb = nt >> 1, pr = (nt & 1) * 2;
            mma_f16(yacc[nt], gh, xh[nb][pr], xh[nb][pr + 1]);
            mma_f16(yacc[nt], gh, xl[nb][pr], xl[nb][pr + 1]);
            mma_f16(yacc[nt], gl, xh[nb][pr], xh[nb][pr + 1]);
            mma_f16(cacc[nt], ch, hh[nb][pr], hh[nb][pr + 1]);
            mma_f16(cacc[nt], cl, hh[nb][pr], hh[nb][pr + 1]);
        }
    }

#pragma unroll
    for (int nt = 0; nt < 4; nt++) {
        const int p = warp_n * 32 + nt * 8 + 2 * tig;
#pragma unroll
        for (int r = 0; r < 2; r++) {
            const int t = warp_m * 16 + g + r * 8;
            const float et = expf(sL[t]);
            const float x0 = __half2float(sXh[p * SPITCH + t]) + __half2float(sXl[p * SPITCH + t]);
            const float x1 = __half2float(sXh[(p + 1) * SPITCH + t]) + __half2float(sXl[(p + 1) * SPITCH + t]);
            const float o0 = yacc[nt][r * 2] + cacc[nt][r * 2] * et + Dh * x0;
            const float o1 = yacc[nt][r * 2 + 1] + cacc[nt][r * 2 + 1] * et + Dh * x1;
            *(__half2*)&g_yraw[(size_t)(rowbase + t) * D_INNER + h * HEADDIM + p] =
                __halves2half2(__float2half(o0), __float2half(o1));
        }
    }
}

// ---------------- gate + RMSNorm (vectorized, y fp16 in), writing fp16 ----------------
__global__ void __launch_bounds__(192) norm_kernel(const float* __restrict__ norm_w) {
    const int row = blockIdx.x;
    const int tid = threadIdx.x;
    const float4* z4 = (const float4*)(g_zxbcdt + (size_t)row * D_IN_PROJ);
    const __half* yrow = g_yraw + (size_t)row * D_INNER;
    __half* hrow = g_yh + (size_t)row * D_INNER;

    float4 gv[2];
    float ss = 0.f;
#pragma unroll
    for (int i = 0; i < 2; i++) {
        const int idx = tid + i * 192;
        float4 z = z4[idx];
        uint2 yr = *(const uint2*)(yrow + idx * 4);
        const __half* y4 = (const __half*)&yr;
        float4 y = make_float4(__half2float(y4[0]), __half2float(y4[1]),
                               __half2float(y4[2]), __half2float(y4[3]));
        y.x *= z.x / (1.f + expf(-z.x));
        y.y *= z.y / (1.f + expf(-z.y));
        y.z *= z.z / (1.f + expf(-z.z));
        y.w *= z.w / (1.f + expf(-z.w));
        gv[i] = y;
        ss += y.x * y.x + y.y * y.y + y.z * y.z + y.w * y.w;
    }
#pragma unroll
    for (int o = 16; o; o >>= 1) ss += __shfl_xor_sync(0xffffffffu, ss, o);
    __shared__ float red[6];
    if ((tid & 31) == 0) red[tid >> 5] = ss;
    __syncthreads();
    __shared__ float stotal;
    if (tid == 0) {
        float v = red[0] + red[1] + red[2] + red[3] + red[4] + red[5];
        stotal = rsqrtf(v * (1.f / D_INNER) + 1e-5f);
    }
    __syncthreads();
    const float scale = stotal;
#pragma unroll
    for (int i = 0; i < 2; i++) {
        const int idx = tid + i * 192;
        float4 w = *(const float4*)(norm_w + idx * 4);
        __half h[4];
        h[0] = __float2half(gv[i].x * scale * w.x);
        h[1] = __float2half(gv[i].y * scale * w.y);
        h[2] = __float2half(gv[i].z * scale * w.z);
        h[3] = __float2half(gv[i].w * scale * w.w);
        *(uint2*)(hrow + idx * 4) = *(uint2*)h;
    }
}

// ---------------- launch ----------------
extern "C" void kernel_launch(void* const* d_in, const int* in_sizes, int n_in,
                              void* d_out, int out_size) {
    const float* x       = (const float*)d_in[0];
    const float* W_in    = (const float*)d_in[1];
    const float* conv_w  = (const float*)d_in[2];
    const float* conv_b  = (const float*)d_in[3];
    const float* dt_bias = (const float*)d_in[4];
    const float* A_log   = (const float*)d_in[5];
    const float* Dp      = (const float*)d_in[6];
    const float* norm_w  = (const float*)d_in[7];
    const float* W_out   = (const float*)d_in[8];
    float* out = (float*)d_out;

    float *zx_ptr;
    cudaGetSymbolAddress((void**)&zx_ptr, g_zxbcdt);
    __half *xh, *yh, *wi, *wo;
    cudaGetSymbolAddress((void**)&xh, g_xh);
    cudaGetSymbolAddress((void**)&yh, g_yh);
    cudaGetSymbolAddress((void**)&wi, g_wi);
    cudaGetSymbolAddress((void**)&wo, g_wo);

    static cudaStream_t s1;
    static cudaEvent_t evA, evB, evC, evD;
    static int attr_set = 0;
    if (!attr_set) {
        cudaFuncSetAttribute(mma_gemm, cudaFuncAttributeMaxDynamicSharedMemorySize, GSMEM);
        cudaFuncSetAttribute(chunk_output, cudaFuncAttributeMaxDynamicSharedMemorySize, CSMEM);
        cudaStreamCreateWithFlags(&s1, cudaStreamNonBlocking);
        cudaEventCreateWithFlags(&evA, cudaEventDisableTiming);
        cudaEventCreateWithFlags(&evB, cudaEventDisableTiming);
        cudaEventCreateWithFlags(&evC, cudaEventDisableTiming);
        cudaEventCreateWithFlags(&evD, cudaEventDisableTiming);
        attr_set = 1;
    }

    // ---- fork 1: weight transposes on s1 concurrent with x convert ----
    cudaEventRecord(evA, 0);
    cudaStreamWaitEvent(s1, evA, 0);
    transpose_f16<<<dim3(NPAD1 / 32, D_MODEL / 32), dim3(32, 8), 0, s1>>>(
        W_in, wi, D_MODEL, D_IN_PROJ, NPAD1);
    transpose_f16<<<dim3(D_MODEL / 32, D_INNER / 32), dim3(32, 8), 0, s1>>>(
        W_out, wo, D_INNER, D_MODEL, D_MODEL);
    convert_f16<<<(ROWS * D_MODEL / 4 + 255) / 256, 256>>>(x, xh, ROWS * D_MODEL / 4);
    cudaEventRecord(evB, s1);
    cudaStreamWaitEvent(0, evB, 0);

    // GEMM1: zxbcdt = x @ W_in
    mma_gemm<<<dim3(NPAD1 / 128, ROWS / 128), 256, GSMEM>>>(
        xh, wi, zx_ptr, ROWS, D_IN_PROJ, D_MODEL);

    // ---- fork 2: dt on s1 concurrent with conv ----
    cudaEventRecord(evC, 0);
    cudaStreamWaitEvent(s1, evC, 0);
    dt_kernel<<<(BATCH * NHEADS * SEQLEN + 255) / 256, 256, 0, s1>>>(dt_bias, A_log);
    conv_kernel<<<((ROWS / 4) * NC4 + 255) / 256, 256>>>(conv_w, conv_b);
    cudaEventRecord(evD, s1);
    cudaStreamWaitEvent(0, evD, 0);

    // chunked SSM scan
    chunk_state<<<dim3(NCHUNK, NHEADS, BATCH), 256>>>();
    state_pass<<<BATCH * NHEADS * SPB, 256>>>();
    chunk_output<<<dim3(NCHUNK, NHEADS, BATCH), 256, CSMEM>>>(Dp);

    // gate + RMSNorm
    norm_kernel<<<ROWS, 192>>>(norm_w);

    // GEMM2: out = y @ W_out
    mma_gemm<<<dim3(D_MODEL / 128, ROWS / 128), 256, GSMEM>>>(
        yh, wo, out, ROWS, D_MODEL, D_INNER);
}

// round 15
// speedup vs baseline: 1.8113x; 1.1624x over previous
#include <cuda_runtime.h>
#include <cuda_fp16.h>
#include <math.h>
#include <stdint.h>

#define D_MODEL   768
#define D_STATE   64
#define D_CONV    4
#define HEADDIM   64
#define D_INNER   1536
#define NHEADS    24
#define CONV_DIM  1664
#define D_IN_PROJ 3224
#define BATCH     2
#define SEQLEN    4096
#define ROWS      (BATCH*SEQLEN)
#define NPAD1     3328
#define NCHUNK    64
#define CT        64

// ---------------- scratch (device globals; no allocation) ----------------
__device__ float g_zxbcdt[(size_t)ROWS * D_IN_PROJ];
__device__ __half g_xBC[(size_t)ROWS * CONV_DIM];
__device__ __half g_yraw[(size_t)ROWS * D_INNER];
__device__ float g_dtT[(size_t)BATCH * NHEADS * SEQLEN];
__device__ float g_dtAT[(size_t)BATCH * NHEADS * SEQLEN];
__device__ __half g_S[(size_t)BATCH * NHEADS * NCHUNK * HEADDIM * D_STATE];
__device__ __half g_H[(size_t)BATCH * NHEADS * NCHUNK * HEADDIM * D_STATE];
__device__ float g_P[(size_t)BATCH * NHEADS * NCHUNK];
__device__ __half g_xh[(size_t)ROWS * D_MODEL];
__device__ __half g_yh[(size_t)ROWS * D_INNER];
__device__ __half g_wi[(size_t)NPAD1 * D_MODEL];
__device__ __half g_wo[(size_t)D_MODEL * D_INNER];

// ---------------- common PTX helpers ----------------
__device__ __forceinline__ void cp16(uint32_t dst, const void* src) {
    asm volatile("cp.async.ca.shared.global [%0], [%1], 16;" :: "r"(dst), "l"(src) : "memory");
}
__device__ __forceinline__ void cp_commit() {
    asm volatile("cp.async.commit_group;" ::: "memory");
}
template <int N> __device__ __forceinline__ void cp_wait() {
    asm volatile("cp.async.wait_group %0;" :: "n"(N) : "memory");
}
__device__ __forceinline__ void ldsm4(uint32_t* r, uint32_t addr) {
    asm volatile("ldmatrix.sync.aligned.m8n8.x4.shared.b16 {%0,%1,%2,%3}, [%4];"
                 : "=r"(r[0]), "=r"(r[1]), "=r"(r[2]), "=r"(r[3]) : "r"(addr));
}
__device__ __forceinline__ void mma_f16(float* d, const uint32_t* a, uint32_t b0, uint32_t b1) {
    asm volatile("mma.sync.aligned.m16n8k16.row.col.f32.f16.f16.f32 "
                 "{%0,%1,%2,%3}, {%4,%5,%6,%7}, {%8,%9}, {%0,%1,%2,%3};"
                 : "+f"(d[0]), "+f"(d[1]), "+f"(d[2]), "+f"(d[3])
                 : "r"(a[0]), "r"(a[1]), "r"(a[2]), "r"(a[3]), "r"(b0), "r"(b1));
}

// ---------------- warp-MMA fp16 GEMM (R8 best config: KC=32, 2 CTA/SM) ----------------
#define KC      32
#define PITCH   40
#define TILE_E  (128 * PITCH)
#define TILE_B  (TILE_E * 2)
#define STAGE_B (2 * TILE_B)
#define STAGES  3
#define GSMEM   (STAGES * STAGE_B)      // 61440 bytes

__global__ void __launch_bounds__(256, 2) mma_gemm(
    const __half* __restrict__ Ah, const __half* __restrict__ Bh,
    float* __restrict__ C, int M, int N, int K) {
    extern __shared__ __half sm[];
    const int tid = threadIdx.x;
    const int wid = tid >> 5, lane = tid & 31;
    const int warp_m = wid >> 1, warp_n = wid & 1;
    const int g = lane >> 2, tig = lane & 3;
    const int bm = blockIdx.y * 128, bn = blockIdx.x * 128;
    const uint32_t sbase = (uint32_t)__cvta_generic_to_shared(sm);

    float acc[2][8][4];
#pragma unroll
    for (int mt = 0; mt < 2; mt++)
#pragma unroll
        for (int nt = 0; nt < 8; nt++)
#pragma unroll
            for (int i = 0; i < 4; i++) acc[mt][nt][i] = 0.f;

    const int nkt = K / KC;
    const int r_ld = tid >> 2, seg_ld = tid & 3;

    auto issue = [&](int kt) {
        const int st = kt % STAGES;
        const int kofs = kt * KC;
        const uint32_t dst0 = sbase + st * STAGE_B;
        const __half* srcs[2] = {Ah, Bh};
#pragma unroll
        for (int arr = 0; arr < 2; arr++) {
            const int rbase = (arr == 0) ? bm : bn;
            const uint32_t db = dst0 + arr * TILE_B;
#pragma unroll
            for (int i = 0; i < 2; i++) {
                const int r = r_ld + i * 64;
                cp16(db + (uint32_t)(r * PITCH + seg_ld * 8) * 2,
                     srcs[arr] + (size_t)(rbase + r) * K + kofs + seg_ld * 8);
            }
        }
    };

    issue(0); cp_commit();
    if (nkt > 1) { issue(1); cp_commit(); }

    const int a_row = (lane & 15);
    const int a_col = (lane >> 4) * 8;
    const int b_row = (lane & 7) + ((lane >> 4) * 8);
    const int b_col = ((lane >> 3) & 1) * 8;

    for (int kt = 0; kt < nkt; kt++) {
        if (kt + 2 < nkt) cp_wait<1>(); else cp_wait<0>();
        __syncthreads();
        if (kt + 2 < nkt) { issue(kt + 2); cp_commit(); }

        const uint32_t st0 = sbase + (kt % STAGES) * STAGE_B;
        const uint32_t aA = st0;
        const uint32_t bB = st0 + TILE_B;

#pragma unroll
        for (int ks = 0; ks < KC; ks += 16) {
            uint32_t ah[2][4], bf[4][4];
#pragma unroll
            for (int mt = 0; mt < 2; mt++) {
                const uint32_t aoff =
                    (uint32_t)((warp_m * 32 + mt * 16 + a_row) * PITCH + ks + a_col) * 2;
                ldsm4(ah[mt], aA + aoff);
            }
#pragma unroll
            for (int ntp = 0; ntp < 4; ntp++) {
                const uint32_t boff =
                    (uint32_t)((warp_n * 64 + ntp * 16 + b_row) * PITCH + ks + b_col) * 2;
                ldsm4(bf[ntp], bB + boff);
            }
#pragma unroll
            for (int nt = 0; nt < 8; nt++) {
                const uint32_t b0 = bf[nt >> 1][(nt & 1) * 2];
                const uint32_t b1 = bf[nt >> 1][(nt & 1) * 2 + 1];
#pragma unroll
                for (int mt = 0; mt < 2; mt++)
                    mma_f16(acc[mt][nt], ah[mt], b0, b1);
            }
        }
        __syncthreads();
    }

#pragma unroll
    for (int mt = 0; mt < 2; mt++) {
        const int row0 = bm + warp_m * 32 + mt * 16 + g;
#pragma unroll
        for (int nt = 0; nt < 8; nt++) {
            const int col = bn + warp_n * 64 + nt * 8 + 2 * tig;
            if (col < N) {
                *(float2*)&C[(size_t)row0 * N + col] = make_float2(acc[mt][nt][0], acc[mt][nt][1]);
                *(float2*)&C[(size_t)(row0 + 8) * N + col] = make_float2(acc[mt][nt][2], acc[mt][nt][3]);
            }
        }
    }
}

// ---------------- fp32 -> fp16 convert ----------------
__global__ void convert_f16(const float* __restrict__ src,
                            __half* __restrict__ dst, int n4) {
    int i = blockIdx.x * blockDim.x + threadIdx.x;
    if (i >= n4) return;
    const int idx = i * 4;
    float4 v = *(const float4*)(src + idx);
    __half h[4];
    h[0] = __float2half(v.x); h[1] = __float2half(v.y);
    h[2] = __float2half(v.z); h[3] = __float2half(v.w);
    *(uint2*)(dst + idx) = *(uint2*)h;
}

// ---------------- transpose to fp16 ----------------
__global__ void transpose_f16(const float* __restrict__ src,
                              __half* __restrict__ dst,
                              int R, int C, int Cpad) {
    __shared__ float tile[32][33];
    const int c0 = blockIdx.x * 32, r0 = blockIdx.y * 32;
    const int tx = threadIdx.x, ty = threadIdx.y;
    const int c = c0 + tx;
#pragma unroll
    for (int j = ty; j < 32; j += 8) {
        const int r = r0 + j;
        tile[j][tx] = (r < R && c < C) ? src[(size_t)r * C + c] : 0.f;
    }
    __syncthreads();
#pragma unroll
    for (int j = ty; j < 32; j += 8) {
        const int orow = c0 + j;
        const int ocol = r0 + tx;
        if (orow < Cpad && ocol < R)
            dst[(size_t)orow * R + ocol] = __float2half(tile[tx][j]);
    }
}

// ---------------- dt ----------------
__global__ void dt_kernel(const float* __restrict__ dt_bias,
                          const float* __restrict__ A_log) {
    int idx = blockIdx.x * blockDim.x + threadIdx.x;
    if (idx >= BATCH * NHEADS * SEQLEN) return;
    const int l = idx % SEQLEN;
    const int bh = idx / SEQLEN;
    const int h = bh % NHEADS, b = bh / NHEADS;
    float v = g_zxbcdt[(size_t)(b * SEQLEN + l) * D_IN_PROJ + (D_INNER + CONV_DIM) + h]
              + dt_bias[h];
    float dtv = (v > 20.f) ? v : log1pf(expf(v));
    float A = -expf(A_log[h]);
    g_dtT[idx] = dtv;
    g_dtAT[idx] = dtv * A;
}

// ---------------- causal depthwise conv + silu -> fp16 out ----------------
#define NC4 (CONV_DIM / 4)
__global__ void conv_kernel(const float* __restrict__ conv_w,
                            const float* __restrict__ conv_b) {
    int i = blockIdx.x * blockDim.x + threadIdx.x;
    if (i >= (ROWS / 4) * NC4) return;
    const int c4 = (i % NC4) * 4;
    const int rb = (i / NC4) * 4;
    const int l0 = rb & (SEQLEN - 1);

    const float4 bias = *(const float4*)(conv_b + c4);
    const float4 w0 = *(const float4*)(conv_w + (c4 + 0) * 4);
    const float4 w1 = *(const float4*)(conv_w + (c4 + 1) * 4);
    const float4 w2 = *(const float4*)(conv_w + (c4 + 2) * 4);
    const float4 w3 = *(const float4*)(conv_w + (c4 + 3) * 4);
    const float wt0[4] = {w0.x, w0.y, w0.z, w0.w};
    const float wt1[4] = {w1.x, w1.y, w1.z, w1.w};
    const float wt2[4] = {w2.x, w2.y, w2.z, w2.w};
    const float wt3[4] = {w3.x, w3.y, w3.z, w3.w};

    float4 v[7];
#pragma unroll
    for (int j = 0; j < 7; j++) {
        const int ls = l0 + j - 3;
        if (ls >= 0)
            v[j] = *(const float4*)(g_zxbcdt + (size_t)(rb + j - 3) * D_IN_PROJ + D_INNER + c4);
        else
            v[j] = make_float4(0.f, 0.f, 0.f, 0.f);
    }

#pragma unroll
    for (int j = 0; j < 4; j++) {
        float4 acc = bias;
#pragma unroll
        for (int k = 0; k < D_CONV; k++) {
            acc.x += v[j + k].x * wt0[k];
            acc.y += v[j + k].y * wt1[k];
            acc.z += v[j + k].z * wt2[k];
            acc.w += v[j + k].w * wt3[k];
        }
        __half h[4];
        h[0] = __float2half(acc.x / (1.f + expf(-acc.x)));
        h[1] = __float2half(acc.y / (1.f + expf(-acc.y)));
        h[2] = __float2half(acc.z / (1.f + expf(-acc.z)));
        h[3] = __float2half(acc.w / (1.f + expf(-acc.w)));
        *(uint2*)(g_xBC + (size_t)(rb + j) * CONV_DIM + c4) = *(uint2*)h;
    }
}

// ================= chunked SSM scan (tensor-core) =================
#define SPITCH 72

// Phase A: A = w*x (fp32 -> hi/lo), B pure fp16. 2 MMAs per tile.
__global__ void __launch_bounds__(256) chunk_state(void) {
    __shared__ __half sAh[CT * SPITCH], sAl[CT * SPITCH];
    __shared__ __half sBh[CT * SPITCH];
    __shared__ float sL[CT], sdt[CT];
    const int c = blockIdx.x, h = blockIdx.y, b = blockIdx.z;
    const int tid = threadIdx.x;
    const int bh = b * NHEADS + h;
    const int rowbase = b * SEQLEN + c * CT;

    if (tid < CT) {
        sdt[tid] = g_dtT[(size_t)bh * SEQLEN + c * CT + tid];
        sL[tid]  = g_dtAT[(size_t)bh * SEQLEN + c * CT + tid];
    }
    __syncthreads();
    if (tid == 0) {
        float run = 0.f;
        for (int t = 0; t < CT; t++) { run += sL[t]; sL[t] = run; }
    }
    __syncthreads();
    const float Lend = sL[CT - 1];

    for (int e = tid; e < CT * 16; e += 256) {
        const int t = e >> 4, q = e & 15;
        const __half* rowp = g_xBC + (size_t)(rowbase + t) * CONV_DIM;
        const float w = sdt[t] * expf(Lend - sL[t]);
        uint2 xr = *(const uint2*)(rowp + h * HEADDIM + q * 4);
        uint2 br = *(const uint2*)(rowp + D_INNER + q * 4);
        const __half* x4 = (const __half*)&xr;
        const __half* b4 = (const __half*)&br;
#pragma unroll
        for (int j = 0; j < 4; j++) {
            const int p = q * 4 + j;
            const float xa = __half2float(x4[j]) * w;
            __half hx = __float2half(xa);
            sAh[p * SPITCH + t] = hx;
            sAl[p * SPITCH + t] = __float2half(xa - __half2float(hx));
            sBh[p * SPITCH + t] = b4[j];
        }
    }
    __syncthreads();

    const int wid = tid >> 5, lane = tid & 31;
    const int warp_m = wid & 3, warp_n = wid >> 2;
    const int a_row = lane & 15, a_col = (lane >> 4) * 8;
    const int b_row = (lane & 7) + ((lane >> 4) * 8), b_col = ((lane >> 3) & 1) * 8;
    const uint32_t uAh = (uint32_t)__cvta_generic_to_shared(sAh);
    const uint32_t uAl = (uint32_t)__cvta_generic_to_shared(sAl);
    const uint32_t uBh = (uint32_t)__cvta_generic_to_shared(sBh);

    float acc[4][4];
#pragma unroll
    for (int nt = 0; nt < 4; nt++)
#pragma unroll
        for (int i = 0; i < 4; i++) acc[nt][i] = 0.f;

#pragma unroll
    for (int kt = 0; kt < 4; kt++) {
        const int k0 = kt * 16;
        uint32_t ah[4], al[4], bh[2][4];
        const uint32_t aoff = (uint32_t)((warp_m * 16 + a_row) * SPITCH + k0 + a_col) * 2;
        ldsm4(ah, uAh + aoff);
        ldsm4(al, uAl + aoff);
#pragma unroll
        for (int nb = 0; nb < 2; nb++) {
            const uint32_t boff =
                (uint32_t)((warp_n * 32 + nb * 16 + b_row) * SPITCH + k0 + b_col) * 2;
            ldsm4(bh[nb], uBh + boff);
        }
#pragma unroll
        for (int nt = 0; nt < 4; nt++) {
            const int nb = nt >> 1, pr = (nt & 1) * 2;
            mma_f16(acc[nt], ah, bh[nb][pr], bh[nb][pr + 1]);
            mma_f16(acc[nt], al, bh[nb][pr], bh[nb][pr + 1]);
        }
    }

    __half* Sb = g_S + ((size_t)bh * NCHUNK + c) * (HEADDIM * D_STATE);
    const int g = lane >> 2, tig = lane & 3;
#pragma unroll
    for (int nt = 0; nt < 4; nt++) {
        const int ncol = warp_n * 32 + nt * 8 + 2 * tig;
        const int prow = warp_m * 16 + g;
        *(__half2*)&Sb[prow * D_STATE + ncol] =
            __halves2half2(__float2half(acc[nt][0]), __float2half(acc[nt][1]));
        *(__half2*)&Sb[(prow + 8) * D_STATE + ncol] =
            __halves2half2(__float2half(acc[nt][2]), __float2half(acc[nt][3]));
    }
    if (tid == 0) g_P[(size_t)bh * NCHUNK + c] = Lend;
}

// Phase B: fully parallel over state elements; S,H fp16
#define SPB 16
__global__ void __launch_bounds__(256) state_pass(void) {
    const int blk = blockIdx.x;
    const int bh = blk / SPB, seg = blk % SPB;
    const int e = seg * 256 + threadIdx.x;
    __shared__ float sP[NCHUNK];
    if (threadIdx.x < NCHUNK)
        sP[threadIdx.x] = expf(g_P[(size_t)bh * NCHUNK + threadIdx.x]);
    __syncthreads();
    float hv = 0.f;
    const size_t base = (size_t)bh * NCHUNK * (HEADDIM * D_STATE) + e;
#pragma unroll 4
    for (int c = 0; c < NCHUNK; c++) {
        const size_t off = base + (size_t)c * (HEADDIM * D_STATE);
        g_H[off] = __float2half(hv);
        hv = sP[c] * hv + __half2float(g_S[off]);
    }
}

// Phase C: pure-fp16 C/B/X/H -> 6 smem tiles, 4 MMAs per tile
#define CTILE (CT * SPITCH)
#define CSMEM (6 * CTILE * 2 + 2 * CT * 4)
__global__ void __launch_bounds__(256) chunk_output(const float* __restrict__ Dparam) {
    extern __shared__ __half cs[];
    __half* sCh = cs;                  // C [t][n]
    __half* sB2h = cs + CTILE;         // B [s][n]
    __half* sXh = cs + 2 * CTILE;      // X^T [p][s]
    __half* sHh = cs + 3 * CTILE;      // H [p][n] -> stored [n-major]
    __half* sGh = cs + 4 * CTILE;      // G' [t][s]
    __half* sGl = cs + 5 * CTILE;
    float* sL = (float*)(cs + 6 * CTILE);
    float* sdt = sL + CT;

    const int c = blockIdx.x, h = blockIdx.y, b = blockIdx.z;
    const int tid = threadIdx.x;
    const int bh = b * NHEADS + h;
    const int rowbase = b * SEQLEN + c * CT;
    const float Dh = Dparam[h];

    if (tid < CT) {
        sdt[tid] = g_dtT[(size_t)bh * SEQLEN + c * CT + tid];
        sL[tid]  = g_dtAT[(size_t)bh * SEQLEN + c * CT + tid];
    }
    __syncthreads();
    if (tid == 0) {
        float run = 0.f;
        for (int t = 0; t < CT; t++) { run += sL[t]; sL[t] = run; }
    }

    const __half* Hbase = g_H + ((size_t)bh * NCHUNK + c) * (HEADDIM * D_STATE);
    for (int e = tid; e < CT * 16; e += 256) {
        const int t = e >> 4, q = e & 15;
        const __half* rowp = g_xBC + (size_t)(rowbase + t) * CONV_DIM;
        uint2 cr = *(const uint2*)(rowp + D_INNER + D_STATE + q * 4);
        uint2 br = *(const uint2*)(rowp + D_INNER + q * 4);
        uint2 xr = *(const uint2*)(rowp + h * HEADDIM + q * 4);
        uint2 hr = *(const uint2*)(Hbase + t * D_STATE + q * 4);   // t plays p
        const __half* c4 = (const __half*)&cr;
        const __half* b4 = (const __half*)&br;
        const __half* x4 = (const __half*)&xr;
        const __half* h4 = (const __half*)&hr;
#pragma unroll
        for (int j = 0; j < 4; j++) {
            const int n = q * 4 + j;
            sCh[t * SPITCH + n] = c4[j];
            sB2h[t * SPITCH + n] = b4[j];
            sXh[n * SPITCH + t] = x4[j];     // transpose: [p][s]
            sHh[t * SPITCH + n] = h4[j];
        }
    }
    __syncthreads();

    const int wid = tid >> 5, lane = tid & 31;
    const int warp_m = wid & 3, warp_n = wid >> 2;
    const int a_row = lane & 15, a_col = (lane >> 4) * 8;
    const int b_row = (lane & 7) + ((lane >> 4) * 8), b_col = ((lane >> 3) & 1) * 8;
    const int g = lane >> 2, tig = lane & 3;
    const uint32_t uCh = (uint32_t)__cvta_generic_to_shared(sCh);
    const uint32_t uB2h = (uint32_t)__cvta_generic_to_shared(sB2h);
    const uint32_t uXh = (uint32_t)__cvta_generic_to_shared(sXh);
    const uint32_t uHh = (uint32_t)__cvta_generic_to_shared(sHh);
    const uint32_t uGh = (uint32_t)__cvta_generic_to_shared(sGh);
    const uint32_t uGl = (uint32_t)__cvta_generic_to_shared(sGl);

    // ---- G = C.B^T (pure fp16 operands, 1 MMA)
    float gacc[4][4];
#pragma unroll
    for (int nt = 0; nt < 4; nt++)
#pragma unroll
        for (int i = 0; i < 4; i++) gacc[nt][i] = 0.f;
#pragma unroll
    for (int kt = 0; kt < 4; kt++) {
        const int k0 = kt * 16;
        uint32_t ah[4], bh[2][4];
        const uint32_t aoff = (uint32_t)((warp_m * 16 + a_row) * SPITCH + k0 + a_col) * 2;
        ldsm4(ah, uCh + aoff);
#pragma unroll
        for (int nb = 0; nb < 2; nb++) {
            const uint32_t boff =
                (uint32_t)((warp_n * 32 + nb * 16 + b_row) * SPITCH + k0 + b_col) * 2;
            ldsm4(bh[nb], uB2h + boff);
        }
#pragma unroll
        for (int nt = 0; nt < 4; nt++) {
            const int nb = nt >> 1, pr = (nt & 1) * 2;
            mma_f16(gacc[nt], ah, bh[nb][pr], bh[nb][pr + 1]);
        }
    }
    __syncthreads();

    // ---- mask + decay, store G' hi/lo (G is fp32-derived -> keep split)
#pragma unroll
    for (int nt = 0; nt < 4; nt++) {
        const int s0 = warp_n * 32 + nt * 8 + 2 * tig;
#pragma unroll
        for (int r = 0; r < 2; r++) {
            const int t = warp_m * 16 + g + r * 8;
            float v0 = gacc[nt][r * 2], v1 = gacc[nt][r * 2 + 1];
            const float Lt = sL[t];
            v0 = (s0 <= t)     ? v0 * sdt[s0]     * expf(Lt - sL[s0])     : 0.f;
            v1 = (s0 + 1 <= t) ? v1 * sdt[s0 + 1] * expf(Lt - sL[s0 + 1]) : 0.f;
            __half h0 = __float2half(v0), h1 = __float2half(v1);
            *(__half2*)&sGh[t * SPITCH + s0] = __halves2half2(h0, h1);
            *(__half2*)&sGl[t * SPITCH + s0] = __halves2half2(
                __float2half(v0 - __half2float(h0)), __float2half(v1 - __half2float(h1)));
        }
    }
    __syncthreads();

    // ---- Y1 = G'.X (2 MMAs), CH = C.H (1 MMA)
    float yacc[4][4], cacc[4][4];
#pragma unroll
    for (int nt = 0; nt < 4; nt++)
#pragma unroll
        for (int i = 0; i < 4; i++) { yacc[nt][i] = 0.f; cacc[nt][i] = 0.f; }
#pragma unroll
    for (int kt = 0; kt < 4; kt++) {
        const int k0 = kt * 16;
        uint32_t gh[4], gl[4], ch[4];
        uint32_t xh[2][4], hh[2][4];
        const uint32_t aoff = (uint32_t)((warp_m * 16 + a_row) * SPITCH + k0 + a_col) * 2;
        ldsm4(gh, uGh + aoff);
        ldsm4(gl, uGl + aoff);
        ldsm4(ch, uCh + aoff);
#pragma unroll
        for (int nb = 0; nb < 2; nb++) {
            const uint32_t boff =
                (uint32_t)((warp_n * 32 + nb * 16 + b_row) * SPITCH + k0 + b_col) * 2;
            ldsm4(xh[nb], uXh + boff);
            ldsm4(hh[nb], uHh + boff);
        }
#pragma unroll
        for (int nt = 0; nt < 4; nt++) {
            const int nb = nt >> 1, pr = (nt & 1) * 2;
            mma_f16(yacc[nt], gh, xh[nb][pr], xh[nb][pr + 1]);
            mma_f16(yacc[nt], gl, xh[nb][pr], xh[nb][pr + 1]);
            mma_f16(cacc[nt], ch, hh[nb][pr], hh[nb][pr + 1]);
        }
    }

    // ---- epilogue: Y = Y1 + CH*exp(L_t) + D*x
#pragma unroll
    for (int nt = 0; nt < 4; nt++) {
        const int p = warp_n * 32 + nt * 8 + 2 * tig;
#pragma unroll
        for (int r = 0; r < 2; r++) {
            const int t = warp_m * 16 + g + r * 8;
            const float et = expf(sL[t]);
            const float x0 = __half2float(sXh[p * SPITCH + t]);
            const float x1 = __half2float(sXh[(p + 1) * SPITCH + t]);
            const float o0 = yacc[nt][r * 2] + cacc[nt][r * 2] * et + Dh * x0;
            const float o1 = yacc[nt][r * 2 + 1] + cacc[nt][r * 2 + 1] * et + Dh * x1;
            *(__half2*)&g_yraw[(size_t)(rowbase + t) * D_INNER + h * HEADDIM + p] =
                __halves2half2(__float2half(o0), __float2half(o1));
        }
    }
}

// ---------------- gate + RMSNorm (vectorized, y fp16 in), writing fp16 ----------------
__global__ void __launch_bounds__(192) norm_kernel(const float* __restrict__ norm_w) {
    const int row = blockIdx.x;
    const int tid = threadIdx.x;
    const float4* z4 = (const float4*)(g_zxbcdt + (size_t)row * D_IN_PROJ);
    const __half* yrow = g_yraw + (size_t)row * D_INNER;
    __half* hrow = g_yh + (size_t)row * D_INNER;

    float4 gv[2];
    float ss = 0.f;
#pragma unroll
    for (int i = 0; i < 2; i++) {
        const int idx = tid + i * 192;
        float4 z = z4[idx];
        uint2 yr = *(const uint2*)(yrow + idx * 4);
        const __half* y4 = (const __half*)&yr;
        float4 y = make_float4(__half2float(y4[0]), __half2float(y4[1]),
                               __half2float(y4[2]), __half2float(y4[3]));
        y.x *= z.x / (1.f + expf(-z.x));
        y.y *= z.y / (1.f + expf(-z.y));
        y.z *= z.z / (1.f + expf(-z.z));
        y.w *= z.w / (1.f + expf(-z.w));
        gv[i] = y;
        ss += y.x * y.x + y.y * y.y + y.z * y.z + y.w * y.w;
    }
#pragma unroll
    for (int o = 16; o; o >>= 1) ss += __shfl_xor_sync(0xffffffffu, ss, o);
    __shared__ float red[6];
    if ((tid & 31) == 0) red[tid >> 5] = ss;
    __syncthreads();
    __shared__ float stotal;
    if (tid == 0) {
        float v = red[0] + red[1] + red[2] + red[3] + red[4] + red[5];
        stotal = rsqrtf(v * (1.f / D_INNER) + 1e-5f);
    }
    __syncthreads();
    const float scale = stotal;
#pragma unroll
    for (int i = 0; i < 2; i++) {
        const int idx = tid + i * 192;
        float4 w = *(const float4*)(norm_w + idx * 4);
        __half h[4];
        h[0] = __float2half(gv[i].x * scale * w.x);
        h[1] = __float2half(gv[i].y * scale * w.y);
        h[2] = __float2half(gv[i].z * scale * w.z);
        h[3] = __float2half(gv[i].w * scale * w.w);
        *(uint2*)(hrow + idx * 4) = *(uint2*)h;
    }
}

// ---------------- launch ----------------
extern "C" void kernel_launch(void* const* d_in, const int* in_sizes, int n_in,
                              void* d_out, int out_size) {
    const float* x       = (const float*)d_in[0];
    const float* W_in    = (const float*)d_in[1];
    const float* conv_w  = (const float*)d_in[2];
    const float* conv_b  = (const float*)d_in[3];
    const float* dt_bias = (const float*)d_in[4];
    const float* A_log   = (const float*)d_in[5];
    const float* Dp      = (const float*)d_in[6];
    const float* norm_w  = (const float*)d_in[7];
    const float* W_out   = (const float*)d_in[8];
    float* out = (float*)d_out;

    float *zx_ptr;
    cudaGetSymbolAddress((void**)&zx_ptr, g_zxbcdt);
    __half *xh, *yh, *wi, *wo;
    cudaGetSymbolAddress((void**)&xh, g_xh);
    cudaGetSymbolAddress((void**)&yh, g_yh);
    cudaGetSymbolAddress((void**)&wi, g_wi);
    cudaGetSymbolAddress((void**)&wo, g_wo);

    static cudaStream_t s1;
    static cudaEvent_t evA, evB, evC, evD;
    static int attr_set = 0;
    if (!attr_set) {
        cudaFuncSetAttribute(mma_gemm, cudaFuncAttributeMaxDynamicSharedMemorySize, GSMEM);
        cudaFuncSetAttribute(chunk_output, cudaFuncAttributeMaxDynamicSharedMemorySize, CSMEM);
        cudaStreamCreateWithFlags(&s1, cudaStreamNonBlocking);
        cudaEventCreateWithFlags(&evA, cudaEventDisableTiming);
        cudaEventCreateWithFlags(&evB, cudaEventDisableTiming);
        cudaEventCreateWithFlags(&evC, cudaEventDisableTiming);
        cudaEventCreateWithFlags(&evD, cudaEventDisableTiming);
        attr_set = 1;
    }

    // ---- fork 1: weight transposes on s1 concurrent with x convert ----
    cudaEventRecord(evA, 0);
    cudaStreamWaitEvent(s1, evA, 0);
    transpose_f16<<<dim3(NPAD1 / 32, D_MODEL / 32), dim3(32, 8), 0, s1>>>(
        W_in, wi, D_MODEL, D_IN_PROJ, NPAD1);
    transpose_f16<<<dim3(D_MODEL / 32, D_INNER / 32), dim3(32, 8), 0, s1>>>(
        W_out, wo, D_INNER, D_MODEL, D_MODEL);
    convert_f16<<<(ROWS * D_MODEL / 4 + 255) / 256, 256>>>(x, xh, ROWS * D_MODEL / 4);
    cudaEventRecord(evB, s1);
    cudaStreamWaitEvent(0, evB, 0);

    // GEMM1: zxbcdt = x @ W_in
    mma_gemm<<<dim3(NPAD1 / 128, ROWS / 128), 256, GSMEM>>>(
        xh, wi, zx_ptr, ROWS, D_IN_PROJ, D_MODEL);

    // ---- fork 2: dt on s1 concurrent with conv ----
    cudaEventRecord(evC, 0);
    cudaStreamWaitEvent(s1, evC, 0);
    dt_kernel<<<(BATCH * NHEADS * SEQLEN + 255) / 256, 256, 0, s1>>>(dt_bias, A_log);
    conv_kernel<<<((ROWS / 4) * NC4 + 255) / 256, 256>>>(conv_w, conv_b);
    cudaEventRecord(evD, s1);
    cudaStreamWaitEvent(0, evD, 0);

    // chunked SSM scan
    chunk_state<<<dim3(NCHUNK, NHEADS, BATCH), 256>>>();
    state_pass<<<BATCH * NHEADS * SPB, 256>>>();
    chunk_output<<<dim3(NCHUNK, NHEADS, BATCH), 256, CSMEM>>>(Dp);

    // gate + RMSNorm
    norm_kernel<<<ROWS, 192>>>(norm_w);

    // GEMM2: out = y @ W_out
    mma_gemm<<<dim3(D_MODEL / 128, ROWS / 128), 256, GSMEM>>>(
        yh, wo, out, ROWS, D_MODEL, D_INNER);
}

// round 16
// speedup vs baseline: 1.8381x; 1.0148x over previous
#include <cuda_runtime.h>
#include <cuda_fp16.h>
#include <math.h>
#include <stdint.h>

#define D_MODEL   768
#define D_STATE   64
#define D_CONV    4
#define HEADDIM   64
#define D_INNER   1536
#define NHEADS    24
#define CONV_DIM  1664
#define D_IN_PROJ 3224
#define BATCH     2
#define SEQLEN    4096
#define ROWS      (BATCH*SEQLEN)
#define NPAD1     3328
#define NCHUNK    64
#define CT        64

// ---------------- scratch (device globals; no allocation) ----------------
__device__ __half g_zxbcdt[(size_t)ROWS * D_IN_PROJ];
__device__ __half g_xBC[(size_t)ROWS * CONV_DIM];
__device__ __half g_yraw[(size_t)ROWS * D_INNER];
__device__ float g_dtT[(size_t)BATCH * NHEADS * SEQLEN];
__device__ float g_dtAT[(size_t)BATCH * NHEADS * SEQLEN];
__device__ __half g_S[(size_t)BATCH * NHEADS * NCHUNK * HEADDIM * D_STATE];
__device__ __half g_H[(size_t)BATCH * NHEADS * NCHUNK * HEADDIM * D_STATE];
__device__ float g_P[(size_t)BATCH * NHEADS * NCHUNK];
__device__ __half g_xh[(size_t)ROWS * D_MODEL];
__device__ __half g_yh[(size_t)ROWS * D_INNER];
__device__ __half g_wi[(size_t)NPAD1 * D_MODEL];
__device__ __half g_wo[(size_t)D_MODEL * D_INNER];

// ---------------- common PTX helpers ----------------
__device__ __forceinline__ void cp16(uint32_t dst, const void* src) {
    asm volatile("cp.async.ca.shared.global [%0], [%1], 16;" :: "r"(dst), "l"(src) : "memory");
}
__device__ __forceinline__ void cp_commit() {
    asm volatile("cp.async.commit_group;" ::: "memory");
}
template <int N> __device__ __forceinline__ void cp_wait() {
    asm volatile("cp.async.wait_group %0;" :: "n"(N) : "memory");
}
__device__ __forceinline__ void ldsm4(uint32_t* r, uint32_t addr) {
    asm volatile("ldmatrix.sync.aligned.m8n8.x4.shared.b16 {%0,%1,%2,%3}, [%4];"
                 : "=r"(r[0]), "=r"(r[1]), "=r"(r[2]), "=r"(r[3]) : "r"(addr));
}
__device__ __forceinline__ void mma_f16(float* d, const uint32_t* a, uint32_t b0, uint32_t b1) {
    asm volatile("mma.sync.aligned.m16n8k16.row.col.f32.f16.f16.f32 "
                 "{%0,%1,%2,%3}, {%4,%5,%6,%7}, {%8,%9}, {%0,%1,%2,%3};"
                 : "+f"(d[0]), "+f"(d[1]), "+f"(d[2]), "+f"(d[3])
                 : "r"(a[0]), "r"(a[1]), "r"(a[2]), "r"(a[3]), "r"(b0), "r"(b1));
}

// ---------------- warp-MMA fp16 GEMM, templated output type ----------------
#define KC      32
#define PITCH   40
#define TILE_E  (128 * PITCH)
#define TILE_B  (TILE_E * 2)
#define STAGE_B (2 * TILE_B)
#define STAGES  3
#define GSMEM   (STAGES * STAGE_B)      // 61440 bytes

template <typename TOUT>
__global__ void __launch_bounds__(256, 2) mma_gemm(
    const __half* __restrict__ Ah, const __half* __restrict__ Bh,
    TOUT* __restrict__ C, int M, int N, int K) {
    extern __shared__ __half sm[];
    const int tid = threadIdx.x;
    const int wid = tid >> 5, lane = tid & 31;
    const int warp_m = wid >> 1, warp_n = wid & 1;
    const int g = lane >> 2, tig = lane & 3;
    const int bm = blockIdx.y * 128, bn = blockIdx.x * 128;
    const uint32_t sbase = (uint32_t)__cvta_generic_to_shared(sm);

    float acc[2][8][4];
#pragma unroll
    for (int mt = 0; mt < 2; mt++)
#pragma unroll
        for (int nt = 0; nt < 8; nt++)
#pragma unroll
            for (int i = 0; i < 4; i++) acc[mt][nt][i] = 0.f;

    const int nkt = K / KC;
    const int r_ld = tid >> 2, seg_ld = tid & 3;

    auto issue = [&](int kt) {
        const int st = kt % STAGES;
        const int kofs = kt * KC;
        const uint32_t dst0 = sbase + st * STAGE_B;
        const __half* srcs[2] = {Ah, Bh};
#pragma unroll
        for (int arr = 0; arr < 2; arr++) {
            const int rbase = (arr == 0) ? bm : bn;
            const uint32_t db = dst0 + arr * TILE_B;
#pragma unroll
            for (int i = 0; i < 2; i++) {
                const int r = r_ld + i * 64;
                cp16(db + (uint32_t)(r * PITCH + seg_ld * 8) * 2,
                     srcs[arr] + (size_t)(rbase + r) * K + kofs + seg_ld * 8);
            }
        }
    };

    issue(0); cp_commit();
    if (nkt > 1) { issue(1); cp_commit(); }

    const int a_row = (lane & 15);
    const int a_col = (lane >> 4) * 8;
    const int b_row = (lane & 7) + ((lane >> 4) * 8);
    const int b_col = ((lane >> 3) & 1) * 8;

    for (int kt = 0; kt < nkt; kt++) {
        if (kt + 2 < nkt) cp_wait<1>(); else cp_wait<0>();
        __syncthreads();
        if (kt + 2 < nkt) { issue(kt + 2); cp_commit(); }

        const uint32_t st0 = sbase + (kt % STAGES) * STAGE_B;
        const uint32_t aA = st0;
        const uint32_t bB = st0 + TILE_B;

#pragma unroll
        for (int ks = 0; ks < KC; ks += 16) {
            uint32_t ah[2][4], bf[4][4];
#pragma unroll
            for (int mt = 0; mt < 2; mt++) {
                const uint32_t aoff =
                    (uint32_t)((warp_m * 32 + mt * 16 + a_row) * PITCH + ks + a_col) * 2;
                ldsm4(ah[mt], aA + aoff);
            }
#pragma unroll
            for (int ntp = 0; ntp < 4; ntp++) {
                const uint32_t boff =
                    (uint32_t)((warp_n * 64 + ntp * 16 + b_row) * PITCH + ks + b_col) * 2;
                ldsm4(bf[ntp], bB + boff);
            }
#pragma unroll
            for (int nt = 0; nt < 8; nt++) {
                const uint32_t b0 = bf[nt >> 1][(nt & 1) * 2];
                const uint32_t b1 = bf[nt >> 1][(nt & 1) * 2 + 1];
#pragma unroll
                for (int mt = 0; mt < 2; mt++)
                    mma_f16(acc[mt][nt], ah[mt], b0, b1);
            }
        }
        __syncthreads();
    }

#pragma unroll
    for (int mt = 0; mt < 2; mt++) {
        const int row0 = bm + warp_m * 32 + mt * 16 + g;
#pragma unroll
        for (int nt = 0; nt < 8; nt++) {
            const int col = bn + warp_n * 64 + nt * 8 + 2 * tig;
            if (col < N) {
                if constexpr (sizeof(TOUT) == 4) {
                    *(float2*)&C[(size_t)row0 * N + col] =
                        make_float2(acc[mt][nt][0], acc[mt][nt][1]);
                    *(float2*)&C[(size_t)(row0 + 8) * N + col] =
                        make_float2(acc[mt][nt][2], acc[mt][nt][3]);
                } else {
                    *(__half2*)&C[(size_t)row0 * N + col] = __halves2half2(
                        __float2half(acc[mt][nt][0]), __float2half(acc[mt][nt][1]));
                    *(__half2*)&C[(size_t)(row0 + 8) * N + col] = __halves2half2(
                        __float2half(acc[mt][nt][2]), __float2half(acc[mt][nt][3]));
                }
            }
        }
    }
}

// ---------------- fp32 -> fp16 convert ----------------
__global__ void convert_f16(const float* __restrict__ src,
                            __half* __restrict__ dst, int n4) {
    int i = blockIdx.x * blockDim.x + threadIdx.x;
    if (i >= n4) return;
    const int idx = i * 4;
    float4 v = *(const float4*)(src + idx);
    __half h[4];
    h[0] = __float2half(v.x); h[1] = __float2half(v.y);
    h[2] = __float2half(v.z); h[3] = __float2half(v.w);
    *(uint2*)(dst + idx) = *(uint2*)h;
}

// ---------------- transpose to fp16 ----------------
__global__ void transpose_f16(const float* __restrict__ src,
                              __half* __restrict__ dst,
                              int R, int C, int Cpad) {
    __shared__ float tile[32][33];
    const int c0 = blockIdx.x * 32, r0 = blockIdx.y * 32;
    const int tx = threadIdx.x, ty = threadIdx.y;
    const int c = c0 + tx;
#pragma unroll
    for (int j = ty; j < 32; j += 8) {
        const int r = r0 + j;
        tile[j][tx] = (r < R && c < C) ? src[(size_t)r * C + c] : 0.f;
    }
    __syncthreads();
#pragma unroll
    for (int j = ty; j < 32; j += 8) {
        const int orow = c0 + j;
        const int ocol = r0 + tx;
        if (orow < Cpad && ocol < R)
            dst[(size_t)orow * R + ocol] = __float2half(tile[tx][j]);
    }
}

// ---------------- dt (reads fp16 zxbcdt) ----------------
__global__ void dt_kernel(const float* __restrict__ dt_bias,
                          const float* __restrict__ A_log) {
    int idx = blockIdx.x * blockDim.x + threadIdx.x;
    if (idx >= BATCH * NHEADS * SEQLEN) return;
    const int l = idx % SEQLEN;
    const int bh = idx / SEQLEN;
    const int h = bh % NHEADS, b = bh / NHEADS;
    float v = __half2float(
                  g_zxbcdt[(size_t)(b * SEQLEN + l) * D_IN_PROJ + (D_INNER + CONV_DIM) + h])
              + dt_bias[h];
    float dtv = (v > 20.f) ? v : log1pf(expf(v));
    float A = -expf(A_log[h]);
    g_dtT[idx] = dtv;
    g_dtAT[idx] = dtv * A;
}

// ---------------- causal depthwise conv + silu (fp16 in/out) ----------------
#define NC4 (CONV_DIM / 4)
__global__ void conv_kernel(const float* __restrict__ conv_w,
                            const float* __restrict__ conv_b) {
    int i = blockIdx.x * blockDim.x + threadIdx.x;
    if (i >= (ROWS / 4) * NC4) return;
    const int c4 = (i % NC4) * 4;
    const int rb = (i / NC4) * 4;
    const int l0 = rb & (SEQLEN - 1);

    const float4 bias = *(const float4*)(conv_b + c4);
    const float4 w0 = *(const float4*)(conv_w + (c4 + 0) * 4);
    const float4 w1 = *(const float4*)(conv_w + (c4 + 1) * 4);
    const float4 w2 = *(const float4*)(conv_w + (c4 + 2) * 4);
    const float4 w3 = *(const float4*)(conv_w + (c4 + 3) * 4);
    const float wt0[4] = {w0.x, w0.y, w0.z, w0.w};
    const float wt1[4] = {w1.x, w1.y, w1.z, w1.w};
    const float wt2[4] = {w2.x, w2.y, w2.z, w2.w};
    const float wt3[4] = {w3.x, w3.y, w3.z, w3.w};

    float4 v[7];
#pragma unroll
    for (int j = 0; j < 7; j++) {
        const int ls = l0 + j - 3;
        if (ls >= 0) {
            uint2 raw = *(const uint2*)(g_zxbcdt +
                (size_t)(rb + j - 3) * D_IN_PROJ + D_INNER + c4);
            const __half* h4 = (const __half*)&raw;
            v[j] = make_float4(__half2float(h4[0]), __half2float(h4[1]),
                               __half2float(h4[2]), __half2float(h4[3]));
        } else {
            v[j] = make_float4(0.f, 0.f, 0.f, 0.f);
        }
    }

#pragma unroll
    for (int j = 0; j < 4; j++) {
        float4 acc = bias;
#pragma unroll
        for (int k = 0; k < D_CONV; k++) {
            acc.x += v[j + k].x * wt0[k];
            acc.y += v[j + k].y * wt1[k];
            acc.z += v[j + k].z * wt2[k];
            acc.w += v[j + k].w * wt3[k];
        }
        __half h[4];
        h[0] = __float2half(acc.x / (1.f + expf(-acc.x)));
        h[1] = __float2half(acc.y / (1.f + expf(-acc.y)));
        h[2] = __float2half(acc.z / (1.f + expf(-acc.z)));
        h[3] = __float2half(acc.w / (1.f + expf(-acc.w)));
        *(uint2*)(g_xBC + (size_t)(rb + j) * CONV_DIM + c4) = *(uint2*)h;
    }
}

// ================= chunked SSM scan (tensor-core) =================
#define SPITCH 72

// Phase A: A = w*x (fp32 -> hi/lo), B pure fp16. 2 MMAs per tile.
__global__ void __launch_bounds__(256) chunk_state(void) {
    __shared__ __half sAh[CT * SPITCH], sAl[CT * SPITCH];
    __shared__ __half sBh[CT * SPITCH];
    __shared__ float sL[CT], sdt[CT];
    const int c = blockIdx.x, h = blockIdx.y, b = blockIdx.z;
    const int tid = threadIdx.x;
    const int bh = b * NHEADS + h;
    const int rowbase = b * SEQLEN + c * CT;

    if (tid < CT) {
        sdt[tid] = g_dtT[(size_t)bh * SEQLEN + c * CT + tid];
        sL[tid]  = g_dtAT[(size_t)bh * SEQLEN + c * CT + tid];
    }
    __syncthreads();
    if (tid == 0) {
        float run = 0.f;
        for (int t = 0; t < CT; t++) { run += sL[t]; sL[t] = run; }
    }
    __syncthreads();
    const float Lend = sL[CT - 1];

    for (int e = tid; e < CT * 16; e += 256) {
        const int t = e >> 4, q = e & 15;
        const __half* rowp = g_xBC + (size_t)(rowbase + t) * CONV_DIM;
        const float w = sdt[t] * expf(Lend - sL[t]);
        uint2 xr = *(const uint2*)(rowp + h * HEADDIM + q * 4);
        uint2 br = *(const uint2*)(rowp + D_INNER + q * 4);
        const __half* x4 = (const __half*)&xr;
        const __half* b4 = (const __half*)&br;
#pragma unroll
        for (int j = 0; j < 4; j++) {
            const int p = q * 4 + j;
            const float xa = __half2float(x4[j]) * w;
            __half hx = __float2half(xa);
            sAh[p * SPITCH + t] = hx;
            sAl[p * SPITCH + t] = __float2half(xa - __half2float(hx));
            sBh[p * SPITCH + t] = b4[j];
        }
    }
    __syncthreads();

    const int wid = tid >> 5, lane = tid & 31;
    const int warp_m = wid & 3, warp_n = wid >> 2;
    const int a_row = lane & 15, a_col = (lane >> 4) * 8;
    const int b_row = (lane & 7) + ((lane >> 4) * 8), b_col = ((lane >> 3) & 1) * 8;
    const uint32_t uAh = (uint32_t)__cvta_generic_to_shared(sAh);
    const uint32_t uAl = (uint32_t)__cvta_generic_to_shared(sAl);
    const uint32_t uBh = (uint32_t)__cvta_generic_to_shared(sBh);

    float acc[4][4];
#pragma unroll
    for (int nt = 0; nt < 4; nt++)
#pragma unroll
        for (int i = 0; i < 4; i++) acc[nt][i] = 0.f;

#pragma unroll
    for (int kt = 0; kt < 4; kt++) {
        const int k0 = kt * 16;
        uint32_t ah[4], al[4], bh[2][4];
        const uint32_t aoff = (uint32_t)((warp_m * 16 + a_row) * SPITCH + k0 + a_col) * 2;
        ldsm4(ah, uAh + aoff);
        ldsm4(al, uAl + aoff);
#pragma unroll
        for (int nb = 0; nb < 2; nb++) {
            const uint32_t boff =
                (uint32_t)((warp_n * 32 + nb * 16 + b_row) * SPITCH + k0 + b_col) * 2;
            ldsm4(bh[nb], uBh + boff);
        }
#pragma unroll
        for (int nt = 0; nt < 4; nt++) {
            const int nb = nt >> 1, pr = (nt & 1) * 2;
            mma_f16(acc[nt], ah, bh[nb][pr], bh[nb][pr + 1]);
            mma_f16(acc[nt], al, bh[nb][pr], bh[nb][pr + 1]);
        }
    }

    __half* Sb = g_S + ((size_t)bh * NCHUNK + c) * (HEADDIM * D_STATE);
    const int g = lane >> 2, tig = lane & 3;
#pragma unroll
    for (int nt = 0; nt < 4; nt++) {
        const int ncol = warp_n * 32 + nt * 8 + 2 * tig;
        const int prow = warp_m * 16 + g;
        *(__half2*)&Sb[prow * D_STATE + ncol] =
            __halves2half2(__float2half(acc[nt][0]), __float2half(acc[nt][1]));
        *(__half2*)&Sb[(prow + 8) * D_STATE + ncol] =
            __halves2half2(__float2half(acc[nt][2]), __float2half(acc[nt][3]));
    }
    if (tid == 0) g_P[(size_t)bh * NCHUNK + c] = Lend;
}

// Phase B: fully parallel over state elements; S,H fp16
#define SPB 16
__global__ void __launch_bounds__(256) state_pass(void) {
    const int blk = blockIdx.x;
    const int bh = blk / SPB, seg = blk % SPB;
    const int e = seg * 256 + threadIdx.x;
    __shared__ float sP[NCHUNK];
    if (threadIdx.x < NCHUNK)
        sP[threadIdx.x] = expf(g_P[(size_t)bh * NCHUNK + threadIdx.x]);
    __syncthreads();
    float hv = 0.f;
    const size_t base = (size_t)bh * NCHUNK * (HEADDIM * D_STATE) + e;
#pragma unroll 4
    for (int c = 0; c < NCHUNK; c++) {
        const size_t off = base + (size_t)c * (HEADDIM * D_STATE);
        g_H[off] = __float2half(hv);
        hv = sP[c] * hv + __half2float(g_S[off]);
    }
}

// Phase C: pure-fp16 C/B/X/H -> 6 smem tiles, 4 MMAs per tile
#define CTILE (CT * SPITCH)
#define CSMEM (6 * CTILE * 2 + 2 * CT * 4)
__global__ void __launch_bounds__(256) chunk_output(const float* __restrict__ Dparam) {
    extern __shared__ __half cs[];
    __half* sCh = cs;
    __half* sB2h = cs + CTILE;
    __half* sXh = cs + 2 * CTILE;
    __half* sHh = cs + 3 * CTILE;
    __half* sGh = cs + 4 * CTILE;
    __half* sGl = cs + 5 * CTILE;
    float* sL = (float*)(cs + 6 * CTILE);
    float* sdt = sL + CT;

    const int c = blockIdx.x, h = blockIdx.y, b = blockIdx.z;
    const int tid = threadIdx.x;
    const int bh = b * NHEADS + h;
    const int rowbase = b * SEQLEN + c * CT;
    const float Dh = Dparam[h];

    if (tid < CT) {
        sdt[tid] = g_dtT[(size_t)bh * SEQLEN + c * CT + tid];
        sL[tid]  = g_dtAT[(size_t)bh * SEQLEN + c * CT + tid];
    }
    __syncthreads();
    if (tid == 0) {
        float run = 0.f;
        for (int t = 0; t < CT; t++) { run += sL[t]; sL[t] = run; }
    }

    const __half* Hbase = g_H + ((size_t)bh * NCHUNK + c) * (HEADDIM * D_STATE);
    for (int e = tid; e < CT * 16; e += 256) {
        const int t = e >> 4, q = e & 15;
        const __half* rowp = g_xBC + (size_t)(rowbase + t) * CONV_DIM;
        uint2 cr = *(const uint2*)(rowp + D_INNER + D_STATE + q * 4);
        uint2 br = *(const uint2*)(rowp + D_INNER + q * 4);
        uint2 xr = *(const uint2*)(rowp + h * HEADDIM + q * 4);
        uint2 hr = *(const uint2*)(Hbase + t * D_STATE + q * 4);
        const __half* c4 = (const __half*)&cr;
        const __half* b4 = (const __half*)&br;
        const __half* x4 = (const __half*)&xr;
        const __half* h4 = (const __half*)&hr;
#pragma unroll
        for (int j = 0; j < 4; j++) {
            const int n = q * 4 + j;
            sCh[t * SPITCH + n] = c4[j];
            sB2h[t * SPITCH + n] = b4[j];
            sXh[n * SPITCH + t] = x4[j];
            sHh[t * SPITCH + n] = h4[j];
        }
    }
    __syncthreads();

    const int wid = tid >> 5, lane = tid & 31;
    const int warp_m = wid & 3, warp_n = wid >> 2;
    const int a_row = lane & 15, a_col = (lane >> 4) * 8;
    const int b_row = (lane & 7) + ((lane >> 4) * 8), b_col = ((lane >> 3) & 1) * 8;
    const int g = lane >> 2, tig = lane & 3;
    const uint32_t uCh = (uint32_t)__cvta_generic_to_shared(sCh);
    const uint32_t uB2h = (uint32_t)__cvta_generic_to_shared(sB2h);
    const uint32_t uXh = (uint32_t)__cvta_generic_to_shared(sXh);
    const uint32_t uHh = (uint32_t)__cvta_generic_to_shared(sHh);
    const uint32_t uGh = (uint32_t)__cvta_generic_to_shared(sGh);
    const uint32_t uGl = (uint32_t)__cvta_generic_to_shared(sGl);

    float gacc[4][4];
#pragma unroll
    for (int nt = 0; nt < 4; nt++)
#pragma unroll
        for (int i = 0; i < 4; i++) gacc[nt][i] = 0.f;
#pragma unroll
    for (int kt = 0; kt < 4; kt++) {
        const int k0 = kt * 16;
        uint32_t ah[4], bh[2][4];
        const uint32_t aoff = (uint32_t)((warp_m * 16 + a_row) * SPITCH + k0 + a_col) * 2;
        ldsm4(ah, uCh + aoff);
#pragma unroll
        for (int nb = 0; nb < 2; nb++) {
            const uint32_t boff =
                (uint32_t)((warp_n * 32 + nb * 16 + b_row) * SPITCH + k0 + b_col) * 2;
            ldsm4(bh[nb], uB2h + boff);
        }
#pragma unroll
        for (int nt = 0; nt < 4; nt++) {
            const int nb = nt >> 1, pr = (nt & 1) * 2;
            mma_f16(gacc[nt], ah, bh[nb][pr], bh[nb][pr + 1]);
        }
    }
    __syncthreads();

#pragma unroll
    for (int nt = 0; nt < 4; nt++) {
        const int s0 = warp_n * 32 + nt * 8 + 2 * tig;
#pragma unroll
        for (int r = 0; r < 2; r++) {
            const int t = warp_m * 16 + g + r * 8;
            float v0 = gacc[nt][r * 2], v1 = gacc[nt][r * 2 + 1];
            const float Lt = sL[t];
            v0 = (s0 <= t)     ? v0 * sdt[s0]     * expf(Lt - sL[s0])     : 0.f;
            v1 = (s0 + 1 <= t) ? v1 * sdt[s0 + 1] * expf(Lt - sL[s0 + 1]) : 0.f;
            __half h0 = __float2half(v0), h1 = __float2half(v1);
            *(__half2*)&sGh[t * SPITCH + s0] = __halves2half2(h0, h1);
            *(__half2*)&sGl[t * SPITCH + s0] = __halves2half2(
                __float2half(v0 - __half2float(h0)), __float2half(v1 - __half2float(h1)));
        }
    }
    __syncthreads();

    float yacc[4][4], cacc[4][4];
#pragma unroll
    for (int nt = 0; nt < 4; nt++)
#pragma unroll
        for (int i = 0; i < 4; i++) { yacc[nt][i] = 0.f; cacc[nt][i] = 0.f; }
#pragma unroll
    for (int kt = 0; kt < 4; kt++) {
        const int k0 = kt * 16;
        uint32_t gh[4], gl[4], ch[4];
        uint32_t xh[2][4], hh[2][4];
        const uint32_t aoff = (uint32_t)((warp_m * 16 + a_row) * SPITCH + k0 + a_col) * 2;
        ldsm4(gh, uGh + aoff);
        ldsm4(gl, uGl + aoff);
        ldsm4(ch, uCh + aoff);
#pragma unroll
        for (int nb = 0; nb < 2; nb++) {
            const uint32_t boff =
                (uint32_t)((warp_n * 32 + nb * 16 + b_row) * SPITCH + k0 + b_col) * 2;
            ldsm4(xh[nb], uXh + boff);
            ldsm4(hh[nb], uHh + boff);
        }
#pragma unroll
        for (int nt = 0; nt < 4; nt++) {
            const int nb = nt >> 1, pr = (nt & 1) * 2;
            mma_f16(yacc[nt], gh, xh[nb][pr], xh[nb][pr + 1]);
            mma_f16(yacc[nt], gl, xh[nb][pr], xh[nb][pr + 1]);
            mma_f16(cacc[nt], ch, hh[nb][pr], hh[nb][pr + 1]);
        }
    }

#pragma unroll
    for (int nt = 0; nt < 4; nt++) {
        const int p = warp_n * 32 + nt * 8 + 2 * tig;
#pragma unroll
        for (int r = 0; r < 2; r++) {
            const int t = warp_m * 16 + g + r * 8;
            const float et = expf(sL[t]);
            const float x0 = __half2float(sXh[p * SPITCH + t]);
            const float x1 = __half2float(sXh[(p + 1) * SPITCH + t]);
            const float o0 = yacc[nt][r * 2] + cacc[nt][r * 2] * et + Dh * x0;
            const float o1 = yacc[nt][r * 2 + 1] + cacc[nt][r * 2 + 1] * et + Dh * x1;
            *(__half2*)&g_yraw[(size_t)(rowbase + t) * D_INNER + h * HEADDIM + p] =
                __halves2half2(__float2half(o0), __float2half(o1));
        }
    }
}

// ---------------- gate + RMSNorm (z fp16 in, y fp16 in), writing fp16 ----------------
__global__ void __launch_bounds__(192) norm_kernel(const float* __restrict__ norm_w) {
    const int row = blockIdx.x;
    const int tid = threadIdx.x;
    const __half* zrow = g_zxbcdt + (size_t)row * D_IN_PROJ;
    const __half* yrow = g_yraw + (size_t)row * D_INNER;
    __half* hrow = g_yh + (size_t)row * D_INNER;

    float4 gv[2];
    float ss = 0.f;
#pragma unroll
    for (int i = 0; i < 2; i++) {
        const int idx = tid + i * 192;
        uint2 zr = *(const uint2*)(zrow + idx * 4);
        uint2 yr = *(const uint2*)(yrow + idx * 4);
        const __half* z4 = (const __half*)&zr;
        const __half* y4 = (const __half*)&yr;
        float4 y;
        {
            const float z0 = __half2float(z4[0]), z1 = __half2float(z4[1]);
            const float z2 = __half2float(z4[2]), z3 = __half2float(z4[3]);
            y.x = __half2float(y4[0]) * (z0 / (1.f + expf(-z0)));
            y.y = __half2float(y4[1]) * (z1 / (1.f + expf(-z1)));
            y.z = __half2float(y4[2]) * (z2 / (1.f + expf(-z2)));
            y.w = __half2float(y4[3]) * (z3 / (1.f + expf(-z3)));
        }
        gv[i] = y;
        ss += y.x * y.x + y.y * y.y + y.z * y.z + y.w * y.w;
    }
#pragma unroll
    for (int o = 16; o; o >>= 1) ss += __shfl_xor_sync(0xffffffffu, ss, o);
    __shared__ float red[6];
    if ((tid & 31) == 0) red[tid >> 5] = ss;
    __syncthreads();
    __shared__ float stotal;
    if (tid == 0) {
        float v = red[0] + red[1] + red[2] + red[3] + red[4] + red[5];
        stotal = rsqrtf(v * (1.f / D_INNER) + 1e-5f);
    }
    __syncthreads();
    const float scale = stotal;
#pragma unroll
    for (int i = 0; i < 2; i++) {
        const int idx = tid + i * 192;
        float4 w = *(const float4*)(norm_w + idx * 4);
        __half h[4];
        h[0] = __float2half(gv[i].x * scale * w.x);
        h[1] = __float2half(gv[i].y * scale * w.y);
        h[2] = __float2half(gv[i].z * scale * w.z);
        h[3] = __float2half(gv[i].w * scale * w.w);
        *(uint2*)(hrow + idx * 4) = *(uint2*)h;
    }
}

// ---------------- launch ----------------
extern "C" void kernel_launch(void* const* d_in, const int* in_sizes, int n_in,
                              void* d_out, int out_size) {
    const float* x       = (const float*)d_in[0];
    const float* W_in    = (const float*)d_in[1];
    const float* conv_w  = (const float*)d_in[2];
    const float* conv_b  = (const float*)d_in[3];
    const float* dt_bias = (const float*)d_in[4];
    const float* A_log   = (const float*)d_in[5];
    const float* Dp      = (const float*)d_in[6];
    const float* norm_w  = (const float*)d_in[7];
    const float* W_out   = (const float*)d_in[8];
    float* out = (float*)d_out;

    __half *zx_ptr, *xh, *yh, *wi, *wo;
    cudaGetSymbolAddress((void**)&zx_ptr, g_zxbcdt);
    cudaGetSymbolAddress((void**)&xh, g_xh);
    cudaGetSymbolAddress((void**)&yh, g_yh);
    cudaGetSymbolAddress((void**)&wi, g_wi);
    cudaGetSymbolAddress((void**)&wo, g_wo);

    static cudaStream_t s1;
    static cudaEvent_t evA, evB, evC, evD;
    static int attr_set = 0;
    if (!attr_set) {
        cudaFuncSetAttribute(mma_gemm<__half>, cudaFuncAttributeMaxDynamicSharedMemorySize, GSMEM);
        cudaFuncSetAttribute(mma_gemm<float>, cudaFuncAttributeMaxDynamicSharedMemorySize, GSMEM);
        cudaFuncSetAttribute(chunk_output, cudaFuncAttributeMaxDynamicSharedMemorySize, CSMEM);
        cudaStreamCreateWithFlags(&s1, cudaStreamNonBlocking);
        cudaEventCreateWithFlags(&evA, cudaEventDisableTiming);
        cudaEventCreateWithFlags(&evB, cudaEventDisableTiming);
        cudaEventCreateWithFlags(&evC, cudaEventDisableTiming);
        cudaEventCreateWithFlags(&evD, cudaEventDisableTiming);
        attr_set = 1;
    }

    // ---- fork 1: weight transposes on s1 concurrent with x convert ----
    cudaEventRecord(evA, 0);
    cudaStreamWaitEvent(s1, evA, 0);
    transpose_f16<<<dim3(NPAD1 / 32, D_MODEL / 32), dim3(32, 8), 0, s1>>>(
        W_in, wi, D_MODEL, D_IN_PROJ, NPAD1);
    transpose_f16<<<dim3(D_MODEL / 32, D_INNER / 32), dim3(32, 8), 0, s1>>>(
        W_out, wo, D_INNER, D_MODEL, D_MODEL);
    convert_f16<<<(ROWS * D_MODEL / 4 + 255) / 256, 256>>>(x, xh, ROWS * D_MODEL / 4);
    cudaEventRecord(evB, s1);
    cudaStreamWaitEvent(0, evB, 0);

    // GEMM1: zxbcdt = x @ W_in (fp16 output)
    mma_gemm<__half><<<dim3(NPAD1 / 128, ROWS / 128), 256, GSMEM>>>(
        xh, wi, zx_ptr, ROWS, D_IN_PROJ, D_MODEL);

    // ---- fork 2: dt on s1 concurrent with conv ----
    cudaEventRecord(evC, 0);
    cudaStreamWaitEvent(s1, evC, 0);
    dt_kernel<<<(BATCH * NHEADS * SEQLEN + 255) / 256, 256, 0, s1>>>(dt_bias, A_log);
    conv_kernel<<<((ROWS / 4) * NC4 + 255) / 256, 256>>>(conv_w, conv_b);
    cudaEventRecord(evD, s1);
    cudaStreamWaitEvent(0, evD, 0);

    // chunked SSM scan
    chunk_state<<<dim3(NCHUNK, NHEADS, BATCH), 256>>>();
    state_pass<<<BATCH * NHEADS * SPB, 256>>>();
    chunk_output<<<dim3(NCHUNK, NHEADS, BATCH), 256, CSMEM>>>(Dp);

    // gate + RMSNorm
    norm_kernel<<<ROWS, 192>>>(norm_w);

    // GEMM2: out = y @ W_out (fp32 output)
    mma_gemm<float><<<dim3(D_MODEL / 128, ROWS / 128), 256, GSMEM>>>(
        yh, wo, out, ROWS, D_MODEL, D_INNER);
}